// round 5
// baseline (speedup 1.0000x reference)
#include <cuda_runtime.h>
#include <cuda_bf16.h>
#include <math.h>
#include <stdint.h>

// ---------------------------------------------------------------------------
// Problem constants
// ---------------------------------------------------------------------------
#define BB     2
#define SS     1024
#define TT     (BB*SS)        // 2048 tokens
#define HID    2048
#define NH     32
#define HD     64
#define ROT    16
#define DFF    8192
#define LN_EPS 1e-5f

// ---------------------------------------------------------------------------
// Static scratch (no allocations allowed)
// ---------------------------------------------------------------------------
__device__ float g_xln[(size_t)TT * HID];
__device__ float g_q  [(size_t)TT * HID];
__device__ float g_k  [(size_t)TT * HID];
__device__ float g_v  [(size_t)TT * HID];
__device__ float g_h  [(size_t)TT * HID];
__device__ float g_yln[(size_t)TT * HID];
__device__ float g_up [(size_t)TT * DFF];

// bf16 3-split scratch
__device__ __nv_bfloat16 g_a3[(size_t)TT * 24576];     // A operand splits / ctx split
__device__ __nv_bfloat16 g_b3[(size_t)DFF * 6144];     // B operand splits
__device__ __nv_bfloat16 g_c3[(size_t)TT * 24576];     // activated-gate split

// ---------------------------------------------------------------------------
// helpers
// ---------------------------------------------------------------------------
__device__ __forceinline__ uint32_t smem_u32(const void* p) {
    uint32_t a;
    asm("{ .reg .u64 t; cvta.to.shared.u64 t, %1; cvt.u32.u64 %0, t; }"
        : "=r"(a) : "l"(p));
    return a;
}

#define CP_ASYNC16(sa, ga) \
    asm volatile("cp.async.cg.shared.global [%0], [%1], 16;" :: "r"(sa), "l"(ga))
#define CP_COMMIT() asm volatile("cp.async.commit_group;")
#define CP_WAIT1()  asm volatile("cp.async.wait_group 1;")

#define LDSM4(r, addr) \
    asm volatile("ldmatrix.sync.aligned.m8n8.x4.shared.b16 {%0,%1,%2,%3}, [%4];" \
        : "=r"((r)[0]), "=r"((r)[1]), "=r"((r)[2]), "=r"((r)[3]) : "r"(addr))

#define MMA16816(d, a, b0, b1) \
    asm volatile("mma.sync.aligned.m16n8k16.row.col.f32.bf16.bf16.f32 " \
        "{%0,%1,%2,%3}, {%4,%5,%6,%7}, {%8,%9}, {%0,%1,%2,%3};" \
        : "+f"((d)[0]), "+f"((d)[1]), "+f"((d)[2]), "+f"((d)[3]) \
        : "r"((a)[0]), "r"((a)[1]), "r"((a)[2]), "r"((a)[3]), "r"(b0), "r"(b1))

__device__ __forceinline__ uint32_t pack_bf2(float a, float b) {
    uint32_t h0 = (uint32_t)__bfloat16_as_ushort(__float2bfloat16(a));
    uint32_t h1 = (uint32_t)__bfloat16_as_ushort(__float2bfloat16(b));
    return h0 | (h1 << 16);
}

// ---------------------------------------------------------------------------
// HMMA bf16 GEMM:  C[M,N] = A3[M,K3] * B3[N,K3]^T
// mode 0: C fp32   mode 1: C = acc + add   mode 3: silu(acc)*add -> bf16 split
// Block tile 128(M) x 256(N), BK=64, 3-stage cp.async, 256 thr = 8 warps,
// warp tile 64x64 (2x4 warp grid), mma m16n8k16 bf16.
// ---------------------------------------------------------------------------
#define GSTAGES       3
#define GA_BYTES      16384                    // 128 rows * 128B
#define GB_BYTES      32768                    // 256 rows * 128B
#define GSTAGE_BYTES  (GA_BYTES + GB_BYTES)    // 48 KB
#define GEMM_DSMEM    (GSTAGES * GSTAGE_BYTES) // 144 KB

__global__ void __launch_bounds__(256, 1) gemm3_kernel(
    const __nv_bfloat16* __restrict__ A, const __nv_bfloat16* __restrict__ B,
    const float* __restrict__ add, float* __restrict__ C,
    __nv_bfloat16* __restrict__ out3,
    int M, int N, int K3, int mode)
{
    extern __shared__ __align__(128) char smem[];
    const uint32_t smem_base = smem_u32(smem);

    const int tid  = threadIdx.x;
    const int lane = tid & 31;
    const int warp = tid >> 5;
    const int wm = warp >> 2;        // 0..1 (64 rows each)
    const int wn = warp & 3;         // 0..3 (64 cols each)
    const int bx = blockIdx.x, by = blockIdx.y;
    const int nk = K3 >> 6;

    // load geometry: p 0..3 -> A (1024 chunks), p 4..11 -> B (2048 chunks)
    int arow[4], aswz[4], brow[8], bswz[8];
#pragma unroll
    for (int p = 0; p < 4; p++) {
        const int id = p * 256 + tid;
        const int row = id >> 3, c = id & 7;
        arow[p] = row;
        aswz[p] = row * 128 + ((c ^ (row & 7)) << 4);
    }
#pragma unroll
    for (int p = 0; p < 8; p++) {
        const int id = p * 256 + tid;
        const int row = id >> 3, c = id & 7;
        brow[p] = row;
        bswz[p] = row * 128 + ((c ^ (row & 7)) << 4);
    }
    const __nv_bfloat16* Abase = A + (size_t)(by * 128) * K3;
    const __nv_bfloat16* Bbase = B + (size_t)(bx * 256) * K3;

    float acc[4][8][4];
#pragma unroll
    for (int i = 0; i < 4; i++)
#pragma unroll
        for (int j = 0; j < 8; j++)
#pragma unroll
            for (int r = 0; r < 4; r++) acc[i][j][r] = 0.f;

    auto load_tile = [&](int ks, int buf) {
        const uint32_t sa = smem_base + buf * GSTAGE_BYTES;
        const uint32_t sb = sa + GA_BYTES;
        const int koff = ks * 64;
#pragma unroll
        for (int p = 0; p < 4; p++) {
            const int c = (p * 256 + tid) & 7;
            CP_ASYNC16(sa + aswz[p], Abase + (size_t)arow[p] * K3 + koff + c * 8);
        }
#pragma unroll
        for (int p = 0; p < 8; p++) {
            const int c = (p * 256 + tid) & 7;
            CP_ASYNC16(sb + bswz[p], Bbase + (size_t)brow[p] * K3 + koff + c * 8);
        }
    };

    load_tile(0, 0); CP_COMMIT();
    load_tile(1, 1); CP_COMMIT();

    for (int ks = 0; ks < nk; ks++) {
        CP_WAIT1();
        __syncthreads();
        if (ks + 2 < nk) load_tile(ks + 2, (ks + 2) % GSTAGES);
        CP_COMMIT();

        const int buf = ks % GSTAGES;
        const uint32_t sa = smem_base + buf * GSTAGE_BYTES;
        const uint32_t sb = sa + GA_BYTES;

#pragma unroll
        for (int kk = 0; kk < 4; kk++) {
            uint32_t ra[4][4];
#pragma unroll
            for (int mt = 0; mt < 4; mt++) {
                const int row = wm * 64 + mt * 16 + (lane & 15);
                const int ch  = kk * 2 + (lane >> 4);
                LDSM4(ra[mt], sa + row * 128 + ((ch ^ (row & 7)) << 4));
            }
            uint32_t rb[4][4];
#pragma unroll
            for (int p = 0; p < 4; p++) {
                const int n  = wn * 64 + p * 16 + (lane & 7) + ((lane >> 4) << 3);
                const int ch = kk * 2 + ((lane >> 3) & 1);
                LDSM4(rb[p], sb + n * 128 + ((ch ^ (n & 7)) << 4));
            }
#pragma unroll
            for (int mt = 0; mt < 4; mt++)
#pragma unroll
                for (int nt = 0; nt < 8; nt++)
                    MMA16816(acc[mt][nt], ra[mt],
                             rb[nt >> 1][(nt & 1) * 2], rb[nt >> 1][(nt & 1) * 2 + 1]);
        }
    }

    // epilogue
    const int r0 = lane >> 2;
    const int c0 = (lane & 3) * 2;
#pragma unroll
    for (int mt = 0; mt < 4; mt++) {
#pragma unroll
        for (int half = 0; half < 2; half++) {
            const int row = by * 128 + wm * 64 + mt * 16 + r0 + half * 8;
            const int colb = bx * 256 + wn * 64;
            if (mode == 3) {
                const float* Ur = add + (size_t)row * N + colb;
                __nv_bfloat16* Or = out3 + (size_t)row * (3 * N) + colb;
#pragma unroll
                for (int nt = 0; nt < 8; nt++) {
                    const float2 uv = *(const float2*)(Ur + nt * 8 + c0);
                    float g0 = acc[mt][nt][half * 2];
                    float g1 = acc[mt][nt][half * 2 + 1];
                    g0 = g0 / (1.f + expf(-g0)) * uv.x;
                    g1 = g1 / (1.f + expf(-g1)) * uv.y;
                    const int c = nt * 8 + c0;
                    __nv_bfloat16 h0 = __float2bfloat16(g0);
                    __nv_bfloat16 h1 = __float2bfloat16(g1);
                    __nv_bfloat16 l0 = __float2bfloat16(g0 - __bfloat162float(h0));
                    __nv_bfloat16 l1 = __float2bfloat16(g1 - __bfloat162float(h1));
                    Or[c] = h0; Or[c + 1] = h1;
                    Or[N + c] = l0; Or[N + c + 1] = l1;
                    Or[2 * N + c] = h0; Or[2 * N + c + 1] = h1;
                }
            } else {
                float* Cr = C + (size_t)row * N + colb;
                const float* Ar = (mode == 1) ? add + (size_t)row * N + colb : nullptr;
#pragma unroll
                for (int nt = 0; nt < 8; nt++) {
                    float2 o;
                    o.x = acc[mt][nt][half * 2];
                    o.y = acc[mt][nt][half * 2 + 1];
                    if (Ar) {
                        const float2 av = *(const float2*)(Ar + nt * 8 + c0);
                        o.x += av.x; o.y += av.y;
                    }
                    *(float2*)(Cr + nt * 8 + c0) = o;
                }
            }
        }
    }
}

// ---------------------------------------------------------------------------
// Flash attention, bf16 HMMA w/ 3-split, fp32 online softmax.
// Block: 128 q-rows x one head. 256 thr = 8 warps (16 q-rows each).
// Writes ctx directly as bf16 3-split [hi|lo|hi] into ctx3 (stride 3*HID).
// ---------------------------------------------------------------------------
#define QS_STRIDE 200     // 192 data + 8 pad (bf16 elems)
#define VT_STRIDE 136     // 128 + 8 pad
#define FA_SMEM   (2*(128*QS_STRIDE*2) + 2*(64*VT_STRIDE*2))   // 137216 B

__global__ void __launch_bounds__(256, 1) flash_attn_kernel(
    const float* __restrict__ q, const float* __restrict__ k,
    const float* __restrict__ v, const float* __restrict__ mask,
    __nv_bfloat16* __restrict__ ctx3)
{
    extern __shared__ __align__(128) char smem[];
    __nv_bfloat16* Qs  = (__nv_bfloat16*)smem;
    __nv_bfloat16* Ks  = Qs + 128 * QS_STRIDE;
    __nv_bfloat16* Vth = Ks + 128 * QS_STRIDE;
    __nv_bfloat16* Vtl = Vth + 64 * VT_STRIDE;
    const uint32_t QsB  = smem_u32(Qs);
    const uint32_t KsB  = smem_u32(Ks);
    const uint32_t VthB = smem_u32(Vth);
    const uint32_t VtlB = smem_u32(Vtl);

    const int tid  = threadIdx.x;
    const int lane = tid & 31;
    const int w    = tid >> 5;
    const int bh = blockIdx.y;
    const int b = bh >> 5, h = bh & 31;
    const int q0 = blockIdx.x * 128;

    // ---- load Q tile once, 3-split [Qh|Ql|Qh] ----
#pragma unroll
    for (int p = 0; p < 8; p++) {
        const int id = p * 256 + tid;          // 0..2047
        const int row = id >> 4;
        const int c4  = (id & 15) * 4;
        const float4 vv = *(const float4*)(q + (size_t)(b * SS + q0 + row) * HID + h * HD + c4);
        const float xs[4] = {vv.x, vv.y, vv.z, vv.w};
#pragma unroll
        for (int j = 0; j < 4; j++) {
            __nv_bfloat16 hi = __float2bfloat16(xs[j]);
            __nv_bfloat16 lo = __float2bfloat16(xs[j] - __bfloat162float(hi));
            Qs[row * QS_STRIDE + c4 + j]       = hi;
            Qs[row * QS_STRIDE + 64 + c4 + j]  = lo;
            Qs[row * QS_STRIDE + 128 + c4 + j] = hi;
        }
    }

    float sc[64];          // 16 n-tiles x 4
    float o[8][4];
#pragma unroll
    for (int j = 0; j < 8; j++)
#pragma unroll
        for (int r = 0; r < 4; r++) o[j][r] = 0.f;
    float mrow[2] = {-INFINITY, -INFINITY};
    float lrow[2] = {0.f, 0.f};

    const int rA = lane >> 2;
    const int cA = (lane & 3) * 2;

    for (int kt = 0; kt < SS / 128; kt++) {
        __syncthreads();
        // ---- load K tile, split [Kh|Kh|Kl] ----
#pragma unroll
        for (int p = 0; p < 8; p++) {
            const int id = p * 256 + tid;
            const int row = id >> 4;
            const int c4  = (id & 15) * 4;
            const float4 vv = *(const float4*)(k + (size_t)(b * SS + kt * 128 + row) * HID + h * HD + c4);
            const float xs[4] = {vv.x, vv.y, vv.z, vv.w};
#pragma unroll
            for (int j = 0; j < 4; j++) {
                __nv_bfloat16 hi = __float2bfloat16(xs[j]);
                __nv_bfloat16 lo = __float2bfloat16(xs[j] - __bfloat162float(hi));
                Ks[row * QS_STRIDE + c4 + j]       = hi;
                Ks[row * QS_STRIDE + 64 + c4 + j]  = hi;
                Ks[row * QS_STRIDE + 128 + c4 + j] = lo;
            }
        }
        // ---- load V tile transposed, hi/lo ----
#pragma unroll
        for (int p = 0; p < 8; p++) {
            const int id = p * 256 + tid;
            const int krow = id >> 4;
            const int c4   = (id & 15) * 4;
            const float4 vv = *(const float4*)(v + (size_t)(b * SS + kt * 128 + krow) * HID + h * HD + c4);
            const float xs[4] = {vv.x, vv.y, vv.z, vv.w};
#pragma unroll
            for (int j = 0; j < 4; j++) {
                __nv_bfloat16 hi = __float2bfloat16(xs[j]);
                __nv_bfloat16 lo = __float2bfloat16(xs[j] - __bfloat162float(hi));
                Vth[(c4 + j) * VT_STRIDE + krow] = hi;
                Vtl[(c4 + j) * VT_STRIDE + krow] = lo;
            }
        }
        __syncthreads();

        // ---- scores: S = Q3 . K3^T  (K3=192) ----
#pragma unroll
        for (int i = 0; i < 64; i++) sc[i] = 0.f;
#pragma unroll
        for (int s = 0; s < 12; s++) {
            uint32_t ra[4];
            const int arow2 = 16 * w + (lane & 15);
            LDSM4(ra, QsB + (arow2 * QS_STRIDE + s * 16 + ((lane >> 4) << 3)) * 2);
#pragma unroll
            for (int t2 = 0; t2 < 8; t2++) {
                uint32_t rb[4];
                const int n  = t2 * 16 + (lane & 7) + ((lane >> 4) << 3);
                const int cb = s * 16 + (((lane >> 3) & 1) << 3);
                LDSM4(rb, KsB + (n * QS_STRIDE + cb) * 2);
                MMA16816((sc + (2 * t2) * 4),     ra, rb[0], rb[1]);
                MMA16816((sc + (2 * t2 + 1) * 4), ra, rb[2], rb[3]);
            }
        }

        // ---- scale + mask, online softmax ----
        const int qrA = q0 + 16 * w + rA;
        const int qrB = qrA + 8;
        float tm[2] = {-INFINITY, -INFINITY};
#pragma unroll
        for (int t = 0; t < 16; t++) {
            const int kc = kt * 128 + t * 8 + cA;
            const float2 mA = *(const float2*)(mask + ((size_t)b * SS + qrA) * SS + kc);
            const float2 mB = *(const float2*)(mask + ((size_t)b * SS + qrB) * SS + kc);
            sc[t * 4 + 0] = sc[t * 4 + 0] * 0.125f + mA.x;
            sc[t * 4 + 1] = sc[t * 4 + 1] * 0.125f + mA.y;
            sc[t * 4 + 2] = sc[t * 4 + 2] * 0.125f + mB.x;
            sc[t * 4 + 3] = sc[t * 4 + 3] * 0.125f + mB.y;
            tm[0] = fmaxf(tm[0], fmaxf(sc[t * 4 + 0], sc[t * 4 + 1]));
            tm[1] = fmaxf(tm[1], fmaxf(sc[t * 4 + 2], sc[t * 4 + 3]));
        }
#pragma unroll
        for (int off = 1; off <= 2; off <<= 1) {
            tm[0] = fmaxf(tm[0], __shfl_xor_sync(0xffffffffu, tm[0], off));
            tm[1] = fmaxf(tm[1], __shfl_xor_sync(0xffffffffu, tm[1], off));
        }
        const float mn0 = fmaxf(mrow[0], tm[0]);
        const float mn1 = fmaxf(mrow[1], tm[1]);
        const float sc0 = __expf(mrow[0] - mn0);
        const float sc1 = __expf(mrow[1] - mn1);
        float ts[2] = {0.f, 0.f};
#pragma unroll
        for (int t = 0; t < 16; t++) {
            sc[t * 4 + 0] = __expf(sc[t * 4 + 0] - mn0);
            sc[t * 4 + 1] = __expf(sc[t * 4 + 1] - mn0);
            sc[t * 4 + 2] = __expf(sc[t * 4 + 2] - mn1);
            sc[t * 4 + 3] = __expf(sc[t * 4 + 3] - mn1);
            ts[0] += sc[t * 4 + 0] + sc[t * 4 + 1];
            ts[1] += sc[t * 4 + 2] + sc[t * 4 + 3];
        }
#pragma unroll
        for (int off = 1; off <= 2; off <<= 1) {
            ts[0] += __shfl_xor_sync(0xffffffffu, ts[0], off);
            ts[1] += __shfl_xor_sync(0xffffffffu, ts[1], off);
        }
        lrow[0] = lrow[0] * sc0 + ts[0];
        lrow[1] = lrow[1] * sc1 + ts[1];
        mrow[0] = mn0; mrow[1] = mn1;
#pragma unroll
        for (int j = 0; j < 8; j++) {
            o[j][0] *= sc0; o[j][1] *= sc0;
            o[j][2] *= sc1; o[j][3] *= sc1;
        }

        // ---- O += P3 . V3 (3-term split) ----
#pragma unroll
        for (int s2 = 0; s2 < 8; s2++) {
            const float p00 = sc[(2 * s2) * 4 + 0], p01 = sc[(2 * s2) * 4 + 1];
            const float p10 = sc[(2 * s2) * 4 + 2], p11 = sc[(2 * s2) * 4 + 3];
            const float r00 = sc[(2 * s2 + 1) * 4 + 0], r01 = sc[(2 * s2 + 1) * 4 + 1];
            const float r10 = sc[(2 * s2 + 1) * 4 + 2], r11 = sc[(2 * s2 + 1) * 4 + 3];
            uint32_t ph[4], pl[4];
            ph[0] = pack_bf2(p00, p01); ph[1] = pack_bf2(p10, p11);
            ph[2] = pack_bf2(r00, r01); ph[3] = pack_bf2(r10, r11);
            pl[0] = pack_bf2(p00 - __bfloat162float(__float2bfloat16(p00)),
                             p01 - __bfloat162float(__float2bfloat16(p01)));
            pl[1] = pack_bf2(p10 - __bfloat162float(__float2bfloat16(p10)),
                             p11 - __bfloat162float(__float2bfloat16(p11)));
            pl[2] = pack_bf2(r00 - __bfloat162float(__float2bfloat16(r00)),
                             r01 - __bfloat162float(__float2bfloat16(r01)));
            pl[3] = pack_bf2(r10 - __bfloat162float(__float2bfloat16(r10)),
                             r11 - __bfloat162float(__float2bfloat16(r11)));
#pragma unroll
            for (int dt = 0; dt < 4; dt++) {
                uint32_t bh_[4], bl_[4];
                const int n  = dt * 16 + (lane & 7) + ((lane >> 4) << 3);
                const int cb = s2 * 16 + (((lane >> 3) & 1) << 3);
                LDSM4(bh_, VthB + (n * VT_STRIDE + cb) * 2);
                LDSM4(bl_, VtlB + (n * VT_STRIDE + cb) * 2);
                MMA16816(o[2 * dt],     ph, bh_[0], bh_[1]);
                MMA16816(o[2 * dt + 1], ph, bh_[2], bh_[3]);
                MMA16816(o[2 * dt],     pl, bh_[0], bh_[1]);
                MMA16816(o[2 * dt + 1], pl, bh_[2], bh_[3]);
                MMA16816(o[2 * dt],     ph, bl_[0], bl_[1]);
                MMA16816(o[2 * dt + 1], ph, bl_[2], bl_[3]);
            }
        }
    }

    // ---- epilogue: normalize, write bf16 3-split ctx ----
    const float inv0 = 1.f / lrow[0];
    const float inv1 = 1.f / lrow[1];
    const size_t tokA = (size_t)(b * SS + q0 + 16 * w + rA);
    const size_t tokB = tokA + 8;
#pragma unroll
    for (int j = 0; j < 8; j++) {
        const int cg = h * HD + j * 8 + cA;
#pragma unroll
        for (int e = 0; e < 2; e++) {
            {
                const float val = o[j][e] * inv0;
                __nv_bfloat16 hi = __float2bfloat16(val);
                __nv_bfloat16 lo = __float2bfloat16(val - __bfloat162float(hi));
                __nv_bfloat16* p = ctx3 + tokA * (3 * HID) + cg + e;
                p[0] = hi; p[HID] = lo; p[2 * HID] = hi;
            }
            {
                const float val = o[j][2 + e] * inv1;
                __nv_bfloat16 hi = __float2bfloat16(val);
                __nv_bfloat16 lo = __float2bfloat16(val - __bfloat162float(hi));
                __nv_bfloat16* p = ctx3 + tokB * (3 * HID) + cg + e;
                p[0] = hi; p[HID] = lo; p[2 * HID] = hi;
            }
        }
    }
}

// ---------------------------------------------------------------------------
// fp32 -> bf16 3-split. brole=0: [hi|lo|hi]  brole=1: [hi|hi|lo]
// ---------------------------------------------------------------------------
__global__ void __launch_bounds__(256) split3_kernel(
    const float* __restrict__ X, __nv_bfloat16* __restrict__ Y, int C, int brole)
{
    const size_t e = ((size_t)blockIdx.x * 256 + threadIdx.x) * 4;
    const size_t r = e / (size_t)C;
    const int   c = (int)(e - r * (size_t)C);
    const float4 v = *(const float4*)(X + e);
    float xs[4] = {v.x, v.y, v.z, v.w};
    uint32_t hpx = 0, hpy = 0, lpx = 0, lpy = 0;
#pragma unroll
    for (int j = 0; j < 4; j++) {
        __nv_bfloat16 h = __float2bfloat16(xs[j]);
        __nv_bfloat16 l = __float2bfloat16(xs[j] - __bfloat162float(h));
        uint32_t hu = (uint32_t)__bfloat16_as_ushort(h);
        uint32_t lu = (uint32_t)__bfloat16_as_ushort(l);
        if (j < 2) { hpx |= hu << (16 * j); lpx |= lu << (16 * j); }
        else       { hpy |= hu << (16 * (j - 2)); lpy |= lu << (16 * (j - 2)); }
    }
    uint2 hp = make_uint2(hpx, hpy), lp = make_uint2(lpx, lpy);
    __nv_bfloat16* yb = Y + r * (size_t)(3 * C) + c;
    *(uint2*)(yb)         = hp;
    *(uint2*)(yb + C)     = brole ? hp : lp;
    *(uint2*)(yb + 2 * C) = brole ? lp : hp;
}

// ---------------------------------------------------------------------------
// LayerNorm
// ---------------------------------------------------------------------------
__global__ void __launch_bounds__(256) layernorm_kernel(
    const float* __restrict__ x, const float* __restrict__ w,
    const float* __restrict__ b, float* __restrict__ out)
{
    const int t   = blockIdx.x;
    const int tid = threadIdx.x;
    const float* xr = x + (size_t)t * HID;

    float v[8];
    float s = 0.f, s2 = 0.f;
#pragma unroll
    for (int i = 0; i < 8; i++) {
        v[i] = xr[tid + i * 256];
        s  += v[i];
        s2 += v[i] * v[i];
    }
#pragma unroll
    for (int o = 16; o; o >>= 1) {
        s  += __shfl_xor_sync(0xffffffffu, s,  o);
        s2 += __shfl_xor_sync(0xffffffffu, s2, o);
    }
    __shared__ float ss[8], ss2[8];
    if ((tid & 31) == 0) { ss[tid >> 5] = s; ss2[tid >> 5] = s2; }
    __syncthreads();
    if (tid < 32) {
        s  = (tid < 8) ? ss [tid] : 0.f;
        s2 = (tid < 8) ? ss2[tid] : 0.f;
#pragma unroll
        for (int o = 4; o; o >>= 1) {
            s  += __shfl_xor_sync(0xffffffffu, s,  o);
            s2 += __shfl_xor_sync(0xffffffffu, s2, o);
        }
        if (tid == 0) { ss[0] = s; ss2[0] = s2; }
    }
    __syncthreads();
    const float mean = ss[0] * (1.f / HID);
    const float var  = ss2[0] * (1.f / HID) - mean * mean;
    const float rstd = rsqrtf(var + LN_EPS);
    float* orow = out + (size_t)t * HID;
#pragma unroll
    for (int i = 0; i < 8; i++) {
        const int idx = tid + i * 256;
        orow[idx] = (v[i] - mean) * rstd * w[idx] + b[idx];
    }
}

// ---------------------------------------------------------------------------
// Partial RoPE
// ---------------------------------------------------------------------------
__global__ void __launch_bounds__(256) rope_kernel(
    float* __restrict__ q, float* __restrict__ k, const int* __restrict__ pos_ids)
{
    const int idx = blockIdx.x * blockDim.x + threadIdx.x;
    if (idx >= TT * NH * 8) return;
    const int i = idx & 7;
    const int h = (idx >> 3) & 31;
    const int t = idx >> 8;
    const int b = t / SS, s = t % SS;
    const int pos = pos_ids[b * SS + s];

    const float freq = powf(10000.0f, -(2.0f * (float)i) / (float)ROT);
    const float ang  = (float)pos * freq;
    float c, si;
    sincosf(ang, &si, &c);

    const size_t base = (size_t)t * HID + h * HD;
    float q0 = q[base + i], q1 = q[base + i + 8];
    q[base + i]     = q0 * c - q1 * si;
    q[base + i + 8] = q1 * c + q0 * si;
    float k0 = k[base + i], k1 = k[base + i + 8];
    k[base + i]     = k0 * c - k1 * si;
    k[base + i + 8] = k1 * c + k0 * si;
}

// ---------------------------------------------------------------------------
// Launch
// ---------------------------------------------------------------------------
extern "C" void kernel_launch(void* const* d_in, const int* in_sizes, int n_in,
                              void* d_out, int out_size)
{
    const float* hidden = (const float*)d_in[0];
    const float* memory = (const float*)d_in[1];
    const float* mask   = (const float*)d_in[2];
    const int*   pos    = (const int*)  d_in[3];
    const float* Wq     = (const float*)d_in[4];
    const float* Wk     = (const float*)d_in[5];
    const float* Wv     = (const float*)d_in[6];
    const float* Wo     = (const float*)d_in[7];
    const float* ln1w   = (const float*)d_in[8];
    const float* ln1b   = (const float*)d_in[9];
    const float* ln2w   = (const float*)d_in[10];
    const float* ln2b   = (const float*)d_in[11];
    const float* gw     = (const float*)d_in[12];
    const float* uw     = (const float*)d_in[13];
    const float* dw     = (const float*)d_in[14];
    float* out = (float*)d_out;

    float *xln, *q, *k, *v, *h, *yln, *up;
    __nv_bfloat16 *a3, *b3, *c3;
    cudaGetSymbolAddress((void**)&xln,  g_xln);
    cudaGetSymbolAddress((void**)&q,    g_q);
    cudaGetSymbolAddress((void**)&k,    g_k);
    cudaGetSymbolAddress((void**)&v,    g_v);
    cudaGetSymbolAddress((void**)&h,    g_h);
    cudaGetSymbolAddress((void**)&yln,  g_yln);
    cudaGetSymbolAddress((void**)&up,   g_up);
    cudaGetSymbolAddress((void**)&a3,   g_a3);
    cudaGetSymbolAddress((void**)&b3,   g_b3);
    cudaGetSymbolAddress((void**)&c3,   g_c3);

    cudaFuncSetAttribute(gemm3_kernel,
                         cudaFuncAttributeMaxDynamicSharedMemorySize, GEMM_DSMEM);
    cudaFuncSetAttribute(flash_attn_kernel,
                         cudaFuncAttributeMaxDynamicSharedMemorySize, FA_SMEM);

    auto gemm = [&](const __nv_bfloat16* A, const __nv_bfloat16* B,
                    const float* add, float* C, __nv_bfloat16* O3,
                    int M, int N, int K3, int mode) {
        gemm3_kernel<<<dim3(N / 256, M / 128), 256, GEMM_DSMEM>>>(
            A, B, add, C, O3, M, N, K3, mode);
    };
    auto split = [&](const float* X, __nv_bfloat16* Y, int R, int C, int brole) {
        split3_kernel<<<(unsigned)((size_t)R * C / 1024), 256>>>(X, Y, C, brole);
    };

    // 1) LN1
    layernorm_kernel<<<TT, 256>>>(hidden, ln1w, ln1b, xln);

    // 2) Q projection
    split(xln, a3, TT, HID, 0);
    split(Wq,  b3, HID, HID, 1);
    gemm(a3, b3, nullptr, q, nullptr, TT, HID, 3 * HID, 0);

    // 3) K/V projections from memory
    split(memory, a3, TT, HID, 0);
    split(Wk, b3, HID, HID, 1);
    gemm(a3, b3, nullptr, k, nullptr, TT, HID, 3 * HID, 0);
    split(Wv, b3, HID, HID, 1);
    gemm(a3, b3, nullptr, v, nullptr, TT, HID, 3 * HID, 0);

    // 4) RoPE
    rope_kernel<<<(TT * NH * 8) / 256, 256>>>(q, k, pos);

    // 5) fused flash attention -> ctx split directly into a3
    flash_attn_kernel<<<dim3(SS / 128, BB * NH), 256, FA_SMEM>>>(q, k, v, mask, a3);

    // 6) O projection + residual
    split(Wo, b3, HID, HID, 1);
    gemm(a3, b3, hidden, h, nullptr, TT, HID, 3 * HID, 1);

    // 7) LN2
    layernorm_kernel<<<TT, 256>>>(h, ln2w, ln2b, yln);

    // 8) SwiGLU MLP + residual
    split(yln, a3, TT, HID, 0);
    split(uw, b3, DFF, HID, 1);
    gemm(a3, b3, nullptr, up, nullptr, TT, DFF, 3 * HID, 0);
    split(gw, b3, DFF, HID, 1);
    gemm(a3, b3, up, nullptr, c3, TT, DFF, 3 * HID, 3);   // silu*up -> split
    split(dw, b3, HID, DFF, 1);
    gemm(c3, b3, h, out, nullptr, TT, HID, 3 * DFF, 1);
}

// round 6
// speedup vs baseline: 1.4828x; 1.4828x over previous
#include <cuda_runtime.h>
#include <cuda_fp16.h>
#include <math.h>
#include <stdint.h>

// ---------------------------------------------------------------------------
// Problem constants
// ---------------------------------------------------------------------------
#define BB     2
#define SS     1024
#define TT     (BB*SS)        // 2048 tokens
#define HID    2048
#define NH     32
#define HD     64
#define ROT    16
#define DFF    8192
#define LN_EPS 1e-5f

// ---------------------------------------------------------------------------
// Static scratch (no allocations allowed)
// ---------------------------------------------------------------------------
__device__ float g_xln[(size_t)TT * HID];
__device__ float g_q  [(size_t)TT * HID];
__device__ float g_k  [(size_t)TT * HID];
__device__ float g_v  [(size_t)TT * HID];
__device__ float g_h  [(size_t)TT * HID];
__device__ float g_yln[(size_t)TT * HID];
__device__ float g_up [(size_t)TT * DFF];

// fp16 2-split scratch
__device__ __half g_a2[(size_t)TT * (2 * HID)];        // activation splits / ctx split
__device__ __half g_b2[(size_t)DFF * (2 * HID)];       // weight splits (down fits too)
__device__ __half g_c2[(size_t)TT * (2 * DFF)];        // activated-gate split

// ---------------------------------------------------------------------------
// helpers
// ---------------------------------------------------------------------------
__device__ __forceinline__ uint32_t smem_u32(const void* p) {
    uint32_t a;
    asm("{ .reg .u64 t; cvta.to.shared.u64 t, %1; cvt.u32.u64 %0, t; }"
        : "=r"(a) : "l"(p));
    return a;
}

#define CP_ASYNC16(sa, ga) \
    asm volatile("cp.async.cg.shared.global [%0], [%1], 16;" :: "r"(sa), "l"(ga))
#define CP_COMMIT() asm volatile("cp.async.commit_group;")
#define CP_WAIT1()  asm volatile("cp.async.wait_group 1;")

#define LDSM4(r, addr) \
    asm volatile("ldmatrix.sync.aligned.m8n8.x4.shared.b16 {%0,%1,%2,%3}, [%4];" \
        : "=r"((r)[0]), "=r"((r)[1]), "=r"((r)[2]), "=r"((r)[3]) : "r"(addr))

#define MMA16816(d, a, b0, b1) \
    asm volatile("mma.sync.aligned.m16n8k16.row.col.f32.f16.f16.f32 " \
        "{%0,%1,%2,%3}, {%4,%5,%6,%7}, {%8,%9}, {%0,%1,%2,%3};" \
        : "+f"((d)[0]), "+f"((d)[1]), "+f"((d)[2]), "+f"((d)[3]) \
        : "r"((a)[0]), "r"((a)[1]), "r"((a)[2]), "r"((a)[3]), "r"(b0), "r"(b1))

__device__ __forceinline__ uint32_t pack_h2(float a, float b) {
    uint32_t h0 = (uint32_t)__half_as_ushort(__float2half_rn(a));
    uint32_t h1 = (uint32_t)__half_as_ushort(__float2half_rn(b));
    return h0 | (h1 << 16);
}

// ---------------------------------------------------------------------------
// HMMA fp16 GEMM:  C[M,N] = A2[M,K2] * B2[N,K2]^T
// mode 0: C fp32   mode 1: C = acc + add   mode 3: silu(acc)*add -> fp16 split
// 128x128 tile, BK=64, 3-stage cp.async, 256 thr, warp tile 64x32
// ---------------------------------------------------------------------------
#define GSTAGES      3
#define GTILE_BYTES  16384
#define GSTAGE_BYTES (2 * GTILE_BYTES)
#define GEMM_DSMEM   (GSTAGES * GSTAGE_BYTES)   // 96 KB

__global__ void __launch_bounds__(256, 2) gemm2_kernel(
    const __half* __restrict__ A, const __half* __restrict__ B,
    const float* __restrict__ add, float* __restrict__ C,
    __half* __restrict__ out2,
    int M, int N, int K2, int mode)
{
    extern __shared__ __align__(128) char smem[];
    const uint32_t smem_base = smem_u32(smem);

    const int tid  = threadIdx.x;
    const int lane = tid & 31;
    const int warp = tid >> 5;
    const int wm = warp >> 2;
    const int wn = warp & 3;
    const int bx = blockIdx.x, by = blockIdx.y;
    const int nk = K2 >> 6;

    int lrow[4], lswz[4];
#pragma unroll
    for (int p = 0; p < 4; p++) {
        const int id = p * 256 + tid;
        const int row = id >> 3;
        const int c   = id & 7;
        lrow[p] = row;
        lswz[p] = row * 128 + ((c ^ (row & 7)) << 4);
    }
    const __half* Abase = A + (size_t)(by * 128) * K2;
    const __half* Bbase = B + (size_t)(bx * 128) * K2;

    float acc[4][4][4];
#pragma unroll
    for (int i = 0; i < 4; i++)
#pragma unroll
        for (int j = 0; j < 4; j++)
#pragma unroll
            for (int r = 0; r < 4; r++) acc[i][j][r] = 0.f;

    auto load_tile = [&](int ks, int buf) {
        const uint32_t sa = smem_base + buf * GSTAGE_BYTES;
        const uint32_t sb = sa + GTILE_BYTES;
        const int koff = ks * 64;
#pragma unroll
        for (int p = 0; p < 4; p++) {
            const int id = p * 256 + tid;
            const int c  = id & 7;
            CP_ASYNC16(sa + lswz[p], Abase + (size_t)lrow[p] * K2 + koff + c * 8);
            CP_ASYNC16(sb + lswz[p], Bbase + (size_t)lrow[p] * K2 + koff + c * 8);
        }
    };

    load_tile(0, 0); CP_COMMIT();
    load_tile(1, 1); CP_COMMIT();

    for (int ks = 0; ks < nk; ks++) {
        CP_WAIT1();
        __syncthreads();
        if (ks + 2 < nk) load_tile(ks + 2, (ks + 2) % GSTAGES);
        CP_COMMIT();

        const int buf = ks % GSTAGES;
        const uint32_t sa = smem_base + buf * GSTAGE_BYTES;
        const uint32_t sb = sa + GTILE_BYTES;

#pragma unroll
        for (int kk = 0; kk < 4; kk++) {
            uint32_t ra[4][4];
#pragma unroll
            for (int mt = 0; mt < 4; mt++) {
                const int row = wm * 64 + mt * 16 + (lane & 15);
                const int ch  = kk * 2 + (lane >> 4);
                LDSM4(ra[mt], sa + row * 128 + ((ch ^ (row & 7)) << 4));
            }
            uint32_t rb[2][4];
#pragma unroll
            for (int pr = 0; pr < 2; pr++) {
                const int n  = wn * 32 + pr * 16 + (lane & 7) + ((lane >> 4) << 3);
                const int ch = kk * 2 + ((lane >> 3) & 1);
                LDSM4(rb[pr], sb + n * 128 + ((ch ^ (n & 7)) << 4));
            }
#pragma unroll
            for (int mt = 0; mt < 4; mt++)
#pragma unroll
                for (int nt = 0; nt < 4; nt++)
                    MMA16816(acc[mt][nt], ra[mt],
                             rb[nt >> 1][(nt & 1) * 2], rb[nt >> 1][(nt & 1) * 2 + 1]);
        }
    }

    // epilogue
    const int r0 = lane >> 2;
    const int c0 = (lane & 3) * 2;
#pragma unroll
    for (int mt = 0; mt < 4; mt++) {
#pragma unroll
        for (int half_ = 0; half_ < 2; half_++) {
            const int row = by * 128 + wm * 64 + mt * 16 + r0 + half_ * 8;
            const int colb = bx * 128 + wn * 32;
            if (mode == 3) {
                const float* Ur = add + (size_t)row * N + colb;
                __half* Or = out2 + (size_t)row * (2 * N) + colb;
#pragma unroll
                for (int nt = 0; nt < 4; nt++) {
                    const float2 uv = *(const float2*)(Ur + nt * 8 + c0);
                    float g0 = acc[mt][nt][half_ * 2];
                    float g1 = acc[mt][nt][half_ * 2 + 1];
                    g0 = g0 / (1.f + expf(-g0)) * uv.x;
                    g1 = g1 / (1.f + expf(-g1)) * uv.y;
                    const int c = nt * 8 + c0;
                    __half h0 = __float2half_rn(g0);
                    __half h1 = __float2half_rn(g1);
                    __half l0 = __float2half_rn(g0 - __half2float(h0));
                    __half l1 = __float2half_rn(g1 - __half2float(h1));
                    Or[c] = h0; Or[c + 1] = h1;
                    Or[N + c] = l0; Or[N + c + 1] = l1;
                }
            } else {
                float* Cr = C + (size_t)row * N + colb;
                const float* Ar = (mode == 1) ? add + (size_t)row * N + colb : nullptr;
#pragma unroll
                for (int nt = 0; nt < 4; nt++) {
                    float2 o;
                    o.x = acc[mt][nt][half_ * 2];
                    o.y = acc[mt][nt][half_ * 2 + 1];
                    if (Ar) {
                        const float2 av = *(const float2*)(Ar + nt * 8 + c0);
                        o.x += av.x; o.y += av.y;
                    }
                    *(float2*)(Cr + nt * 8 + c0) = o;
                }
            }
        }
    }
}

// ---------------------------------------------------------------------------
// Flash attention, fp16 HMMA w/ 3-split (scores+PV exact-ish), fp32 softmax.
// Block: 128 q-rows x one head. 256 thr = 8 warps (16 q-rows each).
// Writes ctx as fp16 2-split [hi|lo] into ctx2 (row stride 2*HID).
// ---------------------------------------------------------------------------
#define QS_STRIDE 200     // 192 data + 8 pad (fp16 elems)
#define VT_STRIDE 136     // 128 + 8 pad
#define FA_SMEM   (2*(128*QS_STRIDE*2) + 2*(64*VT_STRIDE*2))   // 137216 B

__global__ void __launch_bounds__(256, 1) flash_attn_kernel(
    const float* __restrict__ q, const float* __restrict__ k,
    const float* __restrict__ v, const float* __restrict__ mask,
    __half* __restrict__ ctx2)
{
    extern __shared__ __align__(128) char smem[];
    __half* Qs  = (__half*)smem;
    __half* Ks  = Qs + 128 * QS_STRIDE;
    __half* Vth = Ks + 128 * QS_STRIDE;
    __half* Vtl = Vth + 64 * VT_STRIDE;
    const uint32_t QsB  = smem_u32(Qs);
    const uint32_t KsB  = smem_u32(Ks);
    const uint32_t VthB = smem_u32(Vth);
    const uint32_t VtlB = smem_u32(Vtl);

    const int tid  = threadIdx.x;
    const int lane = tid & 31;
    const int w    = tid >> 5;
    const int bh = blockIdx.y;
    const int b = bh >> 5, h = bh & 31;
    const int q0 = blockIdx.x * 128;

    // ---- load Q tile once, 3-split [Qh|Ql|Qh] ----
#pragma unroll
    for (int p = 0; p < 8; p++) {
        const int id = p * 256 + tid;
        const int row = id >> 4;
        const int c4  = (id & 15) * 4;
        const float4 vv = *(const float4*)(q + (size_t)(b * SS + q0 + row) * HID + h * HD + c4);
        const float xs[4] = {vv.x, vv.y, vv.z, vv.w};
#pragma unroll
        for (int j = 0; j < 4; j++) {
            __half hi = __float2half_rn(xs[j]);
            __half lo = __float2half_rn(xs[j] - __half2float(hi));
            Qs[row * QS_STRIDE + c4 + j]       = hi;
            Qs[row * QS_STRIDE + 64 + c4 + j]  = lo;
            Qs[row * QS_STRIDE + 128 + c4 + j] = hi;
        }
    }

    float sc[64];
    float o[8][4];
#pragma unroll
    for (int j = 0; j < 8; j++)
#pragma unroll
        for (int r = 0; r < 4; r++) o[j][r] = 0.f;
    float mrow[2] = {-INFINITY, -INFINITY};
    float lrow[2] = {0.f, 0.f};

    const int rA = lane >> 2;
    const int cA = (lane & 3) * 2;

    for (int kt = 0; kt < SS / 128; kt++) {
        __syncthreads();
        // ---- load K tile, split [Kh|Kh|Kl] ----
#pragma unroll
        for (int p = 0; p < 8; p++) {
            const int id = p * 256 + tid;
            const int row = id >> 4;
            const int c4  = (id & 15) * 4;
            const float4 vv = *(const float4*)(k + (size_t)(b * SS + kt * 128 + row) * HID + h * HD + c4);
            const float xs[4] = {vv.x, vv.y, vv.z, vv.w};
#pragma unroll
            for (int j = 0; j < 4; j++) {
                __half hi = __float2half_rn(xs[j]);
                __half lo = __float2half_rn(xs[j] - __half2float(hi));
                Ks[row * QS_STRIDE + c4 + j]       = hi;
                Ks[row * QS_STRIDE + 64 + c4 + j]  = hi;
                Ks[row * QS_STRIDE + 128 + c4 + j] = lo;
            }
        }
        // ---- load V tile transposed, hi/lo ----
#pragma unroll
        for (int p = 0; p < 8; p++) {
            const int id = p * 256 + tid;
            const int krow = id >> 4;
            const int c4   = (id & 15) * 4;
            const float4 vv = *(const float4*)(v + (size_t)(b * SS + kt * 128 + krow) * HID + h * HD + c4);
            const float xs[4] = {vv.x, vv.y, vv.z, vv.w};
#pragma unroll
            for (int j = 0; j < 4; j++) {
                __half hi = __float2half_rn(xs[j]);
                __half lo = __float2half_rn(xs[j] - __half2float(hi));
                Vth[(c4 + j) * VT_STRIDE + krow] = hi;
                Vtl[(c4 + j) * VT_STRIDE + krow] = lo;
            }
        }
        __syncthreads();

        // ---- scores: S = Q3 . K3^T  (K3=192) ----
#pragma unroll
        for (int i = 0; i < 64; i++) sc[i] = 0.f;
#pragma unroll
        for (int s = 0; s < 12; s++) {
            uint32_t ra[4];
            const int arow2 = 16 * w + (lane & 15);
            LDSM4(ra, QsB + (arow2 * QS_STRIDE + s * 16 + ((lane >> 4) << 3)) * 2);
#pragma unroll
            for (int t2 = 0; t2 < 8; t2++) {
                uint32_t rb[4];
                const int n  = t2 * 16 + (lane & 7) + ((lane >> 4) << 3);
                const int cb = s * 16 + (((lane >> 3) & 1) << 3);
                LDSM4(rb, KsB + (n * QS_STRIDE + cb) * 2);
                MMA16816((sc + (2 * t2) * 4),     ra, rb[0], rb[1]);
                MMA16816((sc + (2 * t2 + 1) * 4), ra, rb[2], rb[3]);
            }
        }

        // ---- scale + mask, online softmax ----
        const int qrA = q0 + 16 * w + rA;
        const int qrB = qrA + 8;
        float tm[2] = {-INFINITY, -INFINITY};
#pragma unroll
        for (int t = 0; t < 16; t++) {
            const int kc = kt * 128 + t * 8 + cA;
            const float2 mA = *(const float2*)(mask + ((size_t)b * SS + qrA) * SS + kc);
            const float2 mB = *(const float2*)(mask + ((size_t)b * SS + qrB) * SS + kc);
            sc[t * 4 + 0] = sc[t * 4 + 0] * 0.125f + mA.x;
            sc[t * 4 + 1] = sc[t * 4 + 1] * 0.125f + mA.y;
            sc[t * 4 + 2] = sc[t * 4 + 2] * 0.125f + mB.x;
            sc[t * 4 + 3] = sc[t * 4 + 3] * 0.125f + mB.y;
            tm[0] = fmaxf(tm[0], fmaxf(sc[t * 4 + 0], sc[t * 4 + 1]));
            tm[1] = fmaxf(tm[1], fmaxf(sc[t * 4 + 2], sc[t * 4 + 3]));
        }
#pragma unroll
        for (int off = 1; off <= 2; off <<= 1) {
            tm[0] = fmaxf(tm[0], __shfl_xor_sync(0xffffffffu, tm[0], off));
            tm[1] = fmaxf(tm[1], __shfl_xor_sync(0xffffffffu, tm[1], off));
        }
        const float mn0 = fmaxf(mrow[0], tm[0]);
        const float mn1 = fmaxf(mrow[1], tm[1]);
        const float sc0 = __expf(mrow[0] - mn0);
        const float sc1 = __expf(mrow[1] - mn1);
        float ts[2] = {0.f, 0.f};
#pragma unroll
        for (int t = 0; t < 16; t++) {
            sc[t * 4 + 0] = __expf(sc[t * 4 + 0] - mn0);
            sc[t * 4 + 1] = __expf(sc[t * 4 + 1] - mn0);
            sc[t * 4 + 2] = __expf(sc[t * 4 + 2] - mn1);
            sc[t * 4 + 3] = __expf(sc[t * 4 + 3] - mn1);
            ts[0] += sc[t * 4 + 0] + sc[t * 4 + 1];
            ts[1] += sc[t * 4 + 2] + sc[t * 4 + 3];
        }
#pragma unroll
        for (int off = 1; off <= 2; off <<= 1) {
            ts[0] += __shfl_xor_sync(0xffffffffu, ts[0], off);
            ts[1] += __shfl_xor_sync(0xffffffffu, ts[1], off);
        }
        lrow[0] = lrow[0] * sc0 + ts[0];
        lrow[1] = lrow[1] * sc1 + ts[1];
        mrow[0] = mn0; mrow[1] = mn1;
#pragma unroll
        for (int j = 0; j < 8; j++) {
            o[j][0] *= sc0; o[j][1] *= sc0;
            o[j][2] *= sc1; o[j][3] *= sc1;
        }

        // ---- O += P3 . V3 (3-term split) ----
#pragma unroll
        for (int s2 = 0; s2 < 8; s2++) {
            const float p00 = sc[(2 * s2) * 4 + 0], p01 = sc[(2 * s2) * 4 + 1];
            const float p10 = sc[(2 * s2) * 4 + 2], p11 = sc[(2 * s2) * 4 + 3];
            const float r00 = sc[(2 * s2 + 1) * 4 + 0], r01 = sc[(2 * s2 + 1) * 4 + 1];
            const float r10 = sc[(2 * s2 + 1) * 4 + 2], r11 = sc[(2 * s2 + 1) * 4 + 3];
            uint32_t ph[4], pl[4];
            ph[0] = pack_h2(p00, p01); ph[1] = pack_h2(p10, p11);
            ph[2] = pack_h2(r00, r01); ph[3] = pack_h2(r10, r11);
            pl[0] = pack_h2(p00 - __half2float(__float2half_rn(p00)),
                            p01 - __half2float(__float2half_rn(p01)));
            pl[1] = pack_h2(p10 - __half2float(__float2half_rn(p10)),
                            p11 - __half2float(__float2half_rn(p11)));
            pl[2] = pack_h2(r00 - __half2float(__float2half_rn(r00)),
                            r01 - __half2float(__float2half_rn(r01)));
            pl[3] = pack_h2(r10 - __half2float(__float2half_rn(r10)),
                            r11 - __half2float(__float2half_rn(r11)));
#pragma unroll
            for (int dt = 0; dt < 4; dt++) {
                uint32_t bh_[4], bl_[4];
                const int n  = dt * 16 + (lane & 7) + ((lane >> 4) << 3);
                const int cb = s2 * 16 + (((lane >> 3) & 1) << 3);
                LDSM4(bh_, VthB + (n * VT_STRIDE + cb) * 2);
                LDSM4(bl_, VtlB + (n * VT_STRIDE + cb) * 2);
                MMA16816(o[2 * dt],     ph, bh_[0], bh_[1]);
                MMA16816(o[2 * dt + 1], ph, bh_[2], bh_[3]);
                MMA16816(o[2 * dt],     pl, bh_[0], bh_[1]);
                MMA16816(o[2 * dt + 1], pl, bh_[2], bh_[3]);
                MMA16816(o[2 * dt],     ph, bl_[0], bl_[1]);
                MMA16816(o[2 * dt + 1], ph, bl_[2], bl_[3]);
            }
        }
    }

    // ---- epilogue: normalize, write fp16 2-split ctx ----
    const float inv0 = 1.f / lrow[0];
    const float inv1 = 1.f / lrow[1];
    const size_t tokA = (size_t)(b * SS + q0 + 16 * w + rA);
    const size_t tokB = tokA + 8;
#pragma unroll
    for (int j = 0; j < 8; j++) {
        const int cg = h * HD + j * 8 + cA;
#pragma unroll
        for (int e = 0; e < 2; e++) {
            {
                const float val = o[j][e] * inv0;
                __half hi = __float2half_rn(val);
                __half lo = __float2half_rn(val - __half2float(hi));
                __half* p = ctx2 + tokA * (2 * HID) + cg + e;
                p[0] = hi; p[HID] = lo;
            }
            {
                const float val = o[j][2 + e] * inv1;
                __half hi = __float2half_rn(val);
                __half lo = __float2half_rn(val - __half2float(hi));
                __half* p = ctx2 + tokB * (2 * HID) + cg + e;
                p[0] = hi; p[HID] = lo;
            }
        }
    }
}

// ---------------------------------------------------------------------------
// fp32 -> fp16 2-split. brole=0: [hi|lo]  brole=1: [hi|hi]
// ---------------------------------------------------------------------------
__global__ void __launch_bounds__(256) split2_kernel(
    const float* __restrict__ X, __half* __restrict__ Y, int C, int brole)
{
    const size_t e = ((size_t)blockIdx.x * 256 + threadIdx.x) * 4;
    const size_t r = e / (size_t)C;
    const int   c = (int)(e - r * (size_t)C);
    const float4 v = *(const float4*)(X + e);
    float xs[4] = {v.x, v.y, v.z, v.w};
    uint32_t hpx = 0, hpy = 0, lpx = 0, lpy = 0;
#pragma unroll
    for (int j = 0; j < 4; j++) {
        __half h = __float2half_rn(xs[j]);
        __half l = __float2half_rn(xs[j] - __half2float(h));
        uint32_t hu = (uint32_t)__half_as_ushort(h);
        uint32_t lu = (uint32_t)__half_as_ushort(l);
        if (j < 2) { hpx |= hu << (16 * j); lpx |= lu << (16 * j); }
        else       { hpy |= hu << (16 * (j - 2)); lpy |= lu << (16 * (j - 2)); }
    }
    uint2 hp = make_uint2(hpx, hpy), lp = make_uint2(lpx, lpy);
    __half* yb = Y + r * (size_t)(2 * C) + c;
    *(uint2*)(yb)     = hp;
    *(uint2*)(yb + C) = brole ? hp : lp;
}

// ---------------------------------------------------------------------------
// LayerNorm
// ---------------------------------------------------------------------------
__global__ void __launch_bounds__(256) layernorm_kernel(
    const float* __restrict__ x, const float* __restrict__ w,
    const float* __restrict__ b, float* __restrict__ out)
{
    const int t   = blockIdx.x;
    const int tid = threadIdx.x;
    const float* xr = x + (size_t)t * HID;

    float v[8];
    float s = 0.f, s2 = 0.f;
#pragma unroll
    for (int i = 0; i < 8; i++) {
        v[i] = xr[tid + i * 256];
        s  += v[i];
        s2 += v[i] * v[i];
    }
#pragma unroll
    for (int o = 16; o; o >>= 1) {
        s  += __shfl_xor_sync(0xffffffffu, s,  o);
        s2 += __shfl_xor_sync(0xffffffffu, s2, o);
    }
    __shared__ float ss[8], ss2[8];
    if ((tid & 31) == 0) { ss[tid >> 5] = s; ss2[tid >> 5] = s2; }
    __syncthreads();
    if (tid < 32) {
        s  = (tid < 8) ? ss [tid] : 0.f;
        s2 = (tid < 8) ? ss2[tid] : 0.f;
#pragma unroll
        for (int o = 4; o; o >>= 1) {
            s  += __shfl_xor_sync(0xffffffffu, s,  o);
            s2 += __shfl_xor_sync(0xffffffffu, s2, o);
        }
        if (tid == 0) { ss[0] = s; ss2[0] = s2; }
    }
    __syncthreads();
    const float mean = ss[0] * (1.f / HID);
    const float var  = ss2[0] * (1.f / HID) - mean * mean;
    const float rstd = rsqrtf(var + LN_EPS);
    float* orow = out + (size_t)t * HID;
#pragma unroll
    for (int i = 0; i < 8; i++) {
        const int idx = tid + i * 256;
        orow[idx] = (v[i] - mean) * rstd * w[idx] + b[idx];
    }
}

// ---------------------------------------------------------------------------
// Partial RoPE
// ---------------------------------------------------------------------------
__global__ void __launch_bounds__(256) rope_kernel(
    float* __restrict__ q, float* __restrict__ k, const int* __restrict__ pos_ids)
{
    const int idx = blockIdx.x * blockDim.x + threadIdx.x;
    if (idx >= TT * NH * 8) return;
    const int i = idx & 7;
    const int h = (idx >> 3) & 31;
    const int t = idx >> 8;
    const int b = t / SS, s = t % SS;
    const int pos = pos_ids[b * SS + s];

    const float freq = powf(10000.0f, -(2.0f * (float)i) / (float)ROT);
    const float ang  = (float)pos * freq;
    float c, si;
    sincosf(ang, &si, &c);

    const size_t base = (size_t)t * HID + h * HD;
    float q0 = q[base + i], q1 = q[base + i + 8];
    q[base + i]     = q0 * c - q1 * si;
    q[base + i + 8] = q1 * c + q0 * si;
    float k0 = k[base + i], k1 = k[base + i + 8];
    k[base + i]     = k0 * c - k1 * si;
    k[base + i + 8] = k1 * c + k0 * si;
}

// ---------------------------------------------------------------------------
// Launch
// ---------------------------------------------------------------------------
extern "C" void kernel_launch(void* const* d_in, const int* in_sizes, int n_in,
                              void* d_out, int out_size)
{
    const float* hidden = (const float*)d_in[0];
    const float* memory = (const float*)d_in[1];
    const float* mask   = (const float*)d_in[2];
    const int*   pos    = (const int*)  d_in[3];
    const float* Wq     = (const float*)d_in[4];
    const float* Wk     = (const float*)d_in[5];
    const float* Wv     = (const float*)d_in[6];
    const float* Wo     = (const float*)d_in[7];
    const float* ln1w   = (const float*)d_in[8];
    const float* ln1b   = (const float*)d_in[9];
    const float* ln2w   = (const float*)d_in[10];
    const float* ln2b   = (const float*)d_in[11];
    const float* gw     = (const float*)d_in[12];
    const float* uw     = (const float*)d_in[13];
    const float* dw     = (const float*)d_in[14];
    float* out = (float*)d_out;

    float *xln, *q, *k, *v, *h, *yln, *up;
    __half *a2, *b2, *c2;
    cudaGetSymbolAddress((void**)&xln,  g_xln);
    cudaGetSymbolAddress((void**)&q,    g_q);
    cudaGetSymbolAddress((void**)&k,    g_k);
    cudaGetSymbolAddress((void**)&v,    g_v);
    cudaGetSymbolAddress((void**)&h,    g_h);
    cudaGetSymbolAddress((void**)&yln,  g_yln);
    cudaGetSymbolAddress((void**)&up,   g_up);
    cudaGetSymbolAddress((void**)&a2,   g_a2);
    cudaGetSymbolAddress((void**)&b2,   g_b2);
    cudaGetSymbolAddress((void**)&c2,   g_c2);

    cudaFuncSetAttribute(gemm2_kernel,
                         cudaFuncAttributeMaxDynamicSharedMemorySize, GEMM_DSMEM);
    cudaFuncSetAttribute(flash_attn_kernel,
                         cudaFuncAttributeMaxDynamicSharedMemorySize, FA_SMEM);

    auto gemm = [&](const __half* A, const __half* B,
                    const float* add, float* C, __half* O2,
                    int M, int N, int K2, int mode) {
        gemm2_kernel<<<dim3(N / 128, M / 128), 256, GEMM_DSMEM>>>(
            A, B, add, C, O2, M, N, K2, mode);
    };
    auto split = [&](const float* X, __half* Y, int R, int C, int brole) {
        split2_kernel<<<(unsigned)((size_t)R * C / 1024), 256>>>(X, Y, C, brole);
    };

    // 1) LN1
    layernorm_kernel<<<TT, 256>>>(hidden, ln1w, ln1b, xln);

    // 2) Q projection
    split(xln, a2, TT, HID, 0);
    split(Wq,  b2, HID, HID, 1);
    gemm(a2, b2, nullptr, q, nullptr, TT, HID, 2 * HID, 0);

    // 3) K/V projections from memory
    split(memory, a2, TT, HID, 0);
    split(Wk, b2, HID, HID, 1);
    gemm(a2, b2, nullptr, k, nullptr, TT, HID, 2 * HID, 0);
    split(Wv, b2, HID, HID, 1);
    gemm(a2, b2, nullptr, v, nullptr, TT, HID, 2 * HID, 0);

    // 4) RoPE
    rope_kernel<<<(TT * NH * 8) / 256, 256>>>(q, k, pos);

    // 5) fused flash attention -> ctx 2-split directly into a2
    flash_attn_kernel<<<dim3(SS / 128, BB * NH), 256, FA_SMEM>>>(q, k, v, mask, a2);

    // 6) O projection + residual
    split(Wo, b2, HID, HID, 1);
    gemm(a2, b2, hidden, h, nullptr, TT, HID, 2 * HID, 1);

    // 7) LN2
    layernorm_kernel<<<TT, 256>>>(h, ln2w, ln2b, yln);

    // 8) SwiGLU MLP + residual
    split(yln, a2, TT, HID, 0);
    split(uw, b2, DFF, HID, 1);
    gemm(a2, b2, nullptr, up, nullptr, TT, DFF, 2 * HID, 0);
    split(gw, b2, DFF, HID, 1);
    gemm(a2, b2, up, nullptr, c2, TT, DFF, 2 * HID, 3);   // silu*up -> split
    split(dw, b2, HID, DFF, 1);
    gemm(c2, b2, h, out, nullptr, TT, HID, 2 * DFF, 1);
}

// round 7
// speedup vs baseline: 1.5515x; 1.0463x over previous
#include <cuda_runtime.h>
#include <cuda_fp16.h>
#include <math.h>
#include <stdint.h>

// ---------------------------------------------------------------------------
// Problem constants
// ---------------------------------------------------------------------------
#define BB     2
#define SS     1024
#define TT     (BB*SS)        // 2048 tokens
#define HID    2048
#define NH     32
#define HD     64
#define ROT    16
#define DFF    8192
#define LN_EPS 1e-5f

// ---------------------------------------------------------------------------
// Static scratch (no allocations allowed)
// ---------------------------------------------------------------------------
__device__ float g_q  [(size_t)TT * HID];
__device__ float g_k  [(size_t)TT * HID];
__device__ float g_v  [(size_t)TT * HID];
__device__ float g_h  [(size_t)TT * HID];
__device__ float g_up [(size_t)TT * DFF];

// fp16 2-split scratch
__device__ __half g_a2[(size_t)TT * (2 * HID)];        // activation splits / ctx split
__device__ __half g_b2[(size_t)DFF * (2 * HID)];       // weight splits
__device__ __half g_c2[(size_t)TT * (2 * DFF)];        // activated-gate split

// ---------------------------------------------------------------------------
// helpers
// ---------------------------------------------------------------------------
__device__ __forceinline__ uint32_t smem_u32(const void* p) {
    uint32_t a;
    asm("{ .reg .u64 t; cvta.to.shared.u64 t, %1; cvt.u32.u64 %0, t; }"
        : "=r"(a) : "l"(p));
    return a;
}

#define CP_ASYNC16(sa, ga) \
    asm volatile("cp.async.cg.shared.global [%0], [%1], 16;" :: "r"(sa), "l"(ga))
#define CP_COMMIT() asm volatile("cp.async.commit_group;")
#define CP_WAIT1()  asm volatile("cp.async.wait_group 1;")

#define LDSM4(r, addr) \
    asm volatile("ldmatrix.sync.aligned.m8n8.x4.shared.b16 {%0,%1,%2,%3}, [%4];" \
        : "=r"((r)[0]), "=r"((r)[1]), "=r"((r)[2]), "=r"((r)[3]) : "r"(addr))

#define MMA16816(d, a, b0, b1) \
    asm volatile("mma.sync.aligned.m16n8k16.row.col.f32.f16.f16.f32 " \
        "{%0,%1,%2,%3}, {%4,%5,%6,%7}, {%8,%9}, {%0,%1,%2,%3};" \
        : "+f"((d)[0]), "+f"((d)[1]), "+f"((d)[2]), "+f"((d)[3]) \
        : "r"((a)[0]), "r"((a)[1]), "r"((a)[2]), "r"((a)[3]), "r"(b0), "r"(b1))

__device__ __forceinline__ uint32_t pack_h2(float a, float b) {
    uint32_t h0 = (uint32_t)__half_as_ushort(__float2half_rn(a));
    uint32_t h1 = (uint32_t)__half_as_ushort(__float2half_rn(b));
    return h0 | (h1 << 16);
}

// ---------------------------------------------------------------------------
// HMMA fp16 GEMM:  C[M,N] = A2[M,K2] * B2[N,K2]^T
// mode 0: C fp32   mode 1: C = acc + add   mode 3: silu(acc)*add -> fp16 split
// 128x128 tile, BK=64, 3-stage cp.async, 128 thr = 4 warps, warp tile 64x64
// (2 CTAs/SM: low LDSM duplication + sync overlap)
// ---------------------------------------------------------------------------
#define GSTAGES      3
#define GTILE_BYTES  16384
#define GSTAGE_BYTES (2 * GTILE_BYTES)
#define GEMM_DSMEM   (GSTAGES * GSTAGE_BYTES)   // 96 KB

__global__ void __launch_bounds__(128, 2) gemm2_kernel(
    const __half* __restrict__ A, const __half* __restrict__ B,
    const float* __restrict__ add, float* __restrict__ C,
    __half* __restrict__ out2,
    int M, int N, int K2, int mode)
{
    extern __shared__ __align__(128) char smem[];
    const uint32_t smem_base = smem_u32(smem);

    const int tid  = threadIdx.x;
    const int lane = tid & 31;
    const int warp = tid >> 5;       // 0..3
    const int wm = warp >> 1;        // 0..1 (64 rows)
    const int wn = warp & 1;         // 0..1 (64 cols)
    const int bx = blockIdx.x, by = blockIdx.y;
    const int nk = K2 >> 6;

    // 8 chunks per tile per thread (128 rows x 8 chunks = 1024, /128 thr)
    int lrow[8], lswz[8];
#pragma unroll
    for (int p = 0; p < 8; p++) {
        const int id = p * 128 + tid;
        const int row = id >> 3;
        const int c   = id & 7;
        lrow[p] = row;
        lswz[p] = row * 128 + ((c ^ (row & 7)) << 4);
    }
    const __half* Abase = A + (size_t)(by * 128) * K2;
    const __half* Bbase = B + (size_t)(bx * 128) * K2;

    float acc[4][8][4];
#pragma unroll
    for (int i = 0; i < 4; i++)
#pragma unroll
        for (int j = 0; j < 8; j++)
#pragma unroll
            for (int r = 0; r < 4; r++) acc[i][j][r] = 0.f;

    auto load_tile = [&](int ks, int buf) {
        const uint32_t sa = smem_base + buf * GSTAGE_BYTES;
        const uint32_t sb = sa + GTILE_BYTES;
        const int koff = ks * 64;
#pragma unroll
        for (int p = 0; p < 8; p++) {
            const int c = (p * 128 + tid) & 7;
            CP_ASYNC16(sa + lswz[p], Abase + (size_t)lrow[p] * K2 + koff + c * 8);
            CP_ASYNC16(sb + lswz[p], Bbase + (size_t)lrow[p] * K2 + koff + c * 8);
        }
    };

    load_tile(0, 0); CP_COMMIT();
    load_tile(1, 1); CP_COMMIT();

    for (int ks = 0; ks < nk; ks++) {
        CP_WAIT1();
        __syncthreads();
        if (ks + 2 < nk) load_tile(ks + 2, (ks + 2) % GSTAGES);
        CP_COMMIT();

        const int buf = ks % GSTAGES;
        const uint32_t sa = smem_base + buf * GSTAGE_BYTES;
        const uint32_t sb = sa + GTILE_BYTES;

#pragma unroll
        for (int kk = 0; kk < 4; kk++) {
            uint32_t ra[4][4];
#pragma unroll
            for (int mt = 0; mt < 4; mt++) {
                const int row = wm * 64 + mt * 16 + (lane & 15);
                const int ch  = kk * 2 + (lane >> 4);
                LDSM4(ra[mt], sa + row * 128 + ((ch ^ (row & 7)) << 4));
            }
            uint32_t rb[4][4];
#pragma unroll
            for (int p = 0; p < 4; p++) {
                const int n  = wn * 64 + p * 16 + (lane & 7) + ((lane >> 4) << 3);
                const int ch = kk * 2 + ((lane >> 3) & 1);
                LDSM4(rb[p], sb + n * 128 + ((ch ^ (n & 7)) << 4));
            }
#pragma unroll
            for (int mt = 0; mt < 4; mt++)
#pragma unroll
                for (int nt = 0; nt < 8; nt++)
                    MMA16816(acc[mt][nt], ra[mt],
                             rb[nt >> 1][(nt & 1) * 2], rb[nt >> 1][(nt & 1) * 2 + 1]);
        }
    }

    // epilogue
    const int r0 = lane >> 2;
    const int c0 = (lane & 3) * 2;
#pragma unroll
    for (int mt = 0; mt < 4; mt++) {
#pragma unroll
        for (int half_ = 0; half_ < 2; half_++) {
            const int row = by * 128 + wm * 64 + mt * 16 + r0 + half_ * 8;
            const int colb = bx * 128 + wn * 64;
            if (mode == 3) {
                const float* Ur = add + (size_t)row * N + colb;
                __half* Or = out2 + (size_t)row * (2 * N) + colb;
#pragma unroll
                for (int nt = 0; nt < 8; nt++) {
                    const float2 uv = *(const float2*)(Ur + nt * 8 + c0);
                    float g0 = acc[mt][nt][half_ * 2];
                    float g1 = acc[mt][nt][half_ * 2 + 1];
                    g0 = g0 / (1.f + expf(-g0)) * uv.x;
                    g1 = g1 / (1.f + expf(-g1)) * uv.y;
                    const int c = nt * 8 + c0;
                    __half h0 = __float2half_rn(g0);
                    __half h1 = __float2half_rn(g1);
                    __half l0 = __float2half_rn(g0 - __half2float(h0));
                    __half l1 = __float2half_rn(g1 - __half2float(h1));
                    Or[c] = h0; Or[c + 1] = h1;
                    Or[N + c] = l0; Or[N + c + 1] = l1;
                }
            } else {
                float* Cr = C + (size_t)row * N + colb;
                const float* Ar = (mode == 1) ? add + (size_t)row * N + colb : nullptr;
#pragma unroll
                for (int nt = 0; nt < 8; nt++) {
                    float2 o;
                    o.x = acc[mt][nt][half_ * 2];
                    o.y = acc[mt][nt][half_ * 2 + 1];
                    if (Ar) {
                        const float2 av = *(const float2*)(Ar + nt * 8 + c0);
                        o.x += av.x; o.y += av.y;
                    }
                    *(float2*)(Cr + nt * 8 + c0) = o;
                }
            }
        }
    }
}

// ---------------------------------------------------------------------------
// Flash attention, fp16 HMMA w/ 3-split, fp32 online softmax.
// Block: 128 q-rows x one head. 256 thr = 8 warps (16 q-rows each).
// Writes ctx as fp16 2-split [hi|lo] into ctx2 (row stride 2*HID).
// ---------------------------------------------------------------------------
#define QS_STRIDE 200     // 192 data + 8 pad (fp16 elems)
#define VT_STRIDE 136     // 128 + 8 pad
#define FA_SMEM   (2*(128*QS_STRIDE*2) + 2*(64*VT_STRIDE*2))   // 137216 B

__global__ void __launch_bounds__(256, 1) flash_attn_kernel(
    const float* __restrict__ q, const float* __restrict__ k,
    const float* __restrict__ v, const float* __restrict__ mask,
    __half* __restrict__ ctx2)
{
    extern __shared__ __align__(128) char smem[];
    __half* Qs  = (__half*)smem;
    __half* Ks  = Qs + 128 * QS_STRIDE;
    __half* Vth = Ks + 128 * QS_STRIDE;
    __half* Vtl = Vth + 64 * VT_STRIDE;
    const uint32_t QsB  = smem_u32(Qs);
    const uint32_t KsB  = smem_u32(Ks);
    const uint32_t VthB = smem_u32(Vth);
    const uint32_t VtlB = smem_u32(Vtl);

    const int tid  = threadIdx.x;
    const int lane = tid & 31;
    const int w    = tid >> 5;
    const int bh = blockIdx.y;
    const int b = bh >> 5, h = bh & 31;
    const int q0 = blockIdx.x * 128;

    // ---- load Q tile once, 3-split [Qh|Ql|Qh] ----
#pragma unroll
    for (int p = 0; p < 8; p++) {
        const int id = p * 256 + tid;
        const int row = id >> 4;
        const int c4  = (id & 15) * 4;
        const float4 vv = *(const float4*)(q + (size_t)(b * SS + q0 + row) * HID + h * HD + c4);
        const float xs[4] = {vv.x, vv.y, vv.z, vv.w};
#pragma unroll
        for (int j = 0; j < 4; j++) {
            __half hi = __float2half_rn(xs[j]);
            __half lo = __float2half_rn(xs[j] - __half2float(hi));
            Qs[row * QS_STRIDE + c4 + j]       = hi;
            Qs[row * QS_STRIDE + 64 + c4 + j]  = lo;
            Qs[row * QS_STRIDE + 128 + c4 + j] = hi;
        }
    }

    float sc[64];
    float o[8][4];
#pragma unroll
    for (int j = 0; j < 8; j++)
#pragma unroll
        for (int r = 0; r < 4; r++) o[j][r] = 0.f;
    float mrow[2] = {-INFINITY, -INFINITY};
    float lrow[2] = {0.f, 0.f};

    const int rA = lane >> 2;
    const int cA = (lane & 3) * 2;

    for (int kt = 0; kt < SS / 128; kt++) {
        __syncthreads();
        // ---- load K tile, split [Kh|Kh|Kl] ----
#pragma unroll
        for (int p = 0; p < 8; p++) {
            const int id = p * 256 + tid;
            const int row = id >> 4;
            const int c4  = (id & 15) * 4;
            const float4 vv = *(const float4*)(k + (size_t)(b * SS + kt * 128 + row) * HID + h * HD + c4);
            const float xs[4] = {vv.x, vv.y, vv.z, vv.w};
#pragma unroll
            for (int j = 0; j < 4; j++) {
                __half hi = __float2half_rn(xs[j]);
                __half lo = __float2half_rn(xs[j] - __half2float(hi));
                Ks[row * QS_STRIDE + c4 + j]       = hi;
                Ks[row * QS_STRIDE + 64 + c4 + j]  = hi;
                Ks[row * QS_STRIDE + 128 + c4 + j] = lo;
            }
        }
        // ---- load V tile transposed, hi/lo ----
#pragma unroll
        for (int p = 0; p < 8; p++) {
            const int id = p * 256 + tid;
            const int krow = id >> 4;
            const int c4   = (id & 15) * 4;
            const float4 vv = *(const float4*)(v + (size_t)(b * SS + kt * 128 + krow) * HID + h * HD + c4);
            const float xs[4] = {vv.x, vv.y, vv.z, vv.w};
#pragma unroll
            for (int j = 0; j < 4; j++) {
                __half hi = __float2half_rn(xs[j]);
                __half lo = __float2half_rn(xs[j] - __half2float(hi));
                Vth[(c4 + j) * VT_STRIDE + krow] = hi;
                Vtl[(c4 + j) * VT_STRIDE + krow] = lo;
            }
        }
        __syncthreads();

        // ---- scores: S = Q3 . K3^T  (K3=192) ----
#pragma unroll
        for (int i = 0; i < 64; i++) sc[i] = 0.f;
#pragma unroll
        for (int s = 0; s < 12; s++) {
            uint32_t ra[4];
            const int arow2 = 16 * w + (lane & 15);
            LDSM4(ra, QsB + (arow2 * QS_STRIDE + s * 16 + ((lane >> 4) << 3)) * 2);
#pragma unroll
            for (int t2 = 0; t2 < 8; t2++) {
                uint32_t rb[4];
                const int n  = t2 * 16 + (lane & 7) + ((lane >> 4) << 3);
                const int cb = s * 16 + (((lane >> 3) & 1) << 3);
                LDSM4(rb, KsB + (n * QS_STRIDE + cb) * 2);
                MMA16816((sc + (2 * t2) * 4),     ra, rb[0], rb[1]);
                MMA16816((sc + (2 * t2 + 1) * 4), ra, rb[2], rb[3]);
            }
        }

        // ---- scale + mask, online softmax ----
        const int qrA = q0 + 16 * w + rA;
        const int qrB = qrA + 8;
        float tm[2] = {-INFINITY, -INFINITY};
#pragma unroll
        for (int t = 0; t < 16; t++) {
            const int kc = kt * 128 + t * 8 + cA;
            const float2 mA = *(const float2*)(mask + ((size_t)b * SS + qrA) * SS + kc);
            const float2 mB = *(const float2*)(mask + ((size_t)b * SS + qrB) * SS + kc);
            sc[t * 4 + 0] = sc[t * 4 + 0] * 0.125f + mA.x;
            sc[t * 4 + 1] = sc[t * 4 + 1] * 0.125f + mA.y;
            sc[t * 4 + 2] = sc[t * 4 + 2] * 0.125f + mB.x;
            sc[t * 4 + 3] = sc[t * 4 + 3] * 0.125f + mB.y;
            tm[0] = fmaxf(tm[0], fmaxf(sc[t * 4 + 0], sc[t * 4 + 1]));
            tm[1] = fmaxf(tm[1], fmaxf(sc[t * 4 + 2], sc[t * 4 + 3]));
        }
#pragma unroll
        for (int off = 1; off <= 2; off <<= 1) {
            tm[0] = fmaxf(tm[0], __shfl_xor_sync(0xffffffffu, tm[0], off));
            tm[1] = fmaxf(tm[1], __shfl_xor_sync(0xffffffffu, tm[1], off));
        }
        const float mn0 = fmaxf(mrow[0], tm[0]);
        const float mn1 = fmaxf(mrow[1], tm[1]);
        const float sc0 = __expf(mrow[0] - mn0);
        const float sc1 = __expf(mrow[1] - mn1);
        float ts[2] = {0.f, 0.f};
#pragma unroll
        for (int t = 0; t < 16; t++) {
            sc[t * 4 + 0] = __expf(sc[t * 4 + 0] - mn0);
            sc[t * 4 + 1] = __expf(sc[t * 4 + 1] - mn0);
            sc[t * 4 + 2] = __expf(sc[t * 4 + 2] - mn1);
            sc[t * 4 + 3] = __expf(sc[t * 4 + 3] - mn1);
            ts[0] += sc[t * 4 + 0] + sc[t * 4 + 1];
            ts[1] += sc[t * 4 + 2] + sc[t * 4 + 3];
        }
#pragma unroll
        for (int off = 1; off <= 2; off <<= 1) {
            ts[0] += __shfl_xor_sync(0xffffffffu, ts[0], off);
            ts[1] += __shfl_xor_sync(0xffffffffu, ts[1], off);
        }
        lrow[0] = lrow[0] * sc0 + ts[0];
        lrow[1] = lrow[1] * sc1 + ts[1];
        mrow[0] = mn0; mrow[1] = mn1;
#pragma unroll
        for (int j = 0; j < 8; j++) {
            o[j][0] *= sc0; o[j][1] *= sc0;
            o[j][2] *= sc1; o[j][3] *= sc1;
        }

        // ---- O += P3 . V3 (3-term split) ----
#pragma unroll
        for (int s2 = 0; s2 < 8; s2++) {
            const float p00 = sc[(2 * s2) * 4 + 0], p01 = sc[(2 * s2) * 4 + 1];
            const float p10 = sc[(2 * s2) * 4 + 2], p11 = sc[(2 * s2) * 4 + 3];
            const float r00 = sc[(2 * s2 + 1) * 4 + 0], r01 = sc[(2 * s2 + 1) * 4 + 1];
            const float r10 = sc[(2 * s2 + 1) * 4 + 2], r11 = sc[(2 * s2 + 1) * 4 + 3];
            uint32_t ph[4], pl[4];
            ph[0] = pack_h2(p00, p01); ph[1] = pack_h2(p10, p11);
            ph[2] = pack_h2(r00, r01); ph[3] = pack_h2(r10, r11);
            pl[0] = pack_h2(p00 - __half2float(__float2half_rn(p00)),
                            p01 - __half2float(__float2half_rn(p01)));
            pl[1] = pack_h2(p10 - __half2float(__float2half_rn(p10)),
                            p11 - __half2float(__float2half_rn(p11)));
            pl[2] = pack_h2(r00 - __half2float(__float2half_rn(r00)),
                            r01 - __half2float(__float2half_rn(r01)));
            pl[3] = pack_h2(r10 - __half2float(__float2half_rn(r10)),
                            r11 - __half2float(__float2half_rn(r11)));
#pragma unroll
            for (int dt = 0; dt < 4; dt++) {
                uint32_t bh_[4], bl_[4];
                const int n  = dt * 16 + (lane & 7) + ((lane >> 4) << 3);
                const int cb = s2 * 16 + (((lane >> 3) & 1) << 3);
                LDSM4(bh_, VthB + (n * VT_STRIDE + cb) * 2);
                LDSM4(bl_, VtlB + (n * VT_STRIDE + cb) * 2);
                MMA16816(o[2 * dt],     ph, bh_[0], bh_[1]);
                MMA16816(o[2 * dt + 1], ph, bh_[2], bh_[3]);
                MMA16816(o[2 * dt],     pl, bh_[0], bh_[1]);
                MMA16816(o[2 * dt + 1], pl, bh_[2], bh_[3]);
                MMA16816(o[2 * dt],     ph, bl_[0], bl_[1]);
                MMA16816(o[2 * dt + 1], ph, bl_[2], bl_[3]);
            }
        }
    }

    // ---- epilogue: normalize, write fp16 2-split ctx ----
    const float inv0 = 1.f / lrow[0];
    const float inv1 = 1.f / lrow[1];
    const size_t tokA = (size_t)(b * SS + q0 + 16 * w + rA);
    const size_t tokB = tokA + 8;
#pragma unroll
    for (int j = 0; j < 8; j++) {
        const int cg = h * HD + j * 8 + cA;
#pragma unroll
        for (int e = 0; e < 2; e++) {
            {
                const float val = o[j][e] * inv0;
                __half hi = __float2half_rn(val);
                __half lo = __float2half_rn(val - __half2float(hi));
                __half* p = ctx2 + tokA * (2 * HID) + cg + e;
                p[0] = hi; p[HID] = lo;
            }
            {
                const float val = o[j][2 + e] * inv1;
                __half hi = __float2half_rn(val);
                __half lo = __float2half_rn(val - __half2float(hi));
                __half* p = ctx2 + tokB * (2 * HID) + cg + e;
                p[0] = hi; p[HID] = lo;
            }
        }
    }
}

// ---------------------------------------------------------------------------
// fp32 -> fp16 2-split. brole=0: [hi|lo]  brole=1: [hi|hi]
// ---------------------------------------------------------------------------
__global__ void __launch_bounds__(256) split2_kernel(
    const float* __restrict__ X, __half* __restrict__ Y, int C, int brole)
{
    const size_t e = ((size_t)blockIdx.x * 256 + threadIdx.x) * 4;
    const size_t r = e / (size_t)C;
    const int   c = (int)(e - r * (size_t)C);
    const float4 v = *(const float4*)(X + e);
    float xs[4] = {v.x, v.y, v.z, v.w};
    uint32_t hpx = 0, hpy = 0, lpx = 0, lpy = 0;
#pragma unroll
    for (int j = 0; j < 4; j++) {
        __half h = __float2half_rn(xs[j]);
        __half l = __float2half_rn(xs[j] - __half2float(h));
        uint32_t hu = (uint32_t)__half_as_ushort(h);
        uint32_t lu = (uint32_t)__half_as_ushort(l);
        if (j < 2) { hpx |= hu << (16 * j); lpx |= lu << (16 * j); }
        else       { hpy |= hu << (16 * (j - 2)); lpy |= lu << (16 * (j - 2)); }
    }
    uint2 hp = make_uint2(hpx, hpy), lp = make_uint2(lpx, lpy);
    __half* yb = Y + r * (size_t)(2 * C) + c;
    *(uint2*)(yb)     = hp;
    *(uint2*)(yb + C) = brole ? hp : lp;
}

// ---------------------------------------------------------------------------
// Fused LayerNorm -> fp16 2-split [hi|lo] (row stride 2*HID)
// ---------------------------------------------------------------------------
__global__ void __launch_bounds__(256) layernorm_split_kernel(
    const float* __restrict__ x, const float* __restrict__ w,
    const float* __restrict__ b, __half* __restrict__ out2)
{
    const int t   = blockIdx.x;
    const int tid = threadIdx.x;
    const float* xr = x + (size_t)t * HID;

    float v[8];
    float s = 0.f, s2 = 0.f;
#pragma unroll
    for (int i = 0; i < 8; i++) {
        v[i] = xr[tid + i * 256];
        s  += v[i];
        s2 += v[i] * v[i];
    }
#pragma unroll
    for (int o = 16; o; o >>= 1) {
        s  += __shfl_xor_sync(0xffffffffu, s,  o);
        s2 += __shfl_xor_sync(0xffffffffu, s2, o);
    }
    __shared__ float ss[8], ss2[8];
    if ((tid & 31) == 0) { ss[tid >> 5] = s; ss2[tid >> 5] = s2; }
    __syncthreads();
    if (tid < 32) {
        s  = (tid < 8) ? ss [tid] : 0.f;
        s2 = (tid < 8) ? ss2[tid] : 0.f;
#pragma unroll
        for (int o = 4; o; o >>= 1) {
            s  += __shfl_xor_sync(0xffffffffu, s,  o);
            s2 += __shfl_xor_sync(0xffffffffu, s2, o);
        }
        if (tid == 0) { ss[0] = s; ss2[0] = s2; }
    }
    __syncthreads();
    const float mean = ss[0] * (1.f / HID);
    const float var  = ss2[0] * (1.f / HID) - mean * mean;
    const float rstd = rsqrtf(var + LN_EPS);
    __half* orow = out2 + (size_t)t * (2 * HID);
#pragma unroll
    for (int i = 0; i < 8; i++) {
        const int idx = tid + i * 256;
        const float y = (v[i] - mean) * rstd * w[idx] + b[idx];
        __half hi = __float2half_rn(y);
        __half lo = __float2half_rn(y - __half2float(hi));
        orow[idx] = hi;
        orow[HID + idx] = lo;
    }
}

// ---------------------------------------------------------------------------
// Partial RoPE
// ---------------------------------------------------------------------------
__global__ void __launch_bounds__(256) rope_kernel(
    float* __restrict__ q, float* __restrict__ k, const int* __restrict__ pos_ids)
{
    const int idx = blockIdx.x * blockDim.x + threadIdx.x;
    if (idx >= TT * NH * 8) return;
    const int i = idx & 7;
    const int h = (idx >> 3) & 31;
    const int t = idx >> 8;
    const int b = t / SS, s = t % SS;
    const int pos = pos_ids[b * SS + s];

    const float freq = powf(10000.0f, -(2.0f * (float)i) / (float)ROT);
    const float ang  = (float)pos * freq;
    float c, si;
    sincosf(ang, &si, &c);

    const size_t base = (size_t)t * HID + h * HD;
    float q0 = q[base + i], q1 = q[base + i + 8];
    q[base + i]     = q0 * c - q1 * si;
    q[base + i + 8] = q1 * c + q0 * si;
    float k0 = k[base + i], k1 = k[base + i + 8];
    k[base + i]     = k0 * c - k1 * si;
    k[base + i + 8] = k1 * c + k0 * si;
}

// ---------------------------------------------------------------------------
// Launch
// ---------------------------------------------------------------------------
extern "C" void kernel_launch(void* const* d_in, const int* in_sizes, int n_in,
                              void* d_out, int out_size)
{
    const float* hidden = (const float*)d_in[0];
    const float* memory = (const float*)d_in[1];
    const float* mask   = (const float*)d_in[2];
    const int*   pos    = (const int*)  d_in[3];
    const float* Wq     = (const float*)d_in[4];
    const float* Wk     = (const float*)d_in[5];
    const float* Wv     = (const float*)d_in[6];
    const float* Wo     = (const float*)d_in[7];
    const float* ln1w   = (const float*)d_in[8];
    const float* ln1b   = (const float*)d_in[9];
    const float* ln2w   = (const float*)d_in[10];
    const float* ln2b   = (const float*)d_in[11];
    const float* gw     = (const float*)d_in[12];
    const float* uw     = (const float*)d_in[13];
    const float* dw     = (const float*)d_in[14];
    float* out = (float*)d_out;

    float *q, *k, *v, *h, *up;
    __half *a2, *b2, *c2;
    cudaGetSymbolAddress((void**)&q,    g_q);
    cudaGetSymbolAddress((void**)&k,    g_k);
    cudaGetSymbolAddress((void**)&v,    g_v);
    cudaGetSymbolAddress((void**)&h,    g_h);
    cudaGetSymbolAddress((void**)&up,   g_up);
    cudaGetSymbolAddress((void**)&a2,   g_a2);
    cudaGetSymbolAddress((void**)&b2,   g_b2);
    cudaGetSymbolAddress((void**)&c2,   g_c2);

    cudaFuncSetAttribute(gemm2_kernel,
                         cudaFuncAttributeMaxDynamicSharedMemorySize, GEMM_DSMEM);
    cudaFuncSetAttribute(flash_attn_kernel,
                         cudaFuncAttributeMaxDynamicSharedMemorySize, FA_SMEM);

    auto gemm = [&](const __half* A, const __half* B,
                    const float* add, float* C, __half* O2,
                    int M, int N, int K2, int mode) {
        gemm2_kernel<<<dim3(N / 128, M / 128), 128, GEMM_DSMEM>>>(
            A, B, add, C, O2, M, N, K2, mode);
    };
    auto split = [&](const float* X, __half* Y, int R, int C, int brole) {
        split2_kernel<<<(unsigned)((size_t)R * C / 1024), 256>>>(X, Y, C, brole);
    };

    // 1) LN1 -> fp16 2-split directly into a2
    layernorm_split_kernel<<<TT, 256>>>(hidden, ln1w, ln1b, a2);

    // 2) Q projection
    split(Wq, b2, HID, HID, 1);
    gemm(a2, b2, nullptr, q, nullptr, TT, HID, 2 * HID, 0);

    // 3) K/V projections from memory
    split(memory, a2, TT, HID, 0);
    split(Wk, b2, HID, HID, 1);
    gemm(a2, b2, nullptr, k, nullptr, TT, HID, 2 * HID, 0);
    split(Wv, b2, HID, HID, 1);
    gemm(a2, b2, nullptr, v, nullptr, TT, HID, 2 * HID, 0);

    // 4) RoPE
    rope_kernel<<<(TT * NH * 8) / 256, 256>>>(q, k, pos);

    // 5) fused flash attention -> ctx 2-split directly into a2
    flash_attn_kernel<<<dim3(SS / 128, BB * NH), 256, FA_SMEM>>>(q, k, v, mask, a2);

    // 6) O projection + residual
    split(Wo, b2, HID, HID, 1);
    gemm(a2, b2, hidden, h, nullptr, TT, HID, 2 * HID, 1);

    // 7) LN2 -> fp16 2-split directly into a2
    layernorm_split_kernel<<<TT, 256>>>(h, ln2w, ln2b, a2);

    // 8) SwiGLU MLP + residual
    split(uw, b2, DFF, HID, 1);
    gemm(a2, b2, nullptr, up, nullptr, TT, DFF, 2 * HID, 0);
    split(gw, b2, DFF, HID, 1);
    gemm(a2, b2, up, nullptr, c2, TT, DFF, 2 * HID, 3);   // silu*up -> split
    split(dw, b2, HID, DFF, 1);
    gemm(c2, b2, h, out, nullptr, TT, HID, 2 * DFF, 1);
}

// round 8
// speedup vs baseline: 2.1011x; 1.3542x over previous
#include <cuda_runtime.h>
#include <cuda_fp16.h>
#include <math.h>
#include <stdint.h>

// ---------------------------------------------------------------------------
// Problem constants
// ---------------------------------------------------------------------------
#define BB     2
#define SS     1024
#define TT     (BB*SS)        // 2048 tokens
#define HID    2048
#define NH     32
#define HD     64
#define ROT    16
#define DFF    8192
#define LN_EPS 1e-5f

// ---------------------------------------------------------------------------
// Static scratch (no allocations allowed)
// ---------------------------------------------------------------------------
__device__ float g_q  [(size_t)TT * HID];
__device__ float g_k  [(size_t)TT * HID];
__device__ float g_v  [(size_t)TT * HID];
__device__ float g_h  [(size_t)TT * HID];
__device__ float g_up [(size_t)TT * DFF];

// fp16 scratch
__device__ __half g_a2[(size_t)TT * (2 * HID)];        // activation splits / ctx split / yln
__device__ __half g_b2[(size_t)DFF * (2 * HID)];       // weight splits / converts
__device__ __half g_c2[(size_t)TT * DFF];              // activated gate (1-term)

// ---------------------------------------------------------------------------
// helpers
// ---------------------------------------------------------------------------
__device__ __forceinline__ uint32_t smem_u32(const void* p) {
    uint32_t a;
    asm("{ .reg .u64 t; cvta.to.shared.u64 t, %1; cvt.u32.u64 %0, t; }"
        : "=r"(a) : "l"(p));
    return a;
}

#define CP_ASYNC16(sa, ga) \
    asm volatile("cp.async.cg.shared.global [%0], [%1], 16;" :: "r"(sa), "l"(ga))
#define CP_COMMIT() asm volatile("cp.async.commit_group;")
#define CP_WAIT1()  asm volatile("cp.async.wait_group 1;")

#define LDSM4(r, addr) \
    asm volatile("ldmatrix.sync.aligned.m8n8.x4.shared.b16 {%0,%1,%2,%3}, [%4];" \
        : "=r"((r)[0]), "=r"((r)[1]), "=r"((r)[2]), "=r"((r)[3]) : "r"(addr))

#define MMA16816(d, a, b0, b1) \
    asm volatile("mma.sync.aligned.m16n8k16.row.col.f32.f16.f16.f32 " \
        "{%0,%1,%2,%3}, {%4,%5,%6,%7}, {%8,%9}, {%0,%1,%2,%3};" \
        : "+f"((d)[0]), "+f"((d)[1]), "+f"((d)[2]), "+f"((d)[3]) \
        : "r"((a)[0]), "r"((a)[1]), "r"((a)[2]), "r"((a)[3]), "r"(b0), "r"(b1))

__device__ __forceinline__ uint32_t pack_h2(float a, float b) {
    uint32_t h0 = (uint32_t)__half_as_ushort(__float2half_rn(a));
    uint32_t h1 = (uint32_t)__half_as_ushort(__float2half_rn(b));
    return h0 | (h1 << 16);
}

// ---------------------------------------------------------------------------
// HMMA fp16 GEMM:  C[M,N] = A[M,K2] * B[N,K2]^T
// mode 0: C fp32   mode 1: C = acc + add   mode 3: silu(acc)*add -> fp16 (1-term)
// 128x128 tile, BK=64, 3-stage cp.async, 128 thr = 4 warps, warp tile 64x64
// ---------------------------------------------------------------------------
#define GSTAGES      3
#define GTILE_BYTES  16384
#define GSTAGE_BYTES (2 * GTILE_BYTES)
#define GEMM_DSMEM   (GSTAGES * GSTAGE_BYTES)   // 96 KB

__global__ void __launch_bounds__(128, 2) gemm2_kernel(
    const __half* __restrict__ A, const __half* __restrict__ B,
    const float* __restrict__ add, float* __restrict__ C,
    __half* __restrict__ out2,
    int M, int N, int K2, int mode)
{
    extern __shared__ __align__(128) char smem[];
    const uint32_t smem_base = smem_u32(smem);

    const int tid  = threadIdx.x;
    const int lane = tid & 31;
    const int warp = tid >> 5;       // 0..3
    const int wm = warp >> 1;        // 0..1 (64 rows)
    const int wn = warp & 1;         // 0..1 (64 cols)
    const int bx = blockIdx.x, by = blockIdx.y;
    const int nk = K2 >> 6;

    int lrow[8], lswz[8];
#pragma unroll
    for (int p = 0; p < 8; p++) {
        const int id = p * 128 + tid;
        const int row = id >> 3;
        const int c   = id & 7;
        lrow[p] = row;
        lswz[p] = row * 128 + ((c ^ (row & 7)) << 4);
    }
    const __half* Abase = A + (size_t)(by * 128) * K2;
    const __half* Bbase = B + (size_t)(bx * 128) * K2;

    float acc[4][8][4];
#pragma unroll
    for (int i = 0; i < 4; i++)
#pragma unroll
        for (int j = 0; j < 8; j++)
#pragma unroll
            for (int r = 0; r < 4; r++) acc[i][j][r] = 0.f;

    auto load_tile = [&](int ks, int buf) {
        const uint32_t sa = smem_base + buf * GSTAGE_BYTES;
        const uint32_t sb = sa + GTILE_BYTES;
        const int koff = ks * 64;
#pragma unroll
        for (int p = 0; p < 8; p++) {
            const int c = (p * 128 + tid) & 7;
            CP_ASYNC16(sa + lswz[p], Abase + (size_t)lrow[p] * K2 + koff + c * 8);
            CP_ASYNC16(sb + lswz[p], Bbase + (size_t)lrow[p] * K2 + koff + c * 8);
        }
    };

    load_tile(0, 0); CP_COMMIT();
    load_tile(1, 1); CP_COMMIT();

    for (int ks = 0; ks < nk; ks++) {
        CP_WAIT1();
        __syncthreads();
        if (ks + 2 < nk) load_tile(ks + 2, (ks + 2) % GSTAGES);
        CP_COMMIT();

        const int buf = ks % GSTAGES;
        const uint32_t sa = smem_base + buf * GSTAGE_BYTES;
        const uint32_t sb = sa + GTILE_BYTES;

#pragma unroll
        for (int kk = 0; kk < 4; kk++) {
            uint32_t ra[4][4];
#pragma unroll
            for (int mt = 0; mt < 4; mt++) {
                const int row = wm * 64 + mt * 16 + (lane & 15);
                const int ch  = kk * 2 + (lane >> 4);
                LDSM4(ra[mt], sa + row * 128 + ((ch ^ (row & 7)) << 4));
            }
            uint32_t rb[4][4];
#pragma unroll
            for (int p = 0; p < 4; p++) {
                const int n  = wn * 64 + p * 16 + (lane & 7) + ((lane >> 4) << 3);
                const int ch = kk * 2 + ((lane >> 3) & 1);
                LDSM4(rb[p], sb + n * 128 + ((ch ^ (n & 7)) << 4));
            }
#pragma unroll
            for (int mt = 0; mt < 4; mt++)
#pragma unroll
                for (int nt = 0; nt < 8; nt++)
                    MMA16816(acc[mt][nt], ra[mt],
                             rb[nt >> 1][(nt & 1) * 2], rb[nt >> 1][(nt & 1) * 2 + 1]);
        }
    }

    // epilogue
    const int r0 = lane >> 2;
    const int c0 = (lane & 3) * 2;
#pragma unroll
    for (int mt = 0; mt < 4; mt++) {
#pragma unroll
        for (int half_ = 0; half_ < 2; half_++) {
            const int row = by * 128 + wm * 64 + mt * 16 + r0 + half_ * 8;
            const int colb = bx * 128 + wn * 64;
            if (mode == 3) {
                // silu(acc) * add -> plain fp16 (1-term)
                const float* Ur = add + (size_t)row * N + colb;
                __half* Or = out2 + (size_t)row * N + colb;
#pragma unroll
                for (int nt = 0; nt < 8; nt++) {
                    const float2 uv = *(const float2*)(Ur + nt * 8 + c0);
                    float g0 = acc[mt][nt][half_ * 2];
                    float g1 = acc[mt][nt][half_ * 2 + 1];
                    g0 = g0 / (1.f + expf(-g0)) * uv.x;
                    g1 = g1 / (1.f + expf(-g1)) * uv.y;
                    const int c = nt * 8 + c0;
                    Or[c]     = __float2half_rn(g0);
                    Or[c + 1] = __float2half_rn(g1);
                }
            } else {
                float* Cr = C + (size_t)row * N + colb;
                const float* Ar = (mode == 1) ? add + (size_t)row * N + colb : nullptr;
#pragma unroll
                for (int nt = 0; nt < 8; nt++) {
                    float2 o;
                    o.x = acc[mt][nt][half_ * 2];
                    o.y = acc[mt][nt][half_ * 2 + 1];
                    if (Ar) {
                        const float2 av = *(const float2*)(Ar + nt * 8 + c0);
                        o.x += av.x; o.y += av.y;
                    }
                    *(float2*)(Cr + nt * 8 + c0) = o;
                }
            }
        }
    }
}

// ---------------------------------------------------------------------------
// Flash attention, fp16 HMMA w/ 3-split, fp32 online softmax.
// Block: 128 q-rows x one head. 256 thr = 8 warps (16 q-rows each).
// Writes ctx as fp16 2-split [hi|lo] into ctx2 (row stride 2*HID).
// ---------------------------------------------------------------------------
#define QS_STRIDE 200     // 192 data + 8 pad (fp16 elems)
#define VT_STRIDE 136     // 128 + 8 pad
#define FA_SMEM   (2*(128*QS_STRIDE*2) + 2*(64*VT_STRIDE*2))   // 137216 B

__global__ void __launch_bounds__(256, 1) flash_attn_kernel(
    const float* __restrict__ q, const float* __restrict__ k,
    const float* __restrict__ v, const float* __restrict__ mask,
    __half* __restrict__ ctx2)
{
    extern __shared__ __align__(128) char smem[];
    __half* Qs  = (__half*)smem;
    __half* Ks  = Qs + 128 * QS_STRIDE;
    __half* Vth = Ks + 128 * QS_STRIDE;
    __half* Vtl = Vth + 64 * VT_STRIDE;
    const uint32_t QsB  = smem_u32(Qs);
    const uint32_t KsB  = smem_u32(Ks);
    const uint32_t VthB = smem_u32(Vth);
    const uint32_t VtlB = smem_u32(Vtl);

    const int tid  = threadIdx.x;
    const int lane = tid & 31;
    const int w    = tid >> 5;
    const int bh = blockIdx.y;
    const int b = bh >> 5, h = bh & 31;
    const int q0 = blockIdx.x * 128;

    // ---- load Q tile once, 3-split [Qh|Ql|Qh] ----
#pragma unroll
    for (int p = 0; p < 8; p++) {
        const int id = p * 256 + tid;
        const int row = id >> 4;
        const int c4  = (id & 15) * 4;
        const float4 vv = *(const float4*)(q + (size_t)(b * SS + q0 + row) * HID + h * HD + c4);
        const float xs[4] = {vv.x, vv.y, vv.z, vv.w};
#pragma unroll
        for (int j = 0; j < 4; j++) {
            __half hi = __float2half_rn(xs[j]);
            __half lo = __float2half_rn(xs[j] - __half2float(hi));
            Qs[row * QS_STRIDE + c4 + j]       = hi;
            Qs[row * QS_STRIDE + 64 + c4 + j]  = lo;
            Qs[row * QS_STRIDE + 128 + c4 + j] = hi;
        }
    }

    float sc[64];
    float o[8][4];
#pragma unroll
    for (int j = 0; j < 8; j++)
#pragma unroll
        for (int r = 0; r < 4; r++) o[j][r] = 0.f;
    float mrow[2] = {-INFINITY, -INFINITY};
    float lrow[2] = {0.f, 0.f};

    const int rA = lane >> 2;
    const int cA = (lane & 3) * 2;

    for (int kt = 0; kt < SS / 128; kt++) {
        __syncthreads();
        // ---- load K tile, split [Kh|Kh|Kl] ----
#pragma unroll
        for (int p = 0; p < 8; p++) {
            const int id = p * 256 + tid;
            const int row = id >> 4;
            const int c4  = (id & 15) * 4;
            const float4 vv = *(const float4*)(k + (size_t)(b * SS + kt * 128 + row) * HID + h * HD + c4);
            const float xs[4] = {vv.x, vv.y, vv.z, vv.w};
#pragma unroll
            for (int j = 0; j < 4; j++) {
                __half hi = __float2half_rn(xs[j]);
                __half lo = __float2half_rn(xs[j] - __half2float(hi));
                Ks[row * QS_STRIDE + c4 + j]       = hi;
                Ks[row * QS_STRIDE + 64 + c4 + j]  = hi;
                Ks[row * QS_STRIDE + 128 + c4 + j] = lo;
            }
        }
        // ---- load V tile transposed, hi/lo ----
#pragma unroll
        for (int p = 0; p < 8; p++) {
            const int id = p * 256 + tid;
            const int krow = id >> 4;
            const int c4   = (id & 15) * 4;
            const float4 vv = *(const float4*)(v + (size_t)(b * SS + kt * 128 + krow) * HID + h * HD + c4);
            const float xs[4] = {vv.x, vv.y, vv.z, vv.w};
#pragma unroll
            for (int j = 0; j < 4; j++) {
                __half hi = __float2half_rn(xs[j]);
                __half lo = __float2half_rn(xs[j] - __half2float(hi));
                Vth[(c4 + j) * VT_STRIDE + krow] = hi;
                Vtl[(c4 + j) * VT_STRIDE + krow] = lo;
            }
        }
        __syncthreads();

        // ---- scores: S = Q3 . K3^T  (K3=192) ----
#pragma unroll
        for (int i = 0; i < 64; i++) sc[i] = 0.f;
#pragma unroll
        for (int s = 0; s < 12; s++) {
            uint32_t ra[4];
            const int arow2 = 16 * w + (lane & 15);
            LDSM4(ra, QsB + (arow2 * QS_STRIDE + s * 16 + ((lane >> 4) << 3)) * 2);
#pragma unroll
            for (int t2 = 0; t2 < 8; t2++) {
                uint32_t rb[4];
                const int n  = t2 * 16 + (lane & 7) + ((lane >> 4) << 3);
                const int cb = s * 16 + (((lane >> 3) & 1) << 3);
                LDSM4(rb, KsB + (n * QS_STRIDE + cb) * 2);
                MMA16816((sc + (2 * t2) * 4),     ra, rb[0], rb[1]);
                MMA16816((sc + (2 * t2 + 1) * 4), ra, rb[2], rb[3]);
            }
        }

        // ---- scale + mask, online softmax ----
        const int qrA = q0 + 16 * w + rA;
        const int qrB = qrA + 8;
        float tm[2] = {-INFINITY, -INFINITY};
#pragma unroll
        for (int t = 0; t < 16; t++) {
            const int kc = kt * 128 + t * 8 + cA;
            const float2 mA = *(const float2*)(mask + ((size_t)b * SS + qrA) * SS + kc);
            const float2 mB = *(const float2*)(mask + ((size_t)b * SS + qrB) * SS + kc);
            sc[t * 4 + 0] = sc[t * 4 + 0] * 0.125f + mA.x;
            sc[t * 4 + 1] = sc[t * 4 + 1] * 0.125f + mA.y;
            sc[t * 4 + 2] = sc[t * 4 + 2] * 0.125f + mB.x;
            sc[t * 4 + 3] = sc[t * 4 + 3] * 0.125f + mB.y;
            tm[0] = fmaxf(tm[0], fmaxf(sc[t * 4 + 0], sc[t * 4 + 1]));
            tm[1] = fmaxf(tm[1], fmaxf(sc[t * 4 + 2], sc[t * 4 + 3]));
        }
#pragma unroll
        for (int off = 1; off <= 2; off <<= 1) {
            tm[0] = fmaxf(tm[0], __shfl_xor_sync(0xffffffffu, tm[0], off));
            tm[1] = fmaxf(tm[1], __shfl_xor_sync(0xffffffffu, tm[1], off));
        }
        const float mn0 = fmaxf(mrow[0], tm[0]);
        const float mn1 = fmaxf(mrow[1], tm[1]);
        const float sc0 = __expf(mrow[0] - mn0);
        const float sc1 = __expf(mrow[1] - mn1);
        float ts[2] = {0.f, 0.f};
#pragma unroll
        for (int t = 0; t < 16; t++) {
            sc[t * 4 + 0] = __expf(sc[t * 4 + 0] - mn0);
            sc[t * 4 + 1] = __expf(sc[t * 4 + 1] - mn0);
            sc[t * 4 + 2] = __expf(sc[t * 4 + 2] - mn1);
            sc[t * 4 + 3] = __expf(sc[t * 4 + 3] - mn1);
            ts[0] += sc[t * 4 + 0] + sc[t * 4 + 1];
            ts[1] += sc[t * 4 + 2] + sc[t * 4 + 3];
        }
#pragma unroll
        for (int off = 1; off <= 2; off <<= 1) {
            ts[0] += __shfl_xor_sync(0xffffffffu, ts[0], off);
            ts[1] += __shfl_xor_sync(0xffffffffu, ts[1], off);
        }
        lrow[0] = lrow[0] * sc0 + ts[0];
        lrow[1] = lrow[1] * sc1 + ts[1];
        mrow[0] = mn0; mrow[1] = mn1;
#pragma unroll
        for (int j = 0; j < 8; j++) {
            o[j][0] *= sc0; o[j][1] *= sc0;
            o[j][2] *= sc1; o[j][3] *= sc1;
        }

        // ---- O += P3 . V3 (3-term split) ----
#pragma unroll
        for (int s2 = 0; s2 < 8; s2++) {
            const float p00 = sc[(2 * s2) * 4 + 0], p01 = sc[(2 * s2) * 4 + 1];
            const float p10 = sc[(2 * s2) * 4 + 2], p11 = sc[(2 * s2) * 4 + 3];
            const float r00 = sc[(2 * s2 + 1) * 4 + 0], r01 = sc[(2 * s2 + 1) * 4 + 1];
            const float r10 = sc[(2 * s2 + 1) * 4 + 2], r11 = sc[(2 * s2 + 1) * 4 + 3];
            uint32_t ph[4], pl[4];
            ph[0] = pack_h2(p00, p01); ph[1] = pack_h2(p10, p11);
            ph[2] = pack_h2(r00, r01); ph[3] = pack_h2(r10, r11);
            pl[0] = pack_h2(p00 - __half2float(__float2half_rn(p00)),
                            p01 - __half2float(__float2half_rn(p01)));
            pl[1] = pack_h2(p10 - __half2float(__float2half_rn(p10)),
                            p11 - __half2float(__float2half_rn(p11)));
            pl[2] = pack_h2(r00 - __half2float(__float2half_rn(r00)),
                            r01 - __half2float(__float2half_rn(r01)));
            pl[3] = pack_h2(r10 - __half2float(__float2half_rn(r10)),
                            r11 - __half2float(__float2half_rn(r11)));
#pragma unroll
            for (int dt = 0; dt < 4; dt++) {
                uint32_t bh_[4], bl_[4];
                const int n  = dt * 16 + (lane & 7) + ((lane >> 4) << 3);
                const int cb = s2 * 16 + (((lane >> 3) & 1) << 3);
                LDSM4(bh_, VthB + (n * VT_STRIDE + cb) * 2);
                LDSM4(bl_, VtlB + (n * VT_STRIDE + cb) * 2);
                MMA16816(o[2 * dt],     ph, bh_[0], bh_[1]);
                MMA16816(o[2 * dt + 1], ph, bh_[2], bh_[3]);
                MMA16816(o[2 * dt],     pl, bh_[0], bh_[1]);
                MMA16816(o[2 * dt + 1], pl, bh_[2], bh_[3]);
                MMA16816(o[2 * dt],     ph, bl_[0], bl_[1]);
                MMA16816(o[2 * dt + 1], ph, bl_[2], bl_[3]);
            }
        }
    }

    // ---- epilogue: normalize, write fp16 2-split ctx ----
    const float inv0 = 1.f / lrow[0];
    const float inv1 = 1.f / lrow[1];
    const size_t tokA = (size_t)(b * SS + q0 + 16 * w + rA);
    const size_t tokB = tokA + 8;
#pragma unroll
    for (int j = 0; j < 8; j++) {
        const int cg = h * HD + j * 8 + cA;
#pragma unroll
        for (int e = 0; e < 2; e++) {
            {
                const float val = o[j][e] * inv0;
                __half hi = __float2half_rn(val);
                __half lo = __float2half_rn(val - __half2float(hi));
                __half* p = ctx2 + tokA * (2 * HID) + cg + e;
                p[0] = hi; p[HID] = lo;
            }
            {
                const float val = o[j][2 + e] * inv1;
                __half hi = __float2half_rn(val);
                __half lo = __float2half_rn(val - __half2float(hi));
                __half* p = ctx2 + tokB * (2 * HID) + cg + e;
                p[0] = hi; p[HID] = lo;
            }
        }
    }
}

// ---------------------------------------------------------------------------
// fp32 -> fp16 2-split. brole=0: [hi|lo]  brole=1: [hi|hi]
// ---------------------------------------------------------------------------
__global__ void __launch_bounds__(256) split2_kernel(
    const float* __restrict__ X, __half* __restrict__ Y, int C, int brole)
{
    const size_t e = ((size_t)blockIdx.x * 256 + threadIdx.x) * 4;
    const size_t r = e / (size_t)C;
    const int   c = (int)(e - r * (size_t)C);
    const float4 v = *(const float4*)(X + e);
    float xs[4] = {v.x, v.y, v.z, v.w};
    uint32_t hpx = 0, hpy = 0, lpx = 0, lpy = 0;
#pragma unroll
    for (int j = 0; j < 4; j++) {
        __half h = __float2half_rn(xs[j]);
        __half l = __float2half_rn(xs[j] - __half2float(h));
        uint32_t hu = (uint32_t)__half_as_ushort(h);
        uint32_t lu = (uint32_t)__half_as_ushort(l);
        if (j < 2) { hpx |= hu << (16 * j); lpx |= lu << (16 * j); }
        else       { hpy |= hu << (16 * (j - 2)); lpy |= lu << (16 * (j - 2)); }
    }
    uint2 hp = make_uint2(hpx, hpy), lp = make_uint2(lpx, lpy);
    __half* yb = Y + r * (size_t)(2 * C) + c;
    *(uint2*)(yb)     = hp;
    *(uint2*)(yb + C) = brole ? hp : lp;
}

// ---------------------------------------------------------------------------
// fp32 -> fp16 plain convert (1-term)
// ---------------------------------------------------------------------------
__global__ void __launch_bounds__(256) conv_kernel(
    const float* __restrict__ X, __half* __restrict__ Y)
{
    const size_t e = ((size_t)blockIdx.x * 256 + threadIdx.x) * 4;
    const float4 v = *(const float4*)(X + e);
    uint2 hp;
    hp.x = pack_h2(v.x, v.y);
    hp.y = pack_h2(v.z, v.w);
    *(uint2*)(Y + e) = hp;
}

// ---------------------------------------------------------------------------
// Fused LayerNorm -> fp16 2-split [hi|lo] (row stride 2*HID)
// ---------------------------------------------------------------------------
__global__ void __launch_bounds__(256) layernorm_split_kernel(
    const float* __restrict__ x, const float* __restrict__ w,
    const float* __restrict__ b, __half* __restrict__ out2)
{
    const int t   = blockIdx.x;
    const int tid = threadIdx.x;
    const float* xr = x + (size_t)t * HID;

    float v[8];
    float s = 0.f, s2 = 0.f;
#pragma unroll
    for (int i = 0; i < 8; i++) {
        v[i] = xr[tid + i * 256];
        s  += v[i];
        s2 += v[i] * v[i];
    }
#pragma unroll
    for (int o = 16; o; o >>= 1) {
        s  += __shfl_xor_sync(0xffffffffu, s,  o);
        s2 += __shfl_xor_sync(0xffffffffu, s2, o);
    }
    __shared__ float ss[8], ss2[8];
    if ((tid & 31) == 0) { ss[tid >> 5] = s; ss2[tid >> 5] = s2; }
    __syncthreads();
    if (tid < 32) {
        s  = (tid < 8) ? ss [tid] : 0.f;
        s2 = (tid < 8) ? ss2[tid] : 0.f;
#pragma unroll
        for (int o = 4; o; o >>= 1) {
            s  += __shfl_xor_sync(0xffffffffu, s,  o);
            s2 += __shfl_xor_sync(0xffffffffu, s2, o);
        }
        if (tid == 0) { ss[0] = s; ss2[0] = s2; }
    }
    __syncthreads();
    const float mean = ss[0] * (1.f / HID);
    const float var  = ss2[0] * (1.f / HID) - mean * mean;
    const float rstd = rsqrtf(var + LN_EPS);
    __half* orow = out2 + (size_t)t * (2 * HID);
#pragma unroll
    for (int i = 0; i < 8; i++) {
        const int idx = tid + i * 256;
        const float y = (v[i] - mean) * rstd * w[idx] + b[idx];
        __half hi = __float2half_rn(y);
        __half lo = __float2half_rn(y - __half2float(hi));
        orow[idx] = hi;
        orow[HID + idx] = lo;
    }
}

// ---------------------------------------------------------------------------
// Fused LayerNorm -> plain fp16 (1-term, row stride HID)
// ---------------------------------------------------------------------------
__global__ void __launch_bounds__(256) layernorm_h_kernel(
    const float* __restrict__ x, const float* __restrict__ w,
    const float* __restrict__ b, __half* __restrict__ outh)
{
    const int t   = blockIdx.x;
    const int tid = threadIdx.x;
    const float* xr = x + (size_t)t * HID;

    float v[8];
    float s = 0.f, s2 = 0.f;
#pragma unroll
    for (int i = 0; i < 8; i++) {
        v[i] = xr[tid + i * 256];
        s  += v[i];
        s2 += v[i] * v[i];
    }
#pragma unroll
    for (int o = 16; o; o >>= 1) {
        s  += __shfl_xor_sync(0xffffffffu, s,  o);
        s2 += __shfl_xor_sync(0xffffffffu, s2, o);
    }
    __shared__ float ss[8], ss2[8];
    if ((tid & 31) == 0) { ss[tid >> 5] = s; ss2[tid >> 5] = s2; }
    __syncthreads();
    if (tid < 32) {
        s  = (tid < 8) ? ss [tid] : 0.f;
        s2 = (tid < 8) ? ss2[tid] : 0.f;
#pragma unroll
        for (int o = 4; o; o >>= 1) {
            s  += __shfl_xor_sync(0xffffffffu, s,  o);
            s2 += __shfl_xor_sync(0xffffffffu, s2, o);
        }
        if (tid == 0) { ss[0] = s; ss2[0] = s2; }
    }
    __syncthreads();
    const float mean = ss[0] * (1.f / HID);
    const float var  = ss2[0] * (1.f / HID) - mean * mean;
    const float rstd = rsqrtf(var + LN_EPS);
    __half* orow = outh + (size_t)t * HID;
#pragma unroll
    for (int i = 0; i < 8; i++) {
        const int idx = tid + i * 256;
        const float y = (v[i] - mean) * rstd * w[idx] + b[idx];
        orow[idx] = __float2half_rn(y);
    }
}

// ---------------------------------------------------------------------------
// Partial RoPE
// ---------------------------------------------------------------------------
__global__ void __launch_bounds__(256) rope_kernel(
    float* __restrict__ q, float* __restrict__ k, const int* __restrict__ pos_ids)
{
    const int idx = blockIdx.x * blockDim.x + threadIdx.x;
    if (idx >= TT * NH * 8) return;
    const int i = idx & 7;
    const int h = (idx >> 3) & 31;
    const int t = idx >> 8;
    const int b = t / SS, s = t % SS;
    const int pos = pos_ids[b * SS + s];

    const float freq = powf(10000.0f, -(2.0f * (float)i) / (float)ROT);
    const float ang  = (float)pos * freq;
    float c, si;
    sincosf(ang, &si, &c);

    const size_t base = (size_t)t * HID + h * HD;
    float q0 = q[base + i], q1 = q[base + i + 8];
    q[base + i]     = q0 * c - q1 * si;
    q[base + i + 8] = q1 * c + q0 * si;
    float k0 = k[base + i], k1 = k[base + i + 8];
    k[base + i]     = k0 * c - k1 * si;
    k[base + i + 8] = k1 * c + k0 * si;
}

// ---------------------------------------------------------------------------
// Launch
// ---------------------------------------------------------------------------
extern "C" void kernel_launch(void* const* d_in, const int* in_sizes, int n_in,
                              void* d_out, int out_size)
{
    const float* hidden = (const float*)d_in[0];
    const float* memory = (const float*)d_in[1];
    const float* mask   = (const float*)d_in[2];
    const int*   pos    = (const int*)  d_in[3];
    const float* Wq     = (const float*)d_in[4];
    const float* Wk     = (const float*)d_in[5];
    const float* Wv     = (const float*)d_in[6];
    const float* Wo     = (const float*)d_in[7];
    const float* ln1w   = (const float*)d_in[8];
    const float* ln1b   = (const float*)d_in[9];
    const float* ln2w   = (const float*)d_in[10];
    const float* ln2b   = (const float*)d_in[11];
    const float* gw     = (const float*)d_in[12];
    const float* uw     = (const float*)d_in[13];
    const float* dw     = (const float*)d_in[14];
    float* out = (float*)d_out;

    float *q, *k, *v, *h, *up;
    __half *a2, *b2, *c2;
    cudaGetSymbolAddress((void**)&q,    g_q);
    cudaGetSymbolAddress((void**)&k,    g_k);
    cudaGetSymbolAddress((void**)&v,    g_v);
    cudaGetSymbolAddress((void**)&h,    g_h);
    cudaGetSymbolAddress((void**)&up,   g_up);
    cudaGetSymbolAddress((void**)&a2,   g_a2);
    cudaGetSymbolAddress((void**)&b2,   g_b2);
    cudaGetSymbolAddress((void**)&c2,   g_c2);

    cudaFuncSetAttribute(gemm2_kernel,
                         cudaFuncAttributeMaxDynamicSharedMemorySize, GEMM_DSMEM);
    cudaFuncSetAttribute(flash_attn_kernel,
                         cudaFuncAttributeMaxDynamicSharedMemorySize, FA_SMEM);

    auto gemm = [&](const __half* A, const __half* B,
                    const float* add, float* C, __half* O2,
                    int M, int N, int K2, int mode) {
        gemm2_kernel<<<dim3(N / 128, M / 128), 128, GEMM_DSMEM>>>(
            A, B, add, C, O2, M, N, K2, mode);
    };
    auto split = [&](const float* X, __half* Y, int R, int C, int brole) {
        split2_kernel<<<(unsigned)((size_t)R * C / 1024), 256>>>(X, Y, C, brole);
    };
    auto conv = [&](const float* X, __half* Y, size_t n) {
        conv_kernel<<<(unsigned)(n / 1024), 256>>>(X, Y);
    };

    // 1) LN1 -> fp16 2-split directly into a2
    layernorm_split_kernel<<<TT, 256>>>(hidden, ln1w, ln1b, a2);

    // 2) Q projection (2-term A, [hi|hi] B)
    split(Wq, b2, HID, HID, 1);
    gemm(a2, b2, nullptr, q, nullptr, TT, HID, 2 * HID, 0);

    // 3) K/V projections from memory (2-term)
    split(memory, a2, TT, HID, 0);
    split(Wk, b2, HID, HID, 1);
    gemm(a2, b2, nullptr, k, nullptr, TT, HID, 2 * HID, 0);
    split(Wv, b2, HID, HID, 1);
    gemm(a2, b2, nullptr, v, nullptr, TT, HID, 2 * HID, 0);

    // 4) RoPE
    rope_kernel<<<(TT * NH * 8) / 256, 256>>>(q, k, pos);

    // 5) fused flash attention -> ctx 2-split directly into a2
    flash_attn_kernel<<<dim3(SS / 128, BB * NH), 256, FA_SMEM>>>(q, k, v, mask, a2);

    // 6) O projection + residual (2-term)
    split(Wo, b2, HID, HID, 1);
    gemm(a2, b2, hidden, h, nullptr, TT, HID, 2 * HID, 1);

    // 7) LN2 -> plain fp16 into a2 (1-term FF path)
    layernorm_h_kernel<<<TT, 256>>>(h, ln2w, ln2b, a2);

    // 8) SwiGLU MLP + residual (1-term fp16 GEMMs, true K)
    conv(uw, b2, (size_t)DFF * HID);
    gemm(a2, b2, nullptr, up, nullptr, TT, DFF, HID, 0);
    conv(gw, b2, (size_t)DFF * HID);
    gemm(a2, b2, up, nullptr, c2, TT, DFF, HID, 3);       // silu*up -> fp16
    conv(dw, b2, (size_t)HID * DFF);
    gemm(c2, b2, h, out, nullptr, TT, HID, DFF, 1);
}

// round 9
// speedup vs baseline: 2.4407x; 1.1616x over previous
#include <cuda_runtime.h>
#include <cuda_fp16.h>
#include <math.h>
#include <stdint.h>

// ---------------------------------------------------------------------------
// Problem constants
// ---------------------------------------------------------------------------
#define BB     2
#define SS     1024
#define TT     (BB*SS)        // 2048 tokens
#define HID    2048
#define NH     32
#define HD     64
#define ROT    16
#define DFF    8192
#define LN_EPS 1e-5f

// ---------------------------------------------------------------------------
// Static scratch (no allocations allowed)
// ---------------------------------------------------------------------------
__device__ float g_q  [(size_t)TT * HID];
__device__ float g_k  [(size_t)TT * HID];
__device__ float g_v  [(size_t)TT * HID];
__device__ float g_h  [(size_t)TT * HID];
__device__ float g_up [(size_t)TT * DFF];

// fp16 scratch
__device__ __half g_a2[(size_t)TT * (2 * HID)];        // activations / ctx
__device__ __half g_b2[(size_t)DFF * (2 * HID)];       // weights
__device__ __half g_c2[(size_t)TT * DFF];              // activated gate

// ---------------------------------------------------------------------------
// helpers
// ---------------------------------------------------------------------------
__device__ __forceinline__ uint32_t smem_u32(const void* p) {
    uint32_t a;
    asm("{ .reg .u64 t; cvta.to.shared.u64 t, %1; cvt.u32.u64 %0, t; }"
        : "=r"(a) : "l"(p));
    return a;
}

#define CP_ASYNC16(sa, ga) \
    asm volatile("cp.async.cg.shared.global [%0], [%1], 16;" :: "r"(sa), "l"(ga))
#define CP_COMMIT() asm volatile("cp.async.commit_group;")
#define CP_WAIT1()  asm volatile("cp.async.wait_group 1;")

#define LDSM4(r, addr) \
    asm volatile("ldmatrix.sync.aligned.m8n8.x4.shared.b16 {%0,%1,%2,%3}, [%4];" \
        : "=r"((r)[0]), "=r"((r)[1]), "=r"((r)[2]), "=r"((r)[3]) : "r"(addr))

#define MMA16816(d, a, b0, b1) \
    asm volatile("mma.sync.aligned.m16n8k16.row.col.f32.f16.f16.f32 " \
        "{%0,%1,%2,%3}, {%4,%5,%6,%7}, {%8,%9}, {%0,%1,%2,%3};" \
        : "+f"((d)[0]), "+f"((d)[1]), "+f"((d)[2]), "+f"((d)[3]) \
        : "r"((a)[0]), "r"((a)[1]), "r"((a)[2]), "r"((a)[3]), "r"(b0), "r"(b1))

__device__ __forceinline__ uint32_t pack_h2(float a, float b) {
    uint32_t h0 = (uint32_t)__half_as_ushort(__float2half_rn(a));
    uint32_t h1 = (uint32_t)__half_as_ushort(__float2half_rn(b));
    return h0 | (h1 << 16);
}

// ---------------------------------------------------------------------------
// HMMA fp16 GEMM:  C[M,N] = A[M,K2] * B[N,K2]^T
// mode 0: C fp32   mode 1: C = acc + add   mode 3: silu(acc)*add -> fp16
// 128x128 tile, BK=64, 3-stage cp.async, 128 thr = 4 warps, warp tile 64x64
// ---------------------------------------------------------------------------
#define GSTAGES      3
#define GTILE_BYTES  16384
#define GSTAGE_BYTES (2 * GTILE_BYTES)
#define GEMM_DSMEM   (GSTAGES * GSTAGE_BYTES)   // 96 KB

__global__ void __launch_bounds__(128, 2) gemm2_kernel(
    const __half* __restrict__ A, const __half* __restrict__ B,
    const float* __restrict__ add, float* __restrict__ C,
    __half* __restrict__ out2,
    int M, int N, int K2, int mode)
{
    extern __shared__ __align__(128) char smem[];
    const uint32_t smem_base = smem_u32(smem);

    const int tid  = threadIdx.x;
    const int lane = tid & 31;
    const int warp = tid >> 5;       // 0..3
    const int wm = warp >> 1;        // 0..1 (64 rows)
    const int wn = warp & 1;         // 0..1 (64 cols)
    const int bx = blockIdx.x, by = blockIdx.y;
    const int nk = K2 >> 6;

    int lrow[8], lswz[8];
#pragma unroll
    for (int p = 0; p < 8; p++) {
        const int id = p * 128 + tid;
        const int row = id >> 3;
        const int c   = id & 7;
        lrow[p] = row;
        lswz[p] = row * 128 + ((c ^ (row & 7)) << 4);
    }
    const __half* Abase = A + (size_t)(by * 128) * K2;
    const __half* Bbase = B + (size_t)(bx * 128) * K2;

    float acc[4][8][4];
#pragma unroll
    for (int i = 0; i < 4; i++)
#pragma unroll
        for (int j = 0; j < 8; j++)
#pragma unroll
            for (int r = 0; r < 4; r++) acc[i][j][r] = 0.f;

    auto load_tile = [&](int ks, int buf) {
        const uint32_t sa = smem_base + buf * GSTAGE_BYTES;
        const uint32_t sb = sa + GTILE_BYTES;
        const int koff = ks * 64;
#pragma unroll
        for (int p = 0; p < 8; p++) {
            const int c = (p * 128 + tid) & 7;
            CP_ASYNC16(sa + lswz[p], Abase + (size_t)lrow[p] * K2 + koff + c * 8);
            CP_ASYNC16(sb + lswz[p], Bbase + (size_t)lrow[p] * K2 + koff + c * 8);
        }
    };

    load_tile(0, 0); CP_COMMIT();
    load_tile(1, 1); CP_COMMIT();

    for (int ks = 0; ks < nk; ks++) {
        CP_WAIT1();
        __syncthreads();
        if (ks + 2 < nk) load_tile(ks + 2, (ks + 2) % GSTAGES);
        CP_COMMIT();

        const int buf = ks % GSTAGES;
        const uint32_t sa = smem_base + buf * GSTAGE_BYTES;
        const uint32_t sb = sa + GTILE_BYTES;

#pragma unroll
        for (int kk = 0; kk < 4; kk++) {
            uint32_t ra[4][4];
#pragma unroll
            for (int mt = 0; mt < 4; mt++) {
                const int row = wm * 64 + mt * 16 + (lane & 15);
                const int ch  = kk * 2 + (lane >> 4);
                LDSM4(ra[mt], sa + row * 128 + ((ch ^ (row & 7)) << 4));
            }
            uint32_t rb[4][4];
#pragma unroll
            for (int p = 0; p < 4; p++) {
                const int n  = wn * 64 + p * 16 + (lane & 7) + ((lane >> 4) << 3);
                const int ch = kk * 2 + ((lane >> 3) & 1);
                LDSM4(rb[p], sb + n * 128 + ((ch ^ (n & 7)) << 4));
            }
#pragma unroll
            for (int mt = 0; mt < 4; mt++)
#pragma unroll
                for (int nt = 0; nt < 8; nt++)
                    MMA16816(acc[mt][nt], ra[mt],
                             rb[nt >> 1][(nt & 1) * 2], rb[nt >> 1][(nt & 1) * 2 + 1]);
        }
    }

    // epilogue
    const int r0 = lane >> 2;
    const int c0 = (lane & 3) * 2;
#pragma unroll
    for (int mt = 0; mt < 4; mt++) {
#pragma unroll
        for (int half_ = 0; half_ < 2; half_++) {
            const int row = by * 128 + wm * 64 + mt * 16 + r0 + half_ * 8;
            const int colb = bx * 128 + wn * 64;
            if (mode == 3) {
                const float* Ur = add + (size_t)row * N + colb;
                __half* Or = out2 + (size_t)row * N + colb;
#pragma unroll
                for (int nt = 0; nt < 8; nt++) {
                    const float2 uv = *(const float2*)(Ur + nt * 8 + c0);
                    float g0 = acc[mt][nt][half_ * 2];
                    float g1 = acc[mt][nt][half_ * 2 + 1];
                    g0 = g0 / (1.f + expf(-g0)) * uv.x;
                    g1 = g1 / (1.f + expf(-g1)) * uv.y;
                    const int c = nt * 8 + c0;
                    Or[c]     = __float2half_rn(g0);
                    Or[c + 1] = __float2half_rn(g1);
                }
            } else {
                float* Cr = C + (size_t)row * N + colb;
                const float* Ar = (mode == 1) ? add + (size_t)row * N + colb : nullptr;
#pragma unroll
                for (int nt = 0; nt < 8; nt++) {
                    float2 o;
                    o.x = acc[mt][nt][half_ * 2];
                    o.y = acc[mt][nt][half_ * 2 + 1];
                    if (Ar) {
                        const float2 av = *(const float2*)(Ar + nt * 8 + c0);
                        o.x += av.x; o.y += av.y;
                    }
                    *(float2*)(Cr + nt * 8 + c0) = o;
                }
            }
        }
    }
}

// ---------------------------------------------------------------------------
// Flash attention, fp16 HMMA w/ 3-split, fp32 online softmax.
// Block: 128 q-rows x one head. 256 thr = 8 warps (16 q-rows each).
// Writes ctx as plain fp16 into ctxh (row stride HID).
// ---------------------------------------------------------------------------
#define QS_STRIDE 200     // 192 data + 8 pad (fp16 elems)
#define VT_STRIDE 136     // 128 + 8 pad
#define FA_SMEM   (2*(128*QS_STRIDE*2) + 2*(64*VT_STRIDE*2))   // 137216 B

__global__ void __launch_bounds__(256, 1) flash_attn_kernel(
    const float* __restrict__ q, const float* __restrict__ k,
    const float* __restrict__ v, const float* __restrict__ mask,
    __half* __restrict__ ctxh)
{
    extern __shared__ __align__(128) char smem[];
    __half* Qs  = (__half*)smem;
    __half* Ks  = Qs + 128 * QS_STRIDE;
    __half* Vth = Ks + 128 * QS_STRIDE;
    __half* Vtl = Vth + 64 * VT_STRIDE;
    const uint32_t QsB  = smem_u32(Qs);
    const uint32_t KsB  = smem_u32(Ks);
    const uint32_t VthB = smem_u32(Vth);
    const uint32_t VtlB = smem_u32(Vtl);

    const int tid  = threadIdx.x;
    const int lane = tid & 31;
    const int w    = tid >> 5;
    const int bh = blockIdx.y;
    const int b = bh >> 5, h = bh & 31;
    const int q0 = blockIdx.x * 128;

    // ---- load Q tile once, 3-split [Qh|Ql|Qh] ----
#pragma unroll
    for (int p = 0; p < 8; p++) {
        const int id = p * 256 + tid;
        const int row = id >> 4;
        const int c4  = (id & 15) * 4;
        const float4 vv = *(const float4*)(q + (size_t)(b * SS + q0 + row) * HID + h * HD + c4);
        const float xs[4] = {vv.x, vv.y, vv.z, vv.w};
#pragma unroll
        for (int j = 0; j < 4; j++) {
            __half hi = __float2half_rn(xs[j]);
            __half lo = __float2half_rn(xs[j] - __half2float(hi));
            Qs[row * QS_STRIDE + c4 + j]       = hi;
            Qs[row * QS_STRIDE + 64 + c4 + j]  = lo;
            Qs[row * QS_STRIDE + 128 + c4 + j] = hi;
        }
    }

    float sc[64];
    float o[8][4];
#pragma unroll
    for (int j = 0; j < 8; j++)
#pragma unroll
        for (int r = 0; r < 4; r++) o[j][r] = 0.f;
    float mrow[2] = {-INFINITY, -INFINITY};
    float lrow[2] = {0.f, 0.f};

    const int rA = lane >> 2;
    const int cA = (lane & 3) * 2;

    for (int kt = 0; kt < SS / 128; kt++) {
        __syncthreads();
        // ---- load K tile, split [Kh|Kh|Kl] ----
#pragma unroll
        for (int p = 0; p < 8; p++) {
            const int id = p * 256 + tid;
            const int row = id >> 4;
            const int c4  = (id & 15) * 4;
            const float4 vv = *(const float4*)(k + (size_t)(b * SS + kt * 128 + row) * HID + h * HD + c4);
            const float xs[4] = {vv.x, vv.y, vv.z, vv.w};
#pragma unroll
            for (int j = 0; j < 4; j++) {
                __half hi = __float2half_rn(xs[j]);
                __half lo = __float2half_rn(xs[j] - __half2float(hi));
                Ks[row * QS_STRIDE + c4 + j]       = hi;
                Ks[row * QS_STRIDE + 64 + c4 + j]  = hi;
                Ks[row * QS_STRIDE + 128 + c4 + j] = lo;
            }
        }
        // ---- load V tile transposed, hi/lo ----
#pragma unroll
        for (int p = 0; p < 8; p++) {
            const int id = p * 256 + tid;
            const int krow = id >> 4;
            const int c4   = (id & 15) * 4;
            const float4 vv = *(const float4*)(v + (size_t)(b * SS + kt * 128 + krow) * HID + h * HD + c4);
            const float xs[4] = {vv.x, vv.y, vv.z, vv.w};
#pragma unroll
            for (int j = 0; j < 4; j++) {
                __half hi = __float2half_rn(xs[j]);
                __half lo = __float2half_rn(xs[j] - __half2float(hi));
                Vth[(c4 + j) * VT_STRIDE + krow] = hi;
                Vtl[(c4 + j) * VT_STRIDE + krow] = lo;
            }
        }
        __syncthreads();

        // ---- scores: S = Q3 . K3^T  (K3=192) ----
#pragma unroll
        for (int i = 0; i < 64; i++) sc[i] = 0.f;
#pragma unroll
        for (int s = 0; s < 12; s++) {
            uint32_t ra[4];
            const int arow2 = 16 * w + (lane & 15);
            LDSM4(ra, QsB + (arow2 * QS_STRIDE + s * 16 + ((lane >> 4) << 3)) * 2);
#pragma unroll
            for (int t2 = 0; t2 < 8; t2++) {
                uint32_t rb[4];
                const int n  = t2 * 16 + (lane & 7) + ((lane >> 4) << 3);
                const int cb = s * 16 + (((lane >> 3) & 1) << 3);
                LDSM4(rb, KsB + (n * QS_STRIDE + cb) * 2);
                MMA16816((sc + (2 * t2) * 4),     ra, rb[0], rb[1]);
                MMA16816((sc + (2 * t2 + 1) * 4), ra, rb[2], rb[3]);
            }
        }

        // ---- scale + mask, online softmax ----
        const int qrA = q0 + 16 * w + rA;
        const int qrB = qrA + 8;
        float tm[2] = {-INFINITY, -INFINITY};
#pragma unroll
        for (int t = 0; t < 16; t++) {
            const int kc = kt * 128 + t * 8 + cA;
            const float2 mA = *(const float2*)(mask + ((size_t)b * SS + qrA) * SS + kc);
            const float2 mB = *(const float2*)(mask + ((size_t)b * SS + qrB) * SS + kc);
            sc[t * 4 + 0] = sc[t * 4 + 0] * 0.125f + mA.x;
            sc[t * 4 + 1] = sc[t * 4 + 1] * 0.125f + mA.y;
            sc[t * 4 + 2] = sc[t * 4 + 2] * 0.125f + mB.x;
            sc[t * 4 + 3] = sc[t * 4 + 3] * 0.125f + mB.y;
            tm[0] = fmaxf(tm[0], fmaxf(sc[t * 4 + 0], sc[t * 4 + 1]));
            tm[1] = fmaxf(tm[1], fmaxf(sc[t * 4 + 2], sc[t * 4 + 3]));
        }
#pragma unroll
        for (int off = 1; off <= 2; off <<= 1) {
            tm[0] = fmaxf(tm[0], __shfl_xor_sync(0xffffffffu, tm[0], off));
            tm[1] = fmaxf(tm[1], __shfl_xor_sync(0xffffffffu, tm[1], off));
        }
        const float mn0 = fmaxf(mrow[0], tm[0]);
        const float mn1 = fmaxf(mrow[1], tm[1]);
        const float sc0 = __expf(mrow[0] - mn0);
        const float sc1 = __expf(mrow[1] - mn1);
        float ts[2] = {0.f, 0.f};
#pragma unroll
        for (int t = 0; t < 16; t++) {
            sc[t * 4 + 0] = __expf(sc[t * 4 + 0] - mn0);
            sc[t * 4 + 1] = __expf(sc[t * 4 + 1] - mn0);
            sc[t * 4 + 2] = __expf(sc[t * 4 + 2] - mn1);
            sc[t * 4 + 3] = __expf(sc[t * 4 + 3] - mn1);
            ts[0] += sc[t * 4 + 0] + sc[t * 4 + 1];
            ts[1] += sc[t * 4 + 2] + sc[t * 4 + 3];
        }
#pragma unroll
        for (int off = 1; off <= 2; off <<= 1) {
            ts[0] += __shfl_xor_sync(0xffffffffu, ts[0], off);
            ts[1] += __shfl_xor_sync(0xffffffffu, ts[1], off);
        }
        lrow[0] = lrow[0] * sc0 + ts[0];
        lrow[1] = lrow[1] * sc1 + ts[1];
        mrow[0] = mn0; mrow[1] = mn1;
#pragma unroll
        for (int j = 0; j < 8; j++) {
            o[j][0] *= sc0; o[j][1] *= sc0;
            o[j][2] *= sc1; o[j][3] *= sc1;
        }

        // ---- O += P3 . V3 (3-term split) ----
#pragma unroll
        for (int s2 = 0; s2 < 8; s2++) {
            const float p00 = sc[(2 * s2) * 4 + 0], p01 = sc[(2 * s2) * 4 + 1];
            const float p10 = sc[(2 * s2) * 4 + 2], p11 = sc[(2 * s2) * 4 + 3];
            const float r00 = sc[(2 * s2 + 1) * 4 + 0], r01 = sc[(2 * s2 + 1) * 4 + 1];
            const float r10 = sc[(2 * s2 + 1) * 4 + 2], r11 = sc[(2 * s2 + 1) * 4 + 3];
            uint32_t ph[4], pl[4];
            ph[0] = pack_h2(p00, p01); ph[1] = pack_h2(p10, p11);
            ph[2] = pack_h2(r00, r01); ph[3] = pack_h2(r10, r11);
            pl[0] = pack_h2(p00 - __half2float(__float2half_rn(p00)),
                            p01 - __half2float(__float2half_rn(p01)));
            pl[1] = pack_h2(p10 - __half2float(__float2half_rn(p10)),
                            p11 - __half2float(__float2half_rn(p11)));
            pl[2] = pack_h2(r00 - __half2float(__float2half_rn(r00)),
                            r01 - __half2float(__float2half_rn(r01)));
            pl[3] = pack_h2(r10 - __half2float(__float2half_rn(r10)),
                            r11 - __half2float(__float2half_rn(r11)));
#pragma unroll
            for (int dt = 0; dt < 4; dt++) {
                uint32_t bh_[4], bl_[4];
                const int n  = dt * 16 + (lane & 7) + ((lane >> 4) << 3);
                const int cb = s2 * 16 + (((lane >> 3) & 1) << 3);
                LDSM4(bh_, VthB + (n * VT_STRIDE + cb) * 2);
                LDSM4(bl_, VtlB + (n * VT_STRIDE + cb) * 2);
                MMA16816(o[2 * dt],     ph, bh_[0], bh_[1]);
                MMA16816(o[2 * dt + 1], ph, bh_[2], bh_[3]);
                MMA16816(o[2 * dt],     pl, bh_[0], bh_[1]);
                MMA16816(o[2 * dt + 1], pl, bh_[2], bh_[3]);
                MMA16816(o[2 * dt],     ph, bl_[0], bl_[1]);
                MMA16816(o[2 * dt + 1], ph, bl_[2], bl_[3]);
            }
        }
    }

    // ---- epilogue: normalize, write plain fp16 ctx ----
    const float inv0 = 1.f / lrow[0];
    const float inv1 = 1.f / lrow[1];
    const size_t tokA = (size_t)(b * SS + q0 + 16 * w + rA);
    const size_t tokB = tokA + 8;
#pragma unroll
    for (int j = 0; j < 8; j++) {
        const int cg = h * HD + j * 8 + cA;
        ctxh[tokA * HID + cg]     = __float2half_rn(o[j][0] * inv0);
        ctxh[tokA * HID + cg + 1] = __float2half_rn(o[j][1] * inv0);
        ctxh[tokB * HID + cg]     = __float2half_rn(o[j][2] * inv1);
        ctxh[tokB * HID + cg + 1] = __float2half_rn(o[j][3] * inv1);
    }
}

// ---------------------------------------------------------------------------
// fp32 -> fp16 plain convert (1-term)
// ---------------------------------------------------------------------------
__global__ void __launch_bounds__(256) conv_kernel(
    const float* __restrict__ X, __half* __restrict__ Y)
{
    const size_t e = ((size_t)blockIdx.x * 256 + threadIdx.x) * 4;
    const float4 v = *(const float4*)(X + e);
    uint2 hp;
    hp.x = pack_h2(v.x, v.y);
    hp.y = pack_h2(v.z, v.w);
    *(uint2*)(Y + e) = hp;
}

// ---------------------------------------------------------------------------
// Fused LayerNorm -> plain fp16 (row stride HID)
// ---------------------------------------------------------------------------
__global__ void __launch_bounds__(256) layernorm_h_kernel(
    const float* __restrict__ x, const float* __restrict__ w,
    const float* __restrict__ b, __half* __restrict__ outh)
{
    const int t   = blockIdx.x;
    const int tid = threadIdx.x;
    const float* xr = x + (size_t)t * HID;

    float v[8];
    float s = 0.f, s2 = 0.f;
#pragma unroll
    for (int i = 0; i < 8; i++) {
        v[i] = xr[tid + i * 256];
        s  += v[i];
        s2 += v[i] * v[i];
    }
#pragma unroll
    for (int o = 16; o; o >>= 1) {
        s  += __shfl_xor_sync(0xffffffffu, s,  o);
        s2 += __shfl_xor_sync(0xffffffffu, s2, o);
    }
    __shared__ float ss[8], ss2[8];
    if ((tid & 31) == 0) { ss[tid >> 5] = s; ss2[tid >> 5] = s2; }
    __syncthreads();
    if (tid < 32) {
        s  = (tid < 8) ? ss [tid] : 0.f;
        s2 = (tid < 8) ? ss2[tid] : 0.f;
#pragma unroll
        for (int o = 4; o; o >>= 1) {
            s  += __shfl_xor_sync(0xffffffffu, s,  o);
            s2 += __shfl_xor_sync(0xffffffffu, s2, o);
        }
        if (tid == 0) { ss[0] = s; ss2[0] = s2; }
    }
    __syncthreads();
    const float mean = ss[0] * (1.f / HID);
    const float var  = ss2[0] * (1.f / HID) - mean * mean;
    const float rstd = rsqrtf(var + LN_EPS);
    __half* orow = outh + (size_t)t * HID;
#pragma unroll
    for (int i = 0; i < 8; i++) {
        const int idx = tid + i * 256;
        const float y = (v[i] - mean) * rstd * w[idx] + b[idx];
        orow[idx] = __float2half_rn(y);
    }
}

// ---------------------------------------------------------------------------
// Partial RoPE
// ---------------------------------------------------------------------------
__global__ void __launch_bounds__(256) rope_kernel(
    float* __restrict__ q, float* __restrict__ k, const int* __restrict__ pos_ids)
{
    const int idx = blockIdx.x * blockDim.x + threadIdx.x;
    if (idx >= TT * NH * 8) return;
    const int i = idx & 7;
    const int h = (idx >> 3) & 31;
    const int t = idx >> 8;
    const int b = t / SS, s = t % SS;
    const int pos = pos_ids[b * SS + s];

    const float freq = powf(10000.0f, -(2.0f * (float)i) / (float)ROT);
    const float ang  = (float)pos * freq;
    float c, si;
    sincosf(ang, &si, &c);

    const size_t base = (size_t)t * HID + h * HD;
    float q0 = q[base + i], q1 = q[base + i + 8];
    q[base + i]     = q0 * c - q1 * si;
    q[base + i + 8] = q1 * c + q0 * si;
    float k0 = k[base + i], k1 = k[base + i + 8];
    k[base + i]     = k0 * c - k1 * si;
    k[base + i + 8] = k1 * c + k0 * si;
}

// ---------------------------------------------------------------------------
// Launch
// ---------------------------------------------------------------------------
extern "C" void kernel_launch(void* const* d_in, const int* in_sizes, int n_in,
                              void* d_out, int out_size)
{
    const float* hidden = (const float*)d_in[0];
    const float* memory = (const float*)d_in[1];
    const float* mask   = (const float*)d_in[2];
    const int*   pos    = (const int*)  d_in[3];
    const float* Wq     = (const float*)d_in[4];
    const float* Wk     = (const float*)d_in[5];
    const float* Wv     = (const float*)d_in[6];
    const float* Wo     = (const float*)d_in[7];
    const float* ln1w   = (const float*)d_in[8];
    const float* ln1b   = (const float*)d_in[9];
    const float* ln2w   = (const float*)d_in[10];
    const float* ln2b   = (const float*)d_in[11];
    const float* gw     = (const float*)d_in[12];
    const float* uw     = (const float*)d_in[13];
    const float* dw     = (const float*)d_in[14];
    float* out = (float*)d_out;

    float *q, *k, *v, *h, *up;
    __half *a2, *b2, *c2;
    cudaGetSymbolAddress((void**)&q,    g_q);
    cudaGetSymbolAddress((void**)&k,    g_k);
    cudaGetSymbolAddress((void**)&v,    g_v);
    cudaGetSymbolAddress((void**)&h,    g_h);
    cudaGetSymbolAddress((void**)&up,   g_up);
    cudaGetSymbolAddress((void**)&a2,   g_a2);
    cudaGetSymbolAddress((void**)&b2,   g_b2);
    cudaGetSymbolAddress((void**)&c2,   g_c2);

    cudaFuncSetAttribute(gemm2_kernel,
                         cudaFuncAttributeMaxDynamicSharedMemorySize, GEMM_DSMEM);
    cudaFuncSetAttribute(flash_attn_kernel,
                         cudaFuncAttributeMaxDynamicSharedMemorySize, FA_SMEM);

    auto gemm = [&](const __half* A, const __half* B,
                    const float* add, float* C, __half* O2,
                    int M, int N, int K2, int mode) {
        gemm2_kernel<<<dim3(N / 128, M / 128), 128, GEMM_DSMEM>>>(
            A, B, add, C, O2, M, N, K2, mode);
    };
    auto conv = [&](const float* X, __half* Y, size_t n) {
        conv_kernel<<<(unsigned)(n / 1024), 256>>>(X, Y);
    };

    // 1) LN1 -> plain fp16 into a2
    layernorm_h_kernel<<<TT, 256>>>(hidden, ln1w, ln1b, a2);

    // 2) Q projection (1-term fp16)
    conv(Wq, b2, (size_t)HID * HID);
    gemm(a2, b2, nullptr, q, nullptr, TT, HID, HID, 0);

    // 3) K/V projections from memory (1-term fp16)
    conv(memory, a2, (size_t)TT * HID);
    conv(Wk, b2, (size_t)HID * HID);
    gemm(a2, b2, nullptr, k, nullptr, TT, HID, HID, 0);
    conv(Wv, b2, (size_t)HID * HID);
    gemm(a2, b2, nullptr, v, nullptr, TT, HID, HID, 0);

    // 4) RoPE
    rope_kernel<<<(TT * NH * 8) / 256, 256>>>(q, k, pos);

    // 5) fused flash attention -> plain fp16 ctx into a2
    flash_attn_kernel<<<dim3(SS / 128, BB * NH), 256, FA_SMEM>>>(q, k, v, mask, a2);

    // 6) O projection + residual (1-term fp16)
    conv(Wo, b2, (size_t)HID * HID);
    gemm(a2, b2, hidden, h, nullptr, TT, HID, HID, 1);

    // 7) LN2 -> plain fp16 into a2
    layernorm_h_kernel<<<TT, 256>>>(h, ln2w, ln2b, a2);

    // 8) SwiGLU MLP + residual (1-term fp16 GEMMs)
    conv(uw, b2, (size_t)DFF * HID);
    gemm(a2, b2, nullptr, up, nullptr, TT, DFF, HID, 0);
    conv(gw, b2, (size_t)DFF * HID);
    gemm(a2, b2, up, nullptr, c2, TT, DFF, HID, 3);       // silu*up -> fp16
    conv(dw, b2, (size_t)HID * DFF);
    gemm(c2, b2, h, out, nullptr, TT, HID, DFF, 1);
}

// round 10
// speedup vs baseline: 2.4860x; 1.0186x over previous
#include <cuda_runtime.h>
#include <cuda_fp16.h>
#include <math.h>
#include <stdint.h>

// ---------------------------------------------------------------------------
// Problem constants
// ---------------------------------------------------------------------------
#define BB     2
#define SS     1024
#define TT     (BB*SS)        // 2048 tokens
#define HID    2048
#define NH     32
#define HD     64
#define ROT    16
#define DFF    8192
#define LN_EPS 1e-5f

// ---------------------------------------------------------------------------
// Static scratch (no allocations allowed)
// ---------------------------------------------------------------------------
__device__ float g_q  [(size_t)TT * HID];
__device__ float g_kv [(size_t)TT * (2 * HID)];        // K | V fused (row stride 4096)
__device__ float g_h  [(size_t)TT * HID];
__device__ float g_up [(size_t)TT * DFF];

// fp16 scratch
__device__ __half g_a2[(size_t)TT * (2 * HID)];        // activations / ctx
__device__ __half g_b2[(size_t)DFF * (2 * HID)];       // weights
__device__ __half g_c2[(size_t)TT * DFF];              // activated gate

// ---------------------------------------------------------------------------
// helpers
// ---------------------------------------------------------------------------
__device__ __forceinline__ uint32_t smem_u32(const void* p) {
    uint32_t a;
    asm("{ .reg .u64 t; cvta.to.shared.u64 t, %1; cvt.u32.u64 %0, t; }"
        : "=r"(a) : "l"(p));
    return a;
}

#define CP_ASYNC16(sa, ga) \
    asm volatile("cp.async.cg.shared.global [%0], [%1], 16;" :: "r"(sa), "l"(ga))
#define CP_COMMIT() asm volatile("cp.async.commit_group;")
#define CP_WAIT1()  asm volatile("cp.async.wait_group 1;")

#define LDSM4(r, addr) \
    asm volatile("ldmatrix.sync.aligned.m8n8.x4.shared.b16 {%0,%1,%2,%3}, [%4];" \
        : "=r"((r)[0]), "=r"((r)[1]), "=r"((r)[2]), "=r"((r)[3]) : "r"(addr))

#define MMA16816(d, a, b0, b1) \
    asm volatile("mma.sync.aligned.m16n8k16.row.col.f32.f16.f16.f32 " \
        "{%0,%1,%2,%3}, {%4,%5,%6,%7}, {%8,%9}, {%0,%1,%2,%3};" \
        : "+f"((d)[0]), "+f"((d)[1]), "+f"((d)[2]), "+f"((d)[3]) \
        : "r"((a)[0]), "r"((a)[1]), "r"((a)[2]), "r"((a)[3]), "r"(b0), "r"(b1))

__device__ __forceinline__ uint32_t pack_h2(float a, float b) {
    uint32_t h0 = (uint32_t)__half_as_ushort(__float2half_rn(a));
    uint32_t h1 = (uint32_t)__half_as_ushort(__float2half_rn(b));
    return h0 | (h1 << 16);
}

// ---------------------------------------------------------------------------
// HMMA fp16 GEMM:  C[M,N] = A[M,K2] * B[N,K2]^T
// mode 0: C fp32   mode 1: C = acc + add   mode 3: silu(acc)*add -> fp16
// 128x128 tile, BK=64, 3-stage cp.async, 128 thr = 4 warps, warp tile 64x64,
// kk-fragment double buffering to hide LDSM latency.
// ---------------------------------------------------------------------------
#define GSTAGES      3
#define GTILE_BYTES  16384
#define GSTAGE_BYTES (2 * GTILE_BYTES)
#define GEMM_DSMEM   (GSTAGES * GSTAGE_BYTES)   // 96 KB

__global__ void __launch_bounds__(128, 2) gemm2_kernel(
    const __half* __restrict__ A, const __half* __restrict__ B,
    const float* __restrict__ add, float* __restrict__ C,
    __half* __restrict__ out2,
    int M, int N, int K2, int mode)
{
    extern __shared__ __align__(128) char smem[];
    const uint32_t smem_base = smem_u32(smem);

    const int tid  = threadIdx.x;
    const int lane = tid & 31;
    const int warp = tid >> 5;       // 0..3
    const int wm = warp >> 1;        // 0..1 (64 rows)
    const int wn = warp & 1;         // 0..1 (64 cols)
    const int bx = blockIdx.x, by = blockIdx.y;
    const int nk = K2 >> 6;

    int lrow[8], lswz[8];
#pragma unroll
    for (int p = 0; p < 8; p++) {
        const int id = p * 128 + tid;
        const int row = id >> 3;
        const int c   = id & 7;
        lrow[p] = row;
        lswz[p] = row * 128 + ((c ^ (row & 7)) << 4);
    }
    const __half* Abase = A + (size_t)(by * 128) * K2;
    const __half* Bbase = B + (size_t)(bx * 128) * K2;

    float acc[4][8][4];
#pragma unroll
    for (int i = 0; i < 4; i++)
#pragma unroll
        for (int j = 0; j < 8; j++)
#pragma unroll
            for (int r = 0; r < 4; r++) acc[i][j][r] = 0.f;

    auto load_tile = [&](int ks, int buf) {
        const uint32_t sa = smem_base + buf * GSTAGE_BYTES;
        const uint32_t sb = sa + GTILE_BYTES;
        const int koff = ks * 64;
#pragma unroll
        for (int p = 0; p < 8; p++) {
            const int c = (p * 128 + tid) & 7;
            CP_ASYNC16(sa + lswz[p], Abase + (size_t)lrow[p] * K2 + koff + c * 8);
            CP_ASYNC16(sb + lswz[p], Bbase + (size_t)lrow[p] * K2 + koff + c * 8);
        }
    };

    load_tile(0, 0); CP_COMMIT();
    load_tile(1, 1); CP_COMMIT();

    for (int ks = 0; ks < nk; ks++) {
        CP_WAIT1();
        __syncthreads();
        if (ks + 2 < nk) load_tile(ks + 2, (ks + 2) % GSTAGES);
        CP_COMMIT();

        const int buf = ks % GSTAGES;
        const uint32_t sa = smem_base + buf * GSTAGE_BYTES;
        const uint32_t sb = sa + GTILE_BYTES;

        uint32_t ra[2][4][4], rb[2][4][4];

        auto ldfrag = [&](int kk, int pb) {
#pragma unroll
            for (int mt = 0; mt < 4; mt++) {
                const int row = wm * 64 + mt * 16 + (lane & 15);
                const int ch  = kk * 2 + (lane >> 4);
                LDSM4(ra[pb][mt], sa + row * 128 + ((ch ^ (row & 7)) << 4));
            }
#pragma unroll
            for (int p = 0; p < 4; p++) {
                const int n  = wn * 64 + p * 16 + (lane & 7) + ((lane >> 4) << 3);
                const int ch = kk * 2 + ((lane >> 3) & 1);
                LDSM4(rb[pb][p], sb + n * 128 + ((ch ^ (n & 7)) << 4));
            }
        };

        ldfrag(0, 0);
#pragma unroll
        for (int kk = 0; kk < 4; kk++) {
            const int cur = kk & 1;
            if (kk < 3) ldfrag(kk + 1, cur ^ 1);
#pragma unroll
            for (int mt = 0; mt < 4; mt++)
#pragma unroll
                for (int nt = 0; nt < 8; nt++)
                    MMA16816(acc[mt][nt], ra[cur][mt],
                             rb[cur][nt >> 1][(nt & 1) * 2],
                             rb[cur][nt >> 1][(nt & 1) * 2 + 1]);
        }
    }

    // epilogue
    const int r0 = lane >> 2;
    const int c0 = (lane & 3) * 2;
#pragma unroll
    for (int mt = 0; mt < 4; mt++) {
#pragma unroll
        for (int half_ = 0; half_ < 2; half_++) {
            const int row = by * 128 + wm * 64 + mt * 16 + r0 + half_ * 8;
            const int colb = bx * 128 + wn * 64;
            if (mode == 3) {
                const float* Ur = add + (size_t)row * N + colb;
                __half* Or = out2 + (size_t)row * N + colb;
#pragma unroll
                for (int nt = 0; nt < 8; nt++) {
                    const float2 uv = *(const float2*)(Ur + nt * 8 + c0);
                    float g0 = acc[mt][nt][half_ * 2];
                    float g1 = acc[mt][nt][half_ * 2 + 1];
                    g0 = g0 / (1.f + expf(-g0)) * uv.x;
                    g1 = g1 / (1.f + expf(-g1)) * uv.y;
                    const int c = nt * 8 + c0;
                    Or[c]     = __float2half_rn(g0);
                    Or[c + 1] = __float2half_rn(g1);
                }
            } else {
                float* Cr = C + (size_t)row * N + colb;
                const float* Ar = (mode == 1) ? add + (size_t)row * N + colb : nullptr;
#pragma unroll
                for (int nt = 0; nt < 8; nt++) {
                    float2 o;
                    o.x = acc[mt][nt][half_ * 2];
                    o.y = acc[mt][nt][half_ * 2 + 1];
                    if (Ar) {
                        const float2 av = *(const float2*)(Ar + nt * 8 + c0);
                        o.x += av.x; o.y += av.y;
                    }
                    *(float2*)(Cr + nt * 8 + c0) = o;
                }
            }
        }
    }
}

// ---------------------------------------------------------------------------
// Flash attention, fp16 HMMA w/ 3-split, fp32 online softmax.
// K/V read from fused kv buffer with row stride kvs (elements).
// ---------------------------------------------------------------------------
#define QS_STRIDE 200     // 192 data + 8 pad (fp16 elems)
#define VT_STRIDE 136     // 128 + 8 pad
#define FA_SMEM   (2*(128*QS_STRIDE*2) + 2*(64*VT_STRIDE*2))   // 137216 B

__global__ void __launch_bounds__(256, 1) flash_attn_kernel(
    const float* __restrict__ q, const float* __restrict__ kbase,
    const float* __restrict__ vbase, const float* __restrict__ mask,
    __half* __restrict__ ctxh, int kvs)
{
    extern __shared__ __align__(128) char smem[];
    __half* Qs  = (__half*)smem;
    __half* Ks  = Qs + 128 * QS_STRIDE;
    __half* Vth = Ks + 128 * QS_STRIDE;
    __half* Vtl = Vth + 64 * VT_STRIDE;
    const uint32_t QsB  = smem_u32(Qs);
    const uint32_t KsB  = smem_u32(Ks);
    const uint32_t VthB = smem_u32(Vth);
    const uint32_t VtlB = smem_u32(Vtl);

    const int tid  = threadIdx.x;
    const int lane = tid & 31;
    const int w    = tid >> 5;
    const int bh = blockIdx.y;
    const int b = bh >> 5, h = bh & 31;
    const int q0 = blockIdx.x * 128;

    // ---- load Q tile once, 3-split [Qh|Ql|Qh] ----
#pragma unroll
    for (int p = 0; p < 8; p++) {
        const int id = p * 256 + tid;
        const int row = id >> 4;
        const int c4  = (id & 15) * 4;
        const float4 vv = *(const float4*)(q + (size_t)(b * SS + q0 + row) * HID + h * HD + c4);
        const float xs[4] = {vv.x, vv.y, vv.z, vv.w};
#pragma unroll
        for (int j = 0; j < 4; j++) {
            __half hi = __float2half_rn(xs[j]);
            __half lo = __float2half_rn(xs[j] - __half2float(hi));
            Qs[row * QS_STRIDE + c4 + j]       = hi;
            Qs[row * QS_STRIDE + 64 + c4 + j]  = lo;
            Qs[row * QS_STRIDE + 128 + c4 + j] = hi;
        }
    }

    float sc[64];
    float o[8][4];
#pragma unroll
    for (int j = 0; j < 8; j++)
#pragma unroll
        for (int r = 0; r < 4; r++) o[j][r] = 0.f;
    float mrow[2] = {-INFINITY, -INFINITY};
    float lrow[2] = {0.f, 0.f};

    const int rA = lane >> 2;
    const int cA = (lane & 3) * 2;

    for (int kt = 0; kt < SS / 128; kt++) {
        __syncthreads();
        // ---- load K tile, split [Kh|Kh|Kl] ----
#pragma unroll
        for (int p = 0; p < 8; p++) {
            const int id = p * 256 + tid;
            const int row = id >> 4;
            const int c4  = (id & 15) * 4;
            const float4 vv = *(const float4*)(kbase + (size_t)(b * SS + kt * 128 + row) * kvs + h * HD + c4);
            const float xs[4] = {vv.x, vv.y, vv.z, vv.w};
#pragma unroll
            for (int j = 0; j < 4; j++) {
                __half hi = __float2half_rn(xs[j]);
                __half lo = __float2half_rn(xs[j] - __half2float(hi));
                Ks[row * QS_STRIDE + c4 + j]       = hi;
                Ks[row * QS_STRIDE + 64 + c4 + j]  = hi;
                Ks[row * QS_STRIDE + 128 + c4 + j] = lo;
            }
        }
        // ---- load V tile transposed, hi/lo ----
#pragma unroll
        for (int p = 0; p < 8; p++) {
            const int id = p * 256 + tid;
            const int krow = id >> 4;
            const int c4   = (id & 15) * 4;
            const float4 vv = *(const float4*)(vbase + (size_t)(b * SS + kt * 128 + krow) * kvs + h * HD + c4);
            const float xs[4] = {vv.x, vv.y, vv.z, vv.w};
#pragma unroll
            for (int j = 0; j < 4; j++) {
                __half hi = __float2half_rn(xs[j]);
                __half lo = __float2half_rn(xs[j] - __half2float(hi));
                Vth[(c4 + j) * VT_STRIDE + krow] = hi;
                Vtl[(c4 + j) * VT_STRIDE + krow] = lo;
            }
        }
        __syncthreads();

        // ---- scores: S = Q3 . K3^T  (K3=192) ----
#pragma unroll
        for (int i = 0; i < 64; i++) sc[i] = 0.f;
#pragma unroll
        for (int s = 0; s < 12; s++) {
            uint32_t ra[4];
            const int arow2 = 16 * w + (lane & 15);
            LDSM4(ra, QsB + (arow2 * QS_STRIDE + s * 16 + ((lane >> 4) << 3)) * 2);
#pragma unroll
            for (int t2 = 0; t2 < 8; t2++) {
                uint32_t rb[4];
                const int n  = t2 * 16 + (lane & 7) + ((lane >> 4) << 3);
                const int cb = s * 16 + (((lane >> 3) & 1) << 3);
                LDSM4(rb, KsB + (n * QS_STRIDE + cb) * 2);
                MMA16816((sc + (2 * t2) * 4),     ra, rb[0], rb[1]);
                MMA16816((sc + (2 * t2 + 1) * 4), ra, rb[2], rb[3]);
            }
        }

        // ---- scale + mask, online softmax ----
        const int qrA = q0 + 16 * w + rA;
        const int qrB = qrA + 8;
        float tm[2] = {-INFINITY, -INFINITY};
#pragma unroll
        for (int t = 0; t < 16; t++) {
            const int kc = kt * 128 + t * 8 + cA;
            const float2 mA = *(const float2*)(mask + ((size_t)b * SS + qrA) * SS + kc);
            const float2 mB = *(const float2*)(mask + ((size_t)b * SS + qrB) * SS + kc);
            sc[t * 4 + 0] = sc[t * 4 + 0] * 0.125f + mA.x;
            sc[t * 4 + 1] = sc[t * 4 + 1] * 0.125f + mA.y;
            sc[t * 4 + 2] = sc[t * 4 + 2] * 0.125f + mB.x;
            sc[t * 4 + 3] = sc[t * 4 + 3] * 0.125f + mB.y;
            tm[0] = fmaxf(tm[0], fmaxf(sc[t * 4 + 0], sc[t * 4 + 1]));
            tm[1] = fmaxf(tm[1], fmaxf(sc[t * 4 + 2], sc[t * 4 + 3]));
        }
#pragma unroll
        for (int off = 1; off <= 2; off <<= 1) {
            tm[0] = fmaxf(tm[0], __shfl_xor_sync(0xffffffffu, tm[0], off));
            tm[1] = fmaxf(tm[1], __shfl_xor_sync(0xffffffffu, tm[1], off));
        }
        const float mn0 = fmaxf(mrow[0], tm[0]);
        const float mn1 = fmaxf(mrow[1], tm[1]);
        const float sc0 = __expf(mrow[0] - mn0);
        const float sc1 = __expf(mrow[1] - mn1);
        float ts[2] = {0.f, 0.f};
#pragma unroll
        for (int t = 0; t < 16; t++) {
            sc[t * 4 + 0] = __expf(sc[t * 4 + 0] - mn0);
            sc[t * 4 + 1] = __expf(sc[t * 4 + 1] - mn0);
            sc[t * 4 + 2] = __expf(sc[t * 4 + 2] - mn1);
            sc[t * 4 + 3] = __expf(sc[t * 4 + 3] - mn1);
            ts[0] += sc[t * 4 + 0] + sc[t * 4 + 1];
            ts[1] += sc[t * 4 + 2] + sc[t * 4 + 3];
        }
#pragma unroll
        for (int off = 1; off <= 2; off <<= 1) {
            ts[0] += __shfl_xor_sync(0xffffffffu, ts[0], off);
            ts[1] += __shfl_xor_sync(0xffffffffu, ts[1], off);
        }
        lrow[0] = lrow[0] * sc0 + ts[0];
        lrow[1] = lrow[1] * sc1 + ts[1];
        mrow[0] = mn0; mrow[1] = mn1;
#pragma unroll
        for (int j = 0; j < 8; j++) {
            o[j][0] *= sc0; o[j][1] *= sc0;
            o[j][2] *= sc1; o[j][3] *= sc1;
        }

        // ---- O += P3 . V3 (3-term split) ----
#pragma unroll
        for (int s2 = 0; s2 < 8; s2++) {
            const float p00 = sc[(2 * s2) * 4 + 0], p01 = sc[(2 * s2) * 4 + 1];
            const float p10 = sc[(2 * s2) * 4 + 2], p11 = sc[(2 * s2) * 4 + 3];
            const float r00 = sc[(2 * s2 + 1) * 4 + 0], r01 = sc[(2 * s2 + 1) * 4 + 1];
            const float r10 = sc[(2 * s2 + 1) * 4 + 2], r11 = sc[(2 * s2 + 1) * 4 + 3];
            uint32_t ph[4], pl[4];
            ph[0] = pack_h2(p00, p01); ph[1] = pack_h2(p10, p11);
            ph[2] = pack_h2(r00, r01); ph[3] = pack_h2(r10, r11);
            pl[0] = pack_h2(p00 - __half2float(__float2half_rn(p00)),
                            p01 - __half2float(__float2half_rn(p01)));
            pl[1] = pack_h2(p10 - __half2float(__float2half_rn(p10)),
                            p11 - __half2float(__float2half_rn(p11)));
            pl[2] = pack_h2(r00 - __half2float(__float2half_rn(r00)),
                            r01 - __half2float(__float2half_rn(r01)));
            pl[3] = pack_h2(r10 - __half2float(__float2half_rn(r10)),
                            r11 - __half2float(__float2half_rn(r11)));
#pragma unroll
            for (int dt = 0; dt < 4; dt++) {
                uint32_t bh_[4], bl_[4];
                const int n  = dt * 16 + (lane & 7) + ((lane >> 4) << 3);
                const int cb = s2 * 16 + (((lane >> 3) & 1) << 3);
                LDSM4(bh_, VthB + (n * VT_STRIDE + cb) * 2);
                LDSM4(bl_, VtlB + (n * VT_STRIDE + cb) * 2);
                MMA16816(o[2 * dt],     ph, bh_[0], bh_[1]);
                MMA16816(o[2 * dt + 1], ph, bh_[2], bh_[3]);
                MMA16816(o[2 * dt],     pl, bh_[0], bh_[1]);
                MMA16816(o[2 * dt + 1], pl, bh_[2], bh_[3]);
                MMA16816(o[2 * dt],     ph, bl_[0], bl_[1]);
                MMA16816(o[2 * dt + 1], ph, bl_[2], bl_[3]);
            }
        }
    }

    // ---- epilogue: normalize, write plain fp16 ctx ----
    const float inv0 = 1.f / lrow[0];
    const float inv1 = 1.f / lrow[1];
    const size_t tokA = (size_t)(b * SS + q0 + 16 * w + rA);
    const size_t tokB = tokA + 8;
#pragma unroll
    for (int j = 0; j < 8; j++) {
        const int cg = h * HD + j * 8 + cA;
        ctxh[tokA * HID + cg]     = __float2half_rn(o[j][0] * inv0);
        ctxh[tokA * HID + cg + 1] = __float2half_rn(o[j][1] * inv0);
        ctxh[tokB * HID + cg]     = __float2half_rn(o[j][2] * inv1);
        ctxh[tokB * HID + cg + 1] = __float2half_rn(o[j][3] * inv1);
    }
}

// ---------------------------------------------------------------------------
// fp32 -> fp16 plain convert, MLP=4 (4 independent float4 per thread)
// n must be divisible by 16384
// ---------------------------------------------------------------------------
__global__ void __launch_bounds__(256) conv_kernel(
    const float* __restrict__ X, __half* __restrict__ Y)
{
    const size_t i0 = ((size_t)blockIdx.x * 256 + threadIdx.x) * 4;
    const size_t st = (size_t)gridDim.x * 1024;
    const float4 a = *(const float4*)(X + i0);
    const float4 b = *(const float4*)(X + i0 + st);
    const float4 c = *(const float4*)(X + i0 + 2 * st);
    const float4 d = *(const float4*)(X + i0 + 3 * st);
    uint2 ha, hb, hc, hd;
    ha.x = pack_h2(a.x, a.y); ha.y = pack_h2(a.z, a.w);
    hb.x = pack_h2(b.x, b.y); hb.y = pack_h2(b.z, b.w);
    hc.x = pack_h2(c.x, c.y); hc.y = pack_h2(c.z, c.w);
    hd.x = pack_h2(d.x, d.y); hd.y = pack_h2(d.z, d.w);
    *(uint2*)(Y + i0)          = ha;
    *(uint2*)(Y + i0 + st)     = hb;
    *(uint2*)(Y + i0 + 2 * st) = hc;
    *(uint2*)(Y + i0 + 3 * st) = hd;
}

// ---------------------------------------------------------------------------
// Fused LayerNorm -> plain fp16 (row stride HID)
// ---------------------------------------------------------------------------
__global__ void __launch_bounds__(256) layernorm_h_kernel(
    const float* __restrict__ x, const float* __restrict__ w,
    const float* __restrict__ b, __half* __restrict__ outh)
{
    const int t   = blockIdx.x;
    const int tid = threadIdx.x;
    const float* xr = x + (size_t)t * HID;

    float v[8];
    float s = 0.f, s2 = 0.f;
#pragma unroll
    for (int i = 0; i < 8; i++) {
        v[i] = xr[tid + i * 256];
        s  += v[i];
        s2 += v[i] * v[i];
    }
#pragma unroll
    for (int o = 16; o; o >>= 1) {
        s  += __shfl_xor_sync(0xffffffffu, s,  o);
        s2 += __shfl_xor_sync(0xffffffffu, s2, o);
    }
    __shared__ float ss[8], ss2[8];
    if ((tid & 31) == 0) { ss[tid >> 5] = s; ss2[tid >> 5] = s2; }
    __syncthreads();
    if (tid < 32) {
        s  = (tid < 8) ? ss [tid] : 0.f;
        s2 = (tid < 8) ? ss2[tid] : 0.f;
#pragma unroll
        for (int o = 4; o; o >>= 1) {
            s  += __shfl_xor_sync(0xffffffffu, s,  o);
            s2 += __shfl_xor_sync(0xffffffffu, s2, o);
        }
        if (tid == 0) { ss[0] = s; ss2[0] = s2; }
    }
    __syncthreads();
    const float mean = ss[0] * (1.f / HID);
    const float var  = ss2[0] * (1.f / HID) - mean * mean;
    const float rstd = rsqrtf(var + LN_EPS);
    __half* orow = outh + (size_t)t * HID;
#pragma unroll
    for (int i = 0; i < 8; i++) {
        const int idx = tid + i * 256;
        const float y = (v[i] - mean) * rstd * w[idx] + b[idx];
        orow[idx] = __float2half_rn(y);
    }
}

// ---------------------------------------------------------------------------
// Partial RoPE: q row stride HID, k row stride kvs
// ---------------------------------------------------------------------------
__global__ void __launch_bounds__(256) rope_kernel(
    float* __restrict__ q, float* __restrict__ k,
    const int* __restrict__ pos_ids, int kvs)
{
    const int idx = blockIdx.x * blockDim.x + threadIdx.x;
    if (idx >= TT * NH * 8) return;
    const int i = idx & 7;
    const int h = (idx >> 3) & 31;
    const int t = idx >> 8;
    const int b = t / SS, s = t % SS;
    const int pos = pos_ids[b * SS + s];

    const float freq = powf(10000.0f, -(2.0f * (float)i) / (float)ROT);
    const float ang  = (float)pos * freq;
    float c, si;
    sincosf(ang, &si, &c);

    {
        const size_t base = (size_t)t * HID + h * HD;
        float q0 = q[base + i], q1 = q[base + i + 8];
        q[base + i]     = q0 * c - q1 * si;
        q[base + i + 8] = q1 * c + q0 * si;
    }
    {
        const size_t base = (size_t)t * kvs + h * HD;
        float k0 = k[base + i], k1 = k[base + i + 8];
        k[base + i]     = k0 * c - k1 * si;
        k[base + i + 8] = k1 * c + k0 * si;
    }
}

// ---------------------------------------------------------------------------
// Launch
// ---------------------------------------------------------------------------
extern "C" void kernel_launch(void* const* d_in, const int* in_sizes, int n_in,
                              void* d_out, int out_size)
{
    const float* hidden = (const float*)d_in[0];
    const float* memory = (const float*)d_in[1];
    const float* mask   = (const float*)d_in[2];
    const int*   pos    = (const int*)  d_in[3];
    const float* Wq     = (const float*)d_in[4];
    const float* Wk     = (const float*)d_in[5];
    const float* Wv     = (const float*)d_in[6];
    const float* Wo     = (const float*)d_in[7];
    const float* ln1w   = (const float*)d_in[8];
    const float* ln1b   = (const float*)d_in[9];
    const float* ln2w   = (const float*)d_in[10];
    const float* ln2b   = (const float*)d_in[11];
    const float* gw     = (const float*)d_in[12];
    const float* uw     = (const float*)d_in[13];
    const float* dw     = (const float*)d_in[14];
    float* out = (float*)d_out;

    float *q, *kv, *h, *up;
    __half *a2, *b2, *c2;
    cudaGetSymbolAddress((void**)&q,    g_q);
    cudaGetSymbolAddress((void**)&kv,   g_kv);
    cudaGetSymbolAddress((void**)&h,    g_h);
    cudaGetSymbolAddress((void**)&up,   g_up);
    cudaGetSymbolAddress((void**)&a2,   g_a2);
    cudaGetSymbolAddress((void**)&b2,   g_b2);
    cudaGetSymbolAddress((void**)&c2,   g_c2);

    cudaFuncSetAttribute(gemm2_kernel,
                         cudaFuncAttributeMaxDynamicSharedMemorySize, GEMM_DSMEM);
    cudaFuncSetAttribute(flash_attn_kernel,
                         cudaFuncAttributeMaxDynamicSharedMemorySize, FA_SMEM);

    auto gemm = [&](const __half* A, const __half* B,
                    const float* add, float* C, __half* O2,
                    int M, int N, int K2, int mode) {
        gemm2_kernel<<<dim3(N / 128, M / 128), 128, GEMM_DSMEM>>>(
            A, B, add, C, O2, M, N, K2, mode);
    };
    auto conv = [&](const float* X, __half* Y, size_t n) {
        conv_kernel<<<(unsigned)(n / 4096), 256>>>(X, Y);
    };

    // 1) LN1 -> plain fp16 into a2
    layernorm_h_kernel<<<TT, 256>>>(hidden, ln1w, ln1b, a2);

    // 2) Q projection (1-term fp16)
    conv(Wq, b2, (size_t)HID * HID);
    gemm(a2, b2, nullptr, q, nullptr, TT, HID, HID, 0);

    // 3) K+V fused projection from memory (1-term fp16, N=4096)
    conv(memory, a2, (size_t)TT * HID);
    conv(Wk, b2, (size_t)HID * HID);
    conv(Wv, b2 + (size_t)HID * HID, (size_t)HID * HID);
    gemm(a2, b2, nullptr, kv, nullptr, TT, 2 * HID, HID, 0);

    // 4) RoPE (k inside fused kv, stride 2*HID)
    rope_kernel<<<(TT * NH * 8) / 256, 256>>>(q, kv, pos, 2 * HID);

    // 5) fused flash attention -> plain fp16 ctx into a2
    flash_attn_kernel<<<dim3(SS / 128, BB * NH), 256, FA_SMEM>>>(
        q, kv, kv + HID, mask, a2, 2 * HID);

    // 6) O projection + residual (1-term fp16)
    conv(Wo, b2, (size_t)HID * HID);
    gemm(a2, b2, hidden, h, nullptr, TT, HID, HID, 1);

    // 7) LN2 -> plain fp16 into a2
    layernorm_h_kernel<<<TT, 256>>>(h, ln2w, ln2b, a2);

    // 8) SwiGLU MLP + residual (1-term fp16 GEMMs)
    conv(uw, b2, (size_t)DFF * HID);
    gemm(a2, b2, nullptr, up, nullptr, TT, DFF, HID, 0);
    conv(gw, b2, (size_t)DFF * HID);
    gemm(a2, b2, up, nullptr, c2, TT, DFF, HID, 3);       // silu*up -> fp16
    conv(dw, b2, (size_t)HID * DFF);
    gemm(c2, b2, h, out, nullptr, TT, HID, DFF, 1);
}

// round 11
// speedup vs baseline: 2.8381x; 1.1417x over previous
#include <cuda_runtime.h>
#include <cuda_fp16.h>
#include <math.h>
#include <stdint.h>

// ---------------------------------------------------------------------------
// Problem constants
// ---------------------------------------------------------------------------
#define BB     2
#define SS     1024
#define TT     (BB*SS)        // 2048 tokens
#define HID    2048
#define NH     32
#define HD     64
#define ROT    16
#define DFF    8192
#define LN_EPS 1e-5f

// ---------------------------------------------------------------------------
// Static scratch (no allocations allowed)
// ---------------------------------------------------------------------------
__device__ float g_q  [(size_t)TT * HID];
__device__ float g_kv [(size_t)TT * (2 * HID)];        // K | V fused (row stride 4096)
__device__ float g_h  [(size_t)TT * HID];

// fp16 scratch
__device__ __half g_a2[(size_t)TT * HID];              // LN outputs / ctx
__device__ __half g_b2[(size_t)DFF * (2 * HID)];       // weights (interleaved gw/uw fit)
__device__ __half g_c2[(size_t)TT * DFF];              // memory-fp16, later activated gate

// ---------------------------------------------------------------------------
// helpers
// ---------------------------------------------------------------------------
__device__ __forceinline__ uint32_t smem_u32(const void* p) {
    uint32_t a;
    asm("{ .reg .u64 t; cvta.to.shared.u64 t, %1; cvt.u32.u64 %0, t; }"
        : "=r"(a) : "l"(p));
    return a;
}

#define CP_ASYNC16(sa, ga) \
    asm volatile("cp.async.cg.shared.global [%0], [%1], 16;" :: "r"(sa), "l"(ga))
#define CP_COMMIT() asm volatile("cp.async.commit_group;")
#define CP_WAIT1()  asm volatile("cp.async.wait_group 1;")

#define LDSM4(r, addr) \
    asm volatile("ldmatrix.sync.aligned.m8n8.x4.shared.b16 {%0,%1,%2,%3}, [%4];" \
        : "=r"((r)[0]), "=r"((r)[1]), "=r"((r)[2]), "=r"((r)[3]) : "r"(addr))

#define MMA16816(d, a, b0, b1) \
    asm volatile("mma.sync.aligned.m16n8k16.row.col.f32.f16.f16.f32 " \
        "{%0,%1,%2,%3}, {%4,%5,%6,%7}, {%8,%9}, {%0,%1,%2,%3};" \
        : "+f"((d)[0]), "+f"((d)[1]), "+f"((d)[2]), "+f"((d)[3]) \
        : "r"((a)[0]), "r"((a)[1]), "r"((a)[2]), "r"((a)[3]), "r"(b0), "r"(b1))

__device__ __forceinline__ uint32_t pack_h2(float a, float b) {
    uint32_t h0 = (uint32_t)__half_as_ushort(__float2half_rn(a));
    uint32_t h1 = (uint32_t)__half_as_ushort(__float2half_rn(b));
    return h0 | (h1 << 16);
}

// ---------------------------------------------------------------------------
// HMMA fp16 GEMM:  C[M,N] = A[M,K2] * B[N,K2]^T
// mode 0: C fp32   mode 1: C = acc + add
// mode 4: interleaved gate/up -> silu(even)*odd -> fp16 out2 (width N/2)
// 128x128 tile, BK=64, 3-stage cp.async, 128 thr = 4 warps, warp tile 64x64
// ---------------------------------------------------------------------------
#define GSTAGES      3
#define GTILE_BYTES  16384
#define GSTAGE_BYTES (2 * GTILE_BYTES)
#define GEMM_DSMEM   (GSTAGES * GSTAGE_BYTES)   // 96 KB

__global__ void __launch_bounds__(128, 2) gemm2_kernel(
    const __half* __restrict__ A, const __half* __restrict__ B,
    const float* __restrict__ add, float* __restrict__ C,
    __half* __restrict__ out2,
    int M, int N, int K2, int mode)
{
    extern __shared__ __align__(128) char smem[];
    const uint32_t smem_base = smem_u32(smem);

    const int tid  = threadIdx.x;
    const int lane = tid & 31;
    const int warp = tid >> 5;
    const int wm = warp >> 1;
    const int wn = warp & 1;
    const int bx = blockIdx.x, by = blockIdx.y;
    const int nk = K2 >> 6;

    int lrow[8], lswz[8];
#pragma unroll
    for (int p = 0; p < 8; p++) {
        const int id = p * 128 + tid;
        const int row = id >> 3;
        const int c   = id & 7;
        lrow[p] = row;
        lswz[p] = row * 128 + ((c ^ (row & 7)) << 4);
    }
    const __half* Abase = A + (size_t)(by * 128) * K2;
    const __half* Bbase = B + (size_t)(bx * 128) * K2;

    float acc[4][8][4];
#pragma unroll
    for (int i = 0; i < 4; i++)
#pragma unroll
        for (int j = 0; j < 8; j++)
#pragma unroll
            for (int r = 0; r < 4; r++) acc[i][j][r] = 0.f;

    auto load_tile = [&](int ks, int buf) {
        const uint32_t sa = smem_base + buf * GSTAGE_BYTES;
        const uint32_t sb = sa + GTILE_BYTES;
        const int koff = ks * 64;
#pragma unroll
        for (int p = 0; p < 8; p++) {
            const int c = (p * 128 + tid) & 7;
            CP_ASYNC16(sa + lswz[p], Abase + (size_t)lrow[p] * K2 + koff + c * 8);
            CP_ASYNC16(sb + lswz[p], Bbase + (size_t)lrow[p] * K2 + koff + c * 8);
        }
    };

    load_tile(0, 0); CP_COMMIT();
    load_tile(1, 1); CP_COMMIT();

    for (int ks = 0; ks < nk; ks++) {
        CP_WAIT1();
        __syncthreads();
        if (ks + 2 < nk) load_tile(ks + 2, (ks + 2) % GSTAGES);
        CP_COMMIT();

        const int buf = ks % GSTAGES;
        const uint32_t sa = smem_base + buf * GSTAGE_BYTES;
        const uint32_t sb = sa + GTILE_BYTES;

        uint32_t ra[2][4][4], rb[2][4][4];

        auto ldfrag = [&](int kk, int pb) {
#pragma unroll
            for (int mt = 0; mt < 4; mt++) {
                const int row = wm * 64 + mt * 16 + (lane & 15);
                const int ch  = kk * 2 + (lane >> 4);
                LDSM4(ra[pb][mt], sa + row * 128 + ((ch ^ (row & 7)) << 4));
            }
#pragma unroll
            for (int p = 0; p < 4; p++) {
                const int n  = wn * 64 + p * 16 + (lane & 7) + ((lane >> 4) << 3);
                const int ch = kk * 2 + ((lane >> 3) & 1);
                LDSM4(rb[pb][p], sb + n * 128 + ((ch ^ (n & 7)) << 4));
            }
        };

        ldfrag(0, 0);
#pragma unroll
        for (int kk = 0; kk < 4; kk++) {
            const int cur = kk & 1;
            if (kk < 3) ldfrag(kk + 1, cur ^ 1);
#pragma unroll
            for (int mt = 0; mt < 4; mt++)
#pragma unroll
                for (int nt = 0; nt < 8; nt++)
                    MMA16816(acc[mt][nt], ra[cur][mt],
                             rb[cur][nt >> 1][(nt & 1) * 2],
                             rb[cur][nt >> 1][(nt & 1) * 2 + 1]);
        }
    }

    // epilogue
    const int r0 = lane >> 2;
    const int c0 = (lane & 3) * 2;
#pragma unroll
    for (int mt = 0; mt < 4; mt++) {
#pragma unroll
        for (int half_ = 0; half_ < 2; half_++) {
            const int row = by * 128 + wm * 64 + mt * 16 + r0 + half_ * 8;
            const int colb = bx * 128 + wn * 64;
            if (mode == 4) {
                // interleaved gate/up: even col = gate, odd = up
                __half* Or = out2 + (size_t)row * (N >> 1);
#pragma unroll
                for (int nt = 0; nt < 8; nt++) {
                    float g = acc[mt][nt][half_ * 2];
                    const float u = acc[mt][nt][half_ * 2 + 1];
                    g = g / (1.f + expf(-g)) * u;
                    Or[(colb + nt * 8 + c0) >> 1] = __float2half_rn(g);
                }
            } else {
                float* Cr = C + (size_t)row * N + colb;
                const float* Ar = (mode == 1) ? add + (size_t)row * N + colb : nullptr;
#pragma unroll
                for (int nt = 0; nt < 8; nt++) {
                    float2 o;
                    o.x = acc[mt][nt][half_ * 2];
                    o.y = acc[mt][nt][half_ * 2 + 1];
                    if (Ar) {
                        const float2 av = *(const float2*)(Ar + nt * 8 + c0);
                        o.x += av.x; o.y += av.y;
                    }
                    *(float2*)(Cr + nt * 8 + c0) = o;
                }
            }
        }
    }
}

// ---------------------------------------------------------------------------
// Flash attention, fp16 HMMA, 2-term QK ([Qh|Ql]x[Kh|Kh]) and PV ((Ph+Pl)xVh),
// fp32 online softmax. 128 q-rows x one head per CTA, 256 thr, 2 CTAs/SM.
// ---------------------------------------------------------------------------
#define QS_STRIDE 136     // 128 data + 8 pad (fp16 elems)
#define VT_STRIDE 136
#define FA_SMEM   (2*(128*QS_STRIDE*2) + 64*VT_STRIDE*2)   // 87040 B

__global__ void __launch_bounds__(256, 2) flash_attn_kernel(
    const float* __restrict__ q, const float* __restrict__ kbase,
    const float* __restrict__ vbase, const float* __restrict__ mask,
    __half* __restrict__ ctxh, int kvs)
{
    extern __shared__ __align__(128) char smem[];
    __half* Qs  = (__half*)smem;
    __half* Ks  = Qs + 128 * QS_STRIDE;
    __half* Vth = Ks + 128 * QS_STRIDE;
    const uint32_t QsB  = smem_u32(Qs);
    const uint32_t KsB  = smem_u32(Ks);
    const uint32_t VthB = smem_u32(Vth);

    const int tid  = threadIdx.x;
    const int lane = tid & 31;
    const int w    = tid >> 5;
    const int bh = blockIdx.y;
    const int b = bh >> 5, h = bh & 31;
    const int q0 = blockIdx.x * 128;

    // ---- load Q tile once, 2-split [Qh|Ql] ----
#pragma unroll
    for (int p = 0; p < 8; p++) {
        const int id = p * 256 + tid;
        const int row = id >> 4;
        const int c4  = (id & 15) * 4;
        const float4 vv = *(const float4*)(q + (size_t)(b * SS + q0 + row) * HID + h * HD + c4);
        const float xs[4] = {vv.x, vv.y, vv.z, vv.w};
#pragma unroll
        for (int j = 0; j < 4; j++) {
            __half hi = __float2half_rn(xs[j]);
            __half lo = __float2half_rn(xs[j] - __half2float(hi));
            Qs[row * QS_STRIDE + c4 + j]      = hi;
            Qs[row * QS_STRIDE + 64 + c4 + j] = lo;
        }
    }

    float sc[64];
    float o[8][4];
#pragma unroll
    for (int j = 0; j < 8; j++)
#pragma unroll
        for (int r = 0; r < 4; r++) o[j][r] = 0.f;
    float mrow[2] = {-INFINITY, -INFINITY};
    float lrow[2] = {0.f, 0.f};

    const int rA = lane >> 2;
    const int cA = (lane & 3) * 2;

    for (int kt = 0; kt < SS / 128; kt++) {
        __syncthreads();
        // ---- load K tile, [Kh|Kh] ----
#pragma unroll
        for (int p = 0; p < 8; p++) {
            const int id = p * 256 + tid;
            const int row = id >> 4;
            const int c4  = (id & 15) * 4;
            const float4 vv = *(const float4*)(kbase + (size_t)(b * SS + kt * 128 + row) * kvs + h * HD + c4);
            const float xs[4] = {vv.x, vv.y, vv.z, vv.w};
#pragma unroll
            for (int j = 0; j < 4; j++) {
                __half hi = __float2half_rn(xs[j]);
                Ks[row * QS_STRIDE + c4 + j]      = hi;
                Ks[row * QS_STRIDE + 64 + c4 + j] = hi;
            }
        }
        // ---- load V tile transposed (hi only) ----
#pragma unroll
        for (int p = 0; p < 8; p++) {
            const int id = p * 256 + tid;
            const int krow = id >> 4;
            const int c4   = (id & 15) * 4;
            const float4 vv = *(const float4*)(vbase + (size_t)(b * SS + kt * 128 + krow) * kvs + h * HD + c4);
            const float xs[4] = {vv.x, vv.y, vv.z, vv.w};
#pragma unroll
            for (int j = 0; j < 4; j++)
                Vth[(c4 + j) * VT_STRIDE + krow] = __float2half_rn(xs[j]);
        }
        __syncthreads();

        // ---- scores: S = [Qh|Ql] . [Kh|Kh]^T  (K=128) ----
#pragma unroll
        for (int i = 0; i < 64; i++) sc[i] = 0.f;
#pragma unroll
        for (int s = 0; s < 8; s++) {
            uint32_t ra[4];
            const int arow2 = 16 * w + (lane & 15);
            LDSM4(ra, QsB + (arow2 * QS_STRIDE + s * 16 + ((lane >> 4) << 3)) * 2);
#pragma unroll
            for (int t2 = 0; t2 < 8; t2++) {
                uint32_t rb[4];
                const int n  = t2 * 16 + (lane & 7) + ((lane >> 4) << 3);
                const int cb = s * 16 + (((lane >> 3) & 1) << 3);
                LDSM4(rb, KsB + (n * QS_STRIDE + cb) * 2);
                MMA16816((sc + (2 * t2) * 4),     ra, rb[0], rb[1]);
                MMA16816((sc + (2 * t2 + 1) * 4), ra, rb[2], rb[3]);
            }
        }

        // ---- scale + mask, online softmax ----
        const int qrA = q0 + 16 * w + rA;
        const int qrB = qrA + 8;
        float tm[2] = {-INFINITY, -INFINITY};
#pragma unroll
        for (int t = 0; t < 16; t++) {
            const int kc = kt * 128 + t * 8 + cA;
            const float2 mA = *(const float2*)(mask + ((size_t)b * SS + qrA) * SS + kc);
            const float2 mB = *(const float2*)(mask + ((size_t)b * SS + qrB) * SS + kc);
            sc[t * 4 + 0] = sc[t * 4 + 0] * 0.125f + mA.x;
            sc[t * 4 + 1] = sc[t * 4 + 1] * 0.125f + mA.y;
            sc[t * 4 + 2] = sc[t * 4 + 2] * 0.125f + mB.x;
            sc[t * 4 + 3] = sc[t * 4 + 3] * 0.125f + mB.y;
            tm[0] = fmaxf(tm[0], fmaxf(sc[t * 4 + 0], sc[t * 4 + 1]));
            tm[1] = fmaxf(tm[1], fmaxf(sc[t * 4 + 2], sc[t * 4 + 3]));
        }
#pragma unroll
        for (int off = 1; off <= 2; off <<= 1) {
            tm[0] = fmaxf(tm[0], __shfl_xor_sync(0xffffffffu, tm[0], off));
            tm[1] = fmaxf(tm[1], __shfl_xor_sync(0xffffffffu, tm[1], off));
        }
        const float mn0 = fmaxf(mrow[0], tm[0]);
        const float mn1 = fmaxf(mrow[1], tm[1]);
        const float sc0 = __expf(mrow[0] - mn0);
        const float sc1 = __expf(mrow[1] - mn1);
        float ts[2] = {0.f, 0.f};
#pragma unroll
        for (int t = 0; t < 16; t++) {
            sc[t * 4 + 0] = __expf(sc[t * 4 + 0] - mn0);
            sc[t * 4 + 1] = __expf(sc[t * 4 + 1] - mn0);
            sc[t * 4 + 2] = __expf(sc[t * 4 + 2] - mn1);
            sc[t * 4 + 3] = __expf(sc[t * 4 + 3] - mn1);
            ts[0] += sc[t * 4 + 0] + sc[t * 4 + 1];
            ts[1] += sc[t * 4 + 2] + sc[t * 4 + 3];
        }
#pragma unroll
        for (int off = 1; off <= 2; off <<= 1) {
            ts[0] += __shfl_xor_sync(0xffffffffu, ts[0], off);
            ts[1] += __shfl_xor_sync(0xffffffffu, ts[1], off);
        }
        lrow[0] = lrow[0] * sc0 + ts[0];
        lrow[1] = lrow[1] * sc1 + ts[1];
        mrow[0] = mn0; mrow[1] = mn1;
#pragma unroll
        for (int j = 0; j < 8; j++) {
            o[j][0] *= sc0; o[j][1] *= sc0;
            o[j][2] *= sc1; o[j][3] *= sc1;
        }

        // ---- O += (Ph + Pl) . Vh (2-term) ----
#pragma unroll
        for (int s2 = 0; s2 < 8; s2++) {
            const float p00 = sc[(2 * s2) * 4 + 0], p01 = sc[(2 * s2) * 4 + 1];
            const float p10 = sc[(2 * s2) * 4 + 2], p11 = sc[(2 * s2) * 4 + 3];
            const float r00 = sc[(2 * s2 + 1) * 4 + 0], r01 = sc[(2 * s2 + 1) * 4 + 1];
            const float r10 = sc[(2 * s2 + 1) * 4 + 2], r11 = sc[(2 * s2 + 1) * 4 + 3];
            uint32_t ph[4], pl[4];
            ph[0] = pack_h2(p00, p01); ph[1] = pack_h2(p10, p11);
            ph[2] = pack_h2(r00, r01); ph[3] = pack_h2(r10, r11);
            pl[0] = pack_h2(p00 - __half2float(__float2half_rn(p00)),
                            p01 - __half2float(__float2half_rn(p01)));
            pl[1] = pack_h2(p10 - __half2float(__float2half_rn(p10)),
                            p11 - __half2float(__float2half_rn(p11)));
            pl[2] = pack_h2(r00 - __half2float(__float2half_rn(r00)),
                            r01 - __half2float(__float2half_rn(r01)));
            pl[3] = pack_h2(r10 - __half2float(__float2half_rn(r10)),
                            r11 - __half2float(__float2half_rn(r11)));
#pragma unroll
            for (int dt = 0; dt < 4; dt++) {
                uint32_t bh_[4];
                const int n  = dt * 16 + (lane & 7) + ((lane >> 4) << 3);
                const int cb = s2 * 16 + (((lane >> 3) & 1) << 3);
                LDSM4(bh_, VthB + (n * VT_STRIDE + cb) * 2);
                MMA16816(o[2 * dt],     ph, bh_[0], bh_[1]);
                MMA16816(o[2 * dt + 1], ph, bh_[2], bh_[3]);
                MMA16816(o[2 * dt],     pl, bh_[0], bh_[1]);
                MMA16816(o[2 * dt + 1], pl, bh_[2], bh_[3]);
            }
        }
    }

    // ---- epilogue: normalize, write plain fp16 ctx ----
    const float inv0 = 1.f / lrow[0];
    const float inv1 = 1.f / lrow[1];
    const size_t tokA = (size_t)(b * SS + q0 + 16 * w + rA);
    const size_t tokB = tokA + 8;
#pragma unroll
    for (int j = 0; j < 8; j++) {
        const int cg = h * HD + j * 8 + cA;
        ctxh[tokA * HID + cg]     = __float2half_rn(o[j][0] * inv0);
        ctxh[tokA * HID + cg + 1] = __float2half_rn(o[j][1] * inv0);
        ctxh[tokB * HID + cg]     = __float2half_rn(o[j][2] * inv1);
        ctxh[tokB * HID + cg + 1] = __float2half_rn(o[j][3] * inv1);
    }
}

// ---------------------------------------------------------------------------
// fp32 -> fp16 plain convert, MLP=4
// ---------------------------------------------------------------------------
__global__ void __launch_bounds__(256) conv_kernel(
    const float* __restrict__ X, __half* __restrict__ Y)
{
    const size_t i0 = ((size_t)blockIdx.x * 256 + threadIdx.x) * 4;
    const size_t st = (size_t)gridDim.x * 1024;
    const float4 a = *(const float4*)(X + i0);
    const float4 b = *(const float4*)(X + i0 + st);
    const float4 c = *(const float4*)(X + i0 + 2 * st);
    const float4 d = *(const float4*)(X + i0 + 3 * st);
    uint2 ha, hb, hc, hd;
    ha.x = pack_h2(a.x, a.y); ha.y = pack_h2(a.z, a.w);
    hb.x = pack_h2(b.x, b.y); hb.y = pack_h2(b.z, b.w);
    hc.x = pack_h2(c.x, c.y); hc.y = pack_h2(c.z, c.w);
    hd.x = pack_h2(d.x, d.y); hd.y = pack_h2(d.z, d.w);
    *(uint2*)(Y + i0)          = ha;
    *(uint2*)(Y + i0 + st)     = hb;
    *(uint2*)(Y + i0 + 2 * st) = hc;
    *(uint2*)(Y + i0 + 3 * st) = hd;
}

// ---------------------------------------------------------------------------
// fp32 -> fp16 convert with row interleave: X row j -> Y row 2j+parity
// X is [DFF x HID]; Y row stride HID. (HID = 2048 = 1<<11)
// ---------------------------------------------------------------------------
__global__ void __launch_bounds__(256) conv_il_kernel(
    const float* __restrict__ X, __half* __restrict__ Y, int parity)
{
    const size_t i0 = ((size_t)blockIdx.x * 256 + threadIdx.x) * 4;
    const size_t st = (size_t)gridDim.x * 1024;
#pragma unroll
    for (int qq = 0; qq < 4; qq++) {
        const size_t e = i0 + qq * st;
        const float4 v = *(const float4*)(X + e);
        const size_t row = e >> 11;
        const size_t col = e & 2047;
        uint2 hp;
        hp.x = pack_h2(v.x, v.y);
        hp.y = pack_h2(v.z, v.w);
        *(uint2*)(Y + ((2 * row + parity) << 11) + col) = hp;
    }
}

// ---------------------------------------------------------------------------
// Fused LayerNorm -> plain fp16 (row stride HID)
// ---------------------------------------------------------------------------
__global__ void __launch_bounds__(256) layernorm_h_kernel(
    const float* __restrict__ x, const float* __restrict__ w,
    const float* __restrict__ b, __half* __restrict__ outh)
{
    const int t   = blockIdx.x;
    const int tid = threadIdx.x;
    const float* xr = x + (size_t)t * HID;

    float v[8];
    float s = 0.f, s2 = 0.f;
#pragma unroll
    for (int i = 0; i < 8; i++) {
        v[i] = xr[tid + i * 256];
        s  += v[i];
        s2 += v[i] * v[i];
    }
#pragma unroll
    for (int o = 16; o; o >>= 1) {
        s  += __shfl_xor_sync(0xffffffffu, s,  o);
        s2 += __shfl_xor_sync(0xffffffffu, s2, o);
    }
    __shared__ float ss[8], ss2[8];
    if ((tid & 31) == 0) { ss[tid >> 5] = s; ss2[tid >> 5] = s2; }
    __syncthreads();
    if (tid < 32) {
        s  = (tid < 8) ? ss [tid] : 0.f;
        s2 = (tid < 8) ? ss2[tid] : 0.f;
#pragma unroll
        for (int o = 4; o; o >>= 1) {
            s  += __shfl_xor_sync(0xffffffffu, s,  o);
            s2 += __shfl_xor_sync(0xffffffffu, s2, o);
        }
        if (tid == 0) { ss[0] = s; ss2[0] = s2; }
    }
    __syncthreads();
    const float mean = ss[0] * (1.f / HID);
    const float var  = ss2[0] * (1.f / HID) - mean * mean;
    const float rstd = rsqrtf(var + LN_EPS);
    __half* orow = outh + (size_t)t * HID;
#pragma unroll
    for (int i = 0; i < 8; i++) {
        const int idx = tid + i * 256;
        const float y = (v[i] - mean) * rstd * w[idx] + b[idx];
        orow[idx] = __float2half_rn(y);
    }
}

// ---------------------------------------------------------------------------
// Partial RoPE: q row stride HID, k row stride kvs
// ---------------------------------------------------------------------------
__global__ void __launch_bounds__(256) rope_kernel(
    float* __restrict__ q, float* __restrict__ k,
    const int* __restrict__ pos_ids, int kvs)
{
    const int idx = blockIdx.x * blockDim.x + threadIdx.x;
    if (idx >= TT * NH * 8) return;
    const int i = idx & 7;
    const int h = (idx >> 3) & 31;
    const int t = idx >> 8;
    const int b = t / SS, s = t % SS;
    const int pos = pos_ids[b * SS + s];

    const float freq = powf(10000.0f, -(2.0f * (float)i) / (float)ROT);
    const float ang  = (float)pos * freq;
    float c, si;
    sincosf(ang, &si, &c);

    {
        const size_t base = (size_t)t * HID + h * HD;
        float q0 = q[base + i], q1 = q[base + i + 8];
        q[base + i]     = q0 * c - q1 * si;
        q[base + i + 8] = q1 * c + q0 * si;
    }
    {
        const size_t base = (size_t)t * kvs + h * HD;
        float k0 = k[base + i], k1 = k[base + i + 8];
        k[base + i]     = k0 * c - k1 * si;
        k[base + i + 8] = k1 * c + k0 * si;
    }
}

// ---------------------------------------------------------------------------
// Launch
// ---------------------------------------------------------------------------
extern "C" void kernel_launch(void* const* d_in, const int* in_sizes, int n_in,
                              void* d_out, int out_size)
{
    const float* hidden = (const float*)d_in[0];
    const float* memory = (const float*)d_in[1];
    const float* mask   = (const float*)d_in[2];
    const int*   pos    = (const int*)  d_in[3];
    const float* Wq     = (const float*)d_in[4];
    const float* Wk     = (const float*)d_in[5];
    const float* Wv     = (const float*)d_in[6];
    const float* Wo     = (const float*)d_in[7];
    const float* ln1w   = (const float*)d_in[8];
    const float* ln1b   = (const float*)d_in[9];
    const float* ln2w   = (const float*)d_in[10];
    const float* ln2b   = (const float*)d_in[11];
    const float* gw     = (const float*)d_in[12];
    const float* uw     = (const float*)d_in[13];
    const float* dw     = (const float*)d_in[14];
    float* out = (float*)d_out;

    float *q, *kv, *h;
    __half *a2, *b2, *c2;
    cudaGetSymbolAddress((void**)&q,    g_q);
    cudaGetSymbolAddress((void**)&kv,   g_kv);
    cudaGetSymbolAddress((void**)&h,    g_h);
    cudaGetSymbolAddress((void**)&a2,   g_a2);
    cudaGetSymbolAddress((void**)&b2,   g_b2);
    cudaGetSymbolAddress((void**)&c2,   g_c2);

    cudaFuncSetAttribute(gemm2_kernel,
                         cudaFuncAttributeMaxDynamicSharedMemorySize, GEMM_DSMEM);
    cudaFuncSetAttribute(flash_attn_kernel,
                         cudaFuncAttributeMaxDynamicSharedMemorySize, FA_SMEM);

    const size_t HH = (size_t)HID * HID;

    auto gemm = [&](const __half* A, const __half* B,
                    const float* add, float* C, __half* O2,
                    int M, int N, int K2, int mode) {
        gemm2_kernel<<<dim3(N / 128, M / 128), 128, GEMM_DSMEM>>>(
            A, B, add, C, O2, M, N, K2, mode);
    };
    auto conv = [&](const float* X, __half* Y, size_t n) {
        conv_kernel<<<(unsigned)(n / 4096), 256>>>(X, Y);
    };

    // weights + inputs to fp16 first (so the 6th launch is a GEMM for ncu)
    conv(Wq, b2, HH);                 // 1
    conv(Wk, b2 + HH, HH);            // 2
    conv(Wv, b2 + 2 * HH, HH);        // 3
    conv(memory, c2, (size_t)TT * HID); // 4
    layernorm_h_kernel<<<TT, 256>>>(hidden, ln1w, ln1b, a2);  // 5

    // Q projection (ncu target)                               // 6
    gemm(a2, b2, nullptr, q, nullptr, TT, HID, HID, 0);
    // K+V fused projection (Wk|Wv stacked)                    // 7
    gemm(c2, b2 + HH, nullptr, kv, nullptr, TT, 2 * HID, HID, 0);

    // RoPE                                                    // 8
    rope_kernel<<<(TT * NH * 8) / 256, 256>>>(q, kv, pos, 2 * HID);

    // flash attention -> plain fp16 ctx into a2               // 9
    flash_attn_kernel<<<dim3(SS / 128, BB * NH), 256, FA_SMEM>>>(
        q, kv, kv + HID, mask, a2, 2 * HID);

    // O projection + residual                                 // 10-11
    conv(Wo, b2, HH);
    gemm(a2, b2, hidden, h, nullptr, TT, HID, HID, 1);

    // LN2                                                     // 12
    layernorm_h_kernel<<<TT, 256>>>(h, ln2w, ln2b, a2);

    // fused gate+up GEMM (interleaved weights), then down     // 13-17
    conv_il_kernel<<<(unsigned)((size_t)DFF * HID / 4096), 256>>>(gw, b2, 0);
    conv_il_kernel<<<(unsigned)((size_t)DFF * HID / 4096), 256>>>(uw, b2, 1);
    gemm(a2, b2, nullptr, nullptr, c2, TT, 2 * DFF, HID, 4);  // silu(g)*u -> c2
    conv(dw, b2, (size_t)HID * DFF);
    gemm(c2, b2, h, out, nullptr, TT, HID, DFF, 1);
}

// round 12
// speedup vs baseline: 2.8813x; 1.0152x over previous
#include <cuda_runtime.h>
#include <cuda_fp16.h>
#include <math.h>
#include <stdint.h>

// ---------------------------------------------------------------------------
// Problem constants
// ---------------------------------------------------------------------------
#define BB     2
#define SS     1024
#define TT     (BB*SS)        // 2048 tokens
#define HID    2048
#define NH     32
#define HD     64
#define ROT    16
#define DFF    8192
#define LN_EPS 1e-5f

// ---------------------------------------------------------------------------
// Static scratch (no allocations allowed)
// ---------------------------------------------------------------------------
__device__ float g_q  [(size_t)TT * HID];
__device__ float g_kv [(size_t)TT * (2 * HID)];        // K | V fused (row stride 4096)
__device__ float g_h  [(size_t)TT * HID];

// fp16 scratch
__device__ __half g_a2[(size_t)TT * HID];              // LN outputs / ctx
__device__ __half g_b2[(size_t)DFF * (2 * HID)];       // weights
__device__ __half g_c2[(size_t)TT * DFF];              // memory-fp16 / activated gate

// ---------------------------------------------------------------------------
// helpers
// ---------------------------------------------------------------------------
__device__ __forceinline__ uint32_t smem_u32(const void* p) {
    uint32_t a;
    asm("{ .reg .u64 t; cvta.to.shared.u64 t, %1; cvt.u32.u64 %0, t; }"
        : "=r"(a) : "l"(p));
    return a;
}

#define CP_ASYNC16(sa, ga) \
    asm volatile("cp.async.cg.shared.global [%0], [%1], 16;" :: "r"(sa), "l"(ga))
#define CP_COMMIT() asm volatile("cp.async.commit_group;")
#define CP_WAIT1()  asm volatile("cp.async.wait_group 1;")

#define LDSM4(r, addr) \
    asm volatile("ldmatrix.sync.aligned.m8n8.x4.shared.b16 {%0,%1,%2,%3}, [%4];" \
        : "=r"((r)[0]), "=r"((r)[1]), "=r"((r)[2]), "=r"((r)[3]) : "r"(addr))

#define LDSM4T(r, addr) \
    asm volatile("ldmatrix.sync.aligned.m8n8.x4.trans.shared.b16 {%0,%1,%2,%3}, [%4];" \
        : "=r"((r)[0]), "=r"((r)[1]), "=r"((r)[2]), "=r"((r)[3]) : "r"(addr))

#define MMA16816(d, a, b0, b1) \
    asm volatile("mma.sync.aligned.m16n8k16.row.col.f32.f16.f16.f32 " \
        "{%0,%1,%2,%3}, {%4,%5,%6,%7}, {%8,%9}, {%0,%1,%2,%3};" \
        : "+f"((d)[0]), "+f"((d)[1]), "+f"((d)[2]), "+f"((d)[3]) \
        : "r"((a)[0]), "r"((a)[1]), "r"((a)[2]), "r"((a)[3]), "r"(b0), "r"(b1))

__device__ __forceinline__ uint32_t pack_h2(float a, float b) {
    uint32_t h0 = (uint32_t)__half_as_ushort(__float2half_rn(a));
    uint32_t h1 = (uint32_t)__half_as_ushort(__float2half_rn(b));
    return h0 | (h1 << 16);
}

// ---------------------------------------------------------------------------
// HMMA fp16 GEMM:  C[M,N] = A[M,K2] * B[N,K2]^T
// mode 0: C fp32   mode 1: C = acc + add
// mode 4: interleaved gate/up -> silu(even)*odd -> fp16 out2 (width N/2)
// 128x128 tile, BK=64, 3-stage cp.async, 128 thr = 4 warps, warp tile 64x64
// ---------------------------------------------------------------------------
#define GSTAGES      3
#define GTILE_BYTES  16384
#define GSTAGE_BYTES (2 * GTILE_BYTES)
#define GEMM_DSMEM   (GSTAGES * GSTAGE_BYTES)   // 96 KB

__global__ void __launch_bounds__(128, 2) gemm2_kernel(
    const __half* __restrict__ A, const __half* __restrict__ B,
    const float* __restrict__ add, float* __restrict__ C,
    __half* __restrict__ out2,
    int M, int N, int K2, int mode)
{
    extern __shared__ __align__(128) char smem[];
    const uint32_t smem_base = smem_u32(smem);

    const int tid  = threadIdx.x;
    const int lane = tid & 31;
    const int warp = tid >> 5;
    const int wm = warp >> 1;
    const int wn = warp & 1;
    const int bx = blockIdx.x, by = blockIdx.y;
    const int nk = K2 >> 6;

    int lrow[8], lswz[8];
#pragma unroll
    for (int p = 0; p < 8; p++) {
        const int id = p * 128 + tid;
        const int row = id >> 3;
        const int c   = id & 7;
        lrow[p] = row;
        lswz[p] = row * 128 + ((c ^ (row & 7)) << 4);
    }
    const __half* Abase = A + (size_t)(by * 128) * K2;
    const __half* Bbase = B + (size_t)(bx * 128) * K2;

    float acc[4][8][4];
#pragma unroll
    for (int i = 0; i < 4; i++)
#pragma unroll
        for (int j = 0; j < 8; j++)
#pragma unroll
            for (int r = 0; r < 4; r++) acc[i][j][r] = 0.f;

    auto load_tile = [&](int ks, int buf) {
        const uint32_t sa = smem_base + buf * GSTAGE_BYTES;
        const uint32_t sb = sa + GTILE_BYTES;
        const int koff = ks * 64;
#pragma unroll
        for (int p = 0; p < 8; p++) {
            const int c = (p * 128 + tid) & 7;
            CP_ASYNC16(sa + lswz[p], Abase + (size_t)lrow[p] * K2 + koff + c * 8);
            CP_ASYNC16(sb + lswz[p], Bbase + (size_t)lrow[p] * K2 + koff + c * 8);
        }
    };

    load_tile(0, 0); CP_COMMIT();
    load_tile(1, 1); CP_COMMIT();

    for (int ks = 0; ks < nk; ks++) {
        CP_WAIT1();
        __syncthreads();
        if (ks + 2 < nk) load_tile(ks + 2, (ks + 2) % GSTAGES);
        CP_COMMIT();

        const int buf = ks % GSTAGES;
        const uint32_t sa = smem_base + buf * GSTAGE_BYTES;
        const uint32_t sb = sa + GTILE_BYTES;

        uint32_t ra[2][4][4], rb[2][4][4];

        auto ldfrag = [&](int kk, int pb) {
#pragma unroll
            for (int mt = 0; mt < 4; mt++) {
                const int row = wm * 64 + mt * 16 + (lane & 15);
                const int ch  = kk * 2 + (lane >> 4);
                LDSM4(ra[pb][mt], sa + row * 128 + ((ch ^ (row & 7)) << 4));
            }
#pragma unroll
            for (int p = 0; p < 4; p++) {
                const int n  = wn * 64 + p * 16 + (lane & 7) + ((lane >> 4) << 3);
                const int ch = kk * 2 + ((lane >> 3) & 1);
                LDSM4(rb[pb][p], sb + n * 128 + ((ch ^ (n & 7)) << 4));
            }
        };

        ldfrag(0, 0);
#pragma unroll
        for (int kk = 0; kk < 4; kk++) {
            const int cur = kk & 1;
            if (kk < 3) ldfrag(kk + 1, cur ^ 1);
#pragma unroll
            for (int mt = 0; mt < 4; mt++)
#pragma unroll
                for (int nt = 0; nt < 8; nt++)
                    MMA16816(acc[mt][nt], ra[cur][mt],
                             rb[cur][nt >> 1][(nt & 1) * 2],
                             rb[cur][nt >> 1][(nt & 1) * 2 + 1]);
        }
    }

    // epilogue
    const int r0 = lane >> 2;
    const int c0 = (lane & 3) * 2;
#pragma unroll
    for (int mt = 0; mt < 4; mt++) {
#pragma unroll
        for (int half_ = 0; half_ < 2; half_++) {
            const int row = by * 128 + wm * 64 + mt * 16 + r0 + half_ * 8;
            const int colb = bx * 128 + wn * 64;
            if (mode == 4) {
                __half* Or = out2 + (size_t)row * (N >> 1);
#pragma unroll
                for (int nt = 0; nt < 8; nt++) {
                    float g = acc[mt][nt][half_ * 2];
                    const float u = acc[mt][nt][half_ * 2 + 1];
                    g = g / (1.f + expf(-g)) * u;
                    Or[(colb + nt * 8 + c0) >> 1] = __float2half_rn(g);
                }
            } else {
                float* Cr = C + (size_t)row * N + colb;
                const float* Ar = (mode == 1) ? add + (size_t)row * N + colb : nullptr;
#pragma unroll
                for (int nt = 0; nt < 8; nt++) {
                    float2 o;
                    o.x = acc[mt][nt][half_ * 2];
                    o.y = acc[mt][nt][half_ * 2 + 1];
                    if (Ar) {
                        const float2 av = *(const float2*)(Ar + nt * 8 + c0);
                        o.x += av.x; o.y += av.y;
                    }
                    *(float2*)(Cr + nt * 8 + c0) = o;
                }
            }
        }
    }
}

// ---------------------------------------------------------------------------
// Flash attention, fp16 HMMA, 2-term QK ([Qh|Ql]x[Kh|Kh]) and PV ((Ph+Pl)xVh),
// fp32 online softmax. V stored row-major [k][d], B-fragments via ldmatrix.trans.
// 128 q-rows x one head per CTA, 256 thr, 2 CTAs/SM.
// ---------------------------------------------------------------------------
#define QS_STRIDE 136     // 128 data + 8 pad (fp16 elems)
#define VS_STRIDE 72      // 64 data + 8 pad
#define FA_SMEM   (2*(128*QS_STRIDE*2) + 128*VS_STRIDE*2)   // 86528 B

__global__ void __launch_bounds__(256, 2) flash_attn_kernel(
    const float* __restrict__ q, const float* __restrict__ kbase,
    const float* __restrict__ vbase, const float* __restrict__ mask,
    __half* __restrict__ ctxh, int kvs)
{
    extern __shared__ __align__(128) char smem[];
    __half* Qs = (__half*)smem;
    __half* Ks = Qs + 128 * QS_STRIDE;
    __half* Vs = Ks + 128 * QS_STRIDE;
    const uint32_t QsB = smem_u32(Qs);
    const uint32_t KsB = smem_u32(Ks);
    const uint32_t VsB = smem_u32(Vs);

    const int tid  = threadIdx.x;
    const int lane = tid & 31;
    const int w    = tid >> 5;
    const int bh = blockIdx.y;
    const int b = bh >> 5, h = bh & 31;
    const int q0 = blockIdx.x * 128;

    // ---- load Q tile once, 2-split [Qh|Ql], vectorized stores ----
#pragma unroll
    for (int p = 0; p < 8; p++) {
        const int id = p * 256 + tid;
        const int row = id >> 4;
        const int c4  = (id & 15) * 4;
        const float4 vv = *(const float4*)(q + (size_t)(b * SS + q0 + row) * HID + h * HD + c4);
        uint2 hi, lo;
        hi.x = pack_h2(vv.x, vv.y); hi.y = pack_h2(vv.z, vv.w);
        lo.x = pack_h2(vv.x - __half2float(__float2half_rn(vv.x)),
                       vv.y - __half2float(__float2half_rn(vv.y)));
        lo.y = pack_h2(vv.z - __half2float(__float2half_rn(vv.z)),
                       vv.w - __half2float(__float2half_rn(vv.w)));
        *(uint2*)(Qs + row * QS_STRIDE + c4)      = hi;
        *(uint2*)(Qs + row * QS_STRIDE + 64 + c4) = lo;
    }

    float sc[64];
    float o[8][4];
#pragma unroll
    for (int j = 0; j < 8; j++)
#pragma unroll
        for (int r = 0; r < 4; r++) o[j][r] = 0.f;
    float mrow[2] = {-INFINITY, -INFINITY};
    float lrow[2] = {0.f, 0.f};

    const int rA = lane >> 2;
    const int cA = (lane & 3) * 2;

    for (int kt = 0; kt < SS / 128; kt++) {
        __syncthreads();
        // ---- load K tile, [Kh|Kh], vectorized ----
#pragma unroll
        for (int p = 0; p < 8; p++) {
            const int id = p * 256 + tid;
            const int row = id >> 4;
            const int c4  = (id & 15) * 4;
            const float4 vv = *(const float4*)(kbase + (size_t)(b * SS + kt * 128 + row) * kvs + h * HD + c4);
            uint2 hi;
            hi.x = pack_h2(vv.x, vv.y); hi.y = pack_h2(vv.z, vv.w);
            *(uint2*)(Ks + row * QS_STRIDE + c4)      = hi;
            *(uint2*)(Ks + row * QS_STRIDE + 64 + c4) = hi;
        }
        // ---- load V tile row-major [k][d], coalesced ----
#pragma unroll
        for (int p = 0; p < 8; p++) {
            const int id = p * 256 + tid;
            const int krow = id >> 4;
            const int c4   = (id & 15) * 4;
            const float4 vv = *(const float4*)(vbase + (size_t)(b * SS + kt * 128 + krow) * kvs + h * HD + c4);
            uint2 hi;
            hi.x = pack_h2(vv.x, vv.y); hi.y = pack_h2(vv.z, vv.w);
            *(uint2*)(Vs + krow * VS_STRIDE + c4) = hi;
        }
        __syncthreads();

        // ---- scores: S = [Qh|Ql] . [Kh|Kh]^T  (K=128) ----
#pragma unroll
        for (int i = 0; i < 64; i++) sc[i] = 0.f;
#pragma unroll
        for (int s = 0; s < 8; s++) {
            uint32_t ra[4];
            const int arow2 = 16 * w + (lane & 15);
            LDSM4(ra, QsB + (arow2 * QS_STRIDE + s * 16 + ((lane >> 4) << 3)) * 2);
#pragma unroll
            for (int t2 = 0; t2 < 8; t2++) {
                uint32_t rb[4];
                const int n  = t2 * 16 + (lane & 7) + ((lane >> 4) << 3);
                const int cb = s * 16 + (((lane >> 3) & 1) << 3);
                LDSM4(rb, KsB + (n * QS_STRIDE + cb) * 2);
                MMA16816((sc + (2 * t2) * 4),     ra, rb[0], rb[1]);
                MMA16816((sc + (2 * t2 + 1) * 4), ra, rb[2], rb[3]);
            }
        }

        // ---- scale + mask, online softmax ----
        const int qrA = q0 + 16 * w + rA;
        const int qrB = qrA + 8;
        float tm[2] = {-INFINITY, -INFINITY};
#pragma unroll
        for (int t = 0; t < 16; t++) {
            const int kc = kt * 128 + t * 8 + cA;
            const float2 mA = *(const float2*)(mask + ((size_t)b * SS + qrA) * SS + kc);
            const float2 mB = *(const float2*)(mask + ((size_t)b * SS + qrB) * SS + kc);
            sc[t * 4 + 0] = sc[t * 4 + 0] * 0.125f + mA.x;
            sc[t * 4 + 1] = sc[t * 4 + 1] * 0.125f + mA.y;
            sc[t * 4 + 2] = sc[t * 4 + 2] * 0.125f + mB.x;
            sc[t * 4 + 3] = sc[t * 4 + 3] * 0.125f + mB.y;
            tm[0] = fmaxf(tm[0], fmaxf(sc[t * 4 + 0], sc[t * 4 + 1]));
            tm[1] = fmaxf(tm[1], fmaxf(sc[t * 4 + 2], sc[t * 4 + 3]));
        }
#pragma unroll
        for (int off = 1; off <= 2; off <<= 1) {
            tm[0] = fmaxf(tm[0], __shfl_xor_sync(0xffffffffu, tm[0], off));
            tm[1] = fmaxf(tm[1], __shfl_xor_sync(0xffffffffu, tm[1], off));
        }
        const float mn0 = fmaxf(mrow[0], tm[0]);
        const float mn1 = fmaxf(mrow[1], tm[1]);
        const float sc0 = __expf(mrow[0] - mn0);
        const float sc1 = __expf(mrow[1] - mn1);
        float ts[2] = {0.f, 0.f};
#pragma unroll
        for (int t = 0; t < 16; t++) {
            sc[t * 4 + 0] = __expf(sc[t * 4 + 0] - mn0);
            sc[t * 4 + 1] = __expf(sc[t * 4 + 1] - mn0);
            sc[t * 4 + 2] = __expf(sc[t * 4 + 2] - mn1);
            sc[t * 4 + 3] = __expf(sc[t * 4 + 3] - mn1);
            ts[0] += sc[t * 4 + 0] + sc[t * 4 + 1];
            ts[1] += sc[t * 4 + 2] + sc[t * 4 + 3];
        }
#pragma unroll
        for (int off = 1; off <= 2; off <<= 1) {
            ts[0] += __shfl_xor_sync(0xffffffffu, ts[0], off);
            ts[1] += __shfl_xor_sync(0xffffffffu, ts[1], off);
        }
        lrow[0] = lrow[0] * sc0 + ts[0];
        lrow[1] = lrow[1] * sc1 + ts[1];
        mrow[0] = mn0; mrow[1] = mn1;
#pragma unroll
        for (int j = 0; j < 8; j++) {
            o[j][0] *= sc0; o[j][1] *= sc0;
            o[j][2] *= sc1; o[j][3] *= sc1;
        }

        // ---- O += (Ph + Pl) . Vh, B-frags via ldmatrix.trans of [k][d] ----
#pragma unroll
        for (int s2 = 0; s2 < 8; s2++) {
            const float p00 = sc[(2 * s2) * 4 + 0], p01 = sc[(2 * s2) * 4 + 1];
            const float p10 = sc[(2 * s2) * 4 + 2], p11 = sc[(2 * s2) * 4 + 3];
            const float r00 = sc[(2 * s2 + 1) * 4 + 0], r01 = sc[(2 * s2 + 1) * 4 + 1];
            const float r10 = sc[(2 * s2 + 1) * 4 + 2], r11 = sc[(2 * s2 + 1) * 4 + 3];
            uint32_t ph[4], pl[4];
            ph[0] = pack_h2(p00, p01); ph[1] = pack_h2(p10, p11);
            ph[2] = pack_h2(r00, r01); ph[3] = pack_h2(r10, r11);
            pl[0] = pack_h2(p00 - __half2float(__float2half_rn(p00)),
                            p01 - __half2float(__float2half_rn(p01)));
            pl[1] = pack_h2(p10 - __half2float(__float2half_rn(p10)),
                            p11 - __half2float(__float2half_rn(p11)));
            pl[2] = pack_h2(r00 - __half2float(__float2half_rn(r00)),
                            r01 - __half2float(__float2half_rn(r01)));
            pl[3] = pack_h2(r10 - __half2float(__float2half_rn(r10)),
                            r11 - __half2float(__float2half_rn(r11)));
            const int krow = s2 * 16 + (lane & 7) + (((lane >> 3) & 1) << 3);
#pragma unroll
            for (int dt = 0; dt < 4; dt++) {
                uint32_t bh_[4];
                LDSM4T(bh_, VsB + (krow * VS_STRIDE + dt * 16 + ((lane >> 4) << 3)) * 2);
                MMA16816(o[2 * dt],     ph, bh_[0], bh_[1]);
                MMA16816(o[2 * dt + 1], ph, bh_[2], bh_[3]);
                MMA16816(o[2 * dt],     pl, bh_[0], bh_[1]);
                MMA16816(o[2 * dt + 1], pl, bh_[2], bh_[3]);
            }
        }
    }

    // ---- epilogue: normalize, write plain fp16 ctx ----
    const float inv0 = 1.f / lrow[0];
    const float inv1 = 1.f / lrow[1];
    const size_t tokA = (size_t)(b * SS + q0 + 16 * w + rA);
    const size_t tokB = tokA + 8;
#pragma unroll
    for (int j = 0; j < 8; j++) {
        const int cg = h * HD + j * 8 + cA;
        ctxh[tokA * HID + cg]     = __float2half_rn(o[j][0] * inv0);
        ctxh[tokA * HID + cg + 1] = __float2half_rn(o[j][1] * inv0);
        ctxh[tokB * HID + cg]     = __float2half_rn(o[j][2] * inv1);
        ctxh[tokB * HID + cg + 1] = __float2half_rn(o[j][3] * inv1);
    }
}

// ---------------------------------------------------------------------------
// fp32 -> fp16 plain convert, MLP=8
// ---------------------------------------------------------------------------
__global__ void __launch_bounds__(256) conv_kernel(
    const float* __restrict__ X, __half* __restrict__ Y)
{
    const size_t i0 = ((size_t)blockIdx.x * 256 + threadIdx.x) * 4;
    const size_t st = (size_t)gridDim.x * 1024;
    float4 v[8];
#pragma unroll
    for (int qq = 0; qq < 8; qq++) v[qq] = *(const float4*)(X + i0 + qq * st);
#pragma unroll
    for (int qq = 0; qq < 8; qq++) {
        uint2 hp;
        hp.x = pack_h2(v[qq].x, v[qq].y);
        hp.y = pack_h2(v[qq].z, v[qq].w);
        *(uint2*)(Y + i0 + qq * st) = hp;
    }
}

// ---------------------------------------------------------------------------
// fp32 -> fp16 convert with row interleave: X row j -> Y row 2j+parity
// X is [DFF x HID]; Y row stride HID. (HID = 2048 = 1<<11), MLP=8
// ---------------------------------------------------------------------------
__global__ void __launch_bounds__(256) conv_il_kernel(
    const float* __restrict__ X, __half* __restrict__ Y, int parity)
{
    const size_t i0 = ((size_t)blockIdx.x * 256 + threadIdx.x) * 4;
    const size_t st = (size_t)gridDim.x * 1024;
    float4 v[8];
#pragma unroll
    for (int qq = 0; qq < 8; qq++) v[qq] = *(const float4*)(X + i0 + qq * st);
#pragma unroll
    for (int qq = 0; qq < 8; qq++) {
        const size_t e = i0 + qq * st;
        const size_t row = e >> 11;
        const size_t col = e & 2047;
        uint2 hp;
        hp.x = pack_h2(v[qq].x, v[qq].y);
        hp.y = pack_h2(v[qq].z, v[qq].w);
        *(uint2*)(Y + ((2 * row + parity) << 11) + col) = hp;
    }
}

// ---------------------------------------------------------------------------
// Fused LayerNorm -> plain fp16 (row stride HID)
// ---------------------------------------------------------------------------
__global__ void __launch_bounds__(256) layernorm_h_kernel(
    const float* __restrict__ x, const float* __restrict__ w,
    const float* __restrict__ b, __half* __restrict__ outh)
{
    const int t   = blockIdx.x;
    const int tid = threadIdx.x;
    const float* xr = x + (size_t)t * HID;

    float v[8];
    float s = 0.f, s2 = 0.f;
#pragma unroll
    for (int i = 0; i < 8; i++) {
        v[i] = xr[tid + i * 256];
        s  += v[i];
        s2 += v[i] * v[i];
    }
#pragma unroll
    for (int o = 16; o; o >>= 1) {
        s  += __shfl_xor_sync(0xffffffffu, s,  o);
        s2 += __shfl_xor_sync(0xffffffffu, s2, o);
    }
    __shared__ float ss[8], ss2[8];
    if ((tid & 31) == 0) { ss[tid >> 5] = s; ss2[tid >> 5] = s2; }
    __syncthreads();
    if (tid < 32) {
        s  = (tid < 8) ? ss [tid] : 0.f;
        s2 = (tid < 8) ? ss2[tid] : 0.f;
#pragma unroll
        for (int o = 4; o; o >>= 1) {
            s  += __shfl_xor_sync(0xffffffffu, s,  o);
            s2 += __shfl_xor_sync(0xffffffffu, s2, o);
        }
        if (tid == 0) { ss[0] = s; ss2[0] = s2; }
    }
    __syncthreads();
    const float mean = ss[0] * (1.f / HID);
    const float var  = ss2[0] * (1.f / HID) - mean * mean;
    const float rstd = rsqrtf(var + LN_EPS);
    __half* orow = outh + (size_t)t * HID;
#pragma unroll
    for (int i = 0; i < 8; i++) {
        const int idx = tid + i * 256;
        const float y = (v[i] - mean) * rstd * w[idx] + b[idx];
        orow[idx] = __float2half_rn(y);
    }
}

// ---------------------------------------------------------------------------
// Partial RoPE: q row stride HID, k row stride kvs
// ---------------------------------------------------------------------------
__global__ void __launch_bounds__(256) rope_kernel(
    float* __restrict__ q, float* __restrict__ k,
    const int* __restrict__ pos_ids, int kvs)
{
    const int idx = blockIdx.x * blockDim.x + threadIdx.x;
    if (idx >= TT * NH * 8) return;
    const int i = idx & 7;
    const int h = (idx >> 3) & 31;
    const int t = idx >> 8;
    const int b = t / SS, s = t % SS;
    const int pos = pos_ids[b * SS + s];

    const float freq = powf(10000.0f, -(2.0f * (float)i) / (float)ROT);
    const float ang  = (float)pos * freq;
    float c, si;
    sincosf(ang, &si, &c);

    {
        const size_t base = (size_t)t * HID + h * HD;
        float q0 = q[base + i], q1 = q[base + i + 8];
        q[base + i]     = q0 * c - q1 * si;
        q[base + i + 8] = q1 * c + q0 * si;
    }
    {
        const size_t base = (size_t)t * kvs + h * HD;
        float k0 = k[base + i], k1 = k[base + i + 8];
        k[base + i]     = k0 * c - k1 * si;
        k[base + i + 8] = k1 * c + k0 * si;
    }
}

// ---------------------------------------------------------------------------
// Launch
// ---------------------------------------------------------------------------
extern "C" void kernel_launch(void* const* d_in, const int* in_sizes, int n_in,
                              void* d_out, int out_size)
{
    const float* hidden = (const float*)d_in[0];
    const float* memory = (const float*)d_in[1];
    const float* mask   = (const float*)d_in[2];
    const int*   pos    = (const int*)  d_in[3];
    const float* Wq     = (const float*)d_in[4];
    const float* Wk     = (const float*)d_in[5];
    const float* Wv     = (const float*)d_in[6];
    const float* Wo     = (const float*)d_in[7];
    const float* ln1w   = (const float*)d_in[8];
    const float* ln1b   = (const float*)d_in[9];
    const float* ln2w   = (const float*)d_in[10];
    const float* ln2b   = (const float*)d_in[11];
    const float* gw     = (const float*)d_in[12];
    const float* uw     = (const float*)d_in[13];
    const float* dw     = (const float*)d_in[14];
    float* out = (float*)d_out;

    float *q, *kv, *h;
    __half *a2, *b2, *c2;
    cudaGetSymbolAddress((void**)&q,    g_q);
    cudaGetSymbolAddress((void**)&kv,   g_kv);
    cudaGetSymbolAddress((void**)&h,    g_h);
    cudaGetSymbolAddress((void**)&a2,   g_a2);
    cudaGetSymbolAddress((void**)&b2,   g_b2);
    cudaGetSymbolAddress((void**)&c2,   g_c2);

    cudaFuncSetAttribute(gemm2_kernel,
                         cudaFuncAttributeMaxDynamicSharedMemorySize, GEMM_DSMEM);
    cudaFuncSetAttribute(flash_attn_kernel,
                         cudaFuncAttributeMaxDynamicSharedMemorySize, FA_SMEM);

    const size_t HH = (size_t)HID * HID;

    auto gemm = [&](const __half* A, const __half* B,
                    const float* add, float* C, __half* O2,
                    int M, int N, int K2, int mode) {
        gemm2_kernel<<<dim3(N / 128, M / 128), 128, GEMM_DSMEM>>>(
            A, B, add, C, O2, M, N, K2, mode);
    };
    auto conv = [&](const float* X, __half* Y, size_t n) {
        conv_kernel<<<(unsigned)(n / 8192), 256>>>(X, Y);
    };

    // weights + inputs to fp16
    conv(Wq, b2, HH);
    conv(Wk, b2 + HH, HH);
    conv(Wv, b2 + 2 * HH, HH);
    conv(memory, c2, (size_t)TT * HID);
    layernorm_h_kernel<<<TT, 256>>>(hidden, ln1w, ln1b, a2);

    // Q projection
    gemm(a2, b2, nullptr, q, nullptr, TT, HID, HID, 0);
    // K+V fused projection (Wk|Wv stacked)
    gemm(c2, b2 + HH, nullptr, kv, nullptr, TT, 2 * HID, HID, 0);

    // RoPE
    rope_kernel<<<(TT * NH * 8) / 256, 256>>>(q, kv, pos, 2 * HID);

    // flash attention -> plain fp16 ctx into a2
    flash_attn_kernel<<<dim3(SS / 128, BB * NH), 256, FA_SMEM>>>(
        q, kv, kv + HID, mask, a2, 2 * HID);

    // O projection + residual
    conv(Wo, b2, HH);
    gemm(a2, b2, hidden, h, nullptr, TT, HID, HID, 1);

    // LN2
    layernorm_h_kernel<<<TT, 256>>>(h, ln2w, ln2b, a2);

    // fused gate+up GEMM (interleaved weights), then down
    conv_il_kernel<<<(unsigned)((size_t)DFF * HID / 8192), 256>>>(gw, b2, 0);
    conv_il_kernel<<<(unsigned)((size_t)DFF * HID / 8192), 256>>>(uw, b2, 1);
    gemm(a2, b2, nullptr, nullptr, c2, TT, 2 * DFF, HID, 4);  // silu(g)*u -> c2
    conv(dw, b2, (size_t)HID * DFF);
    gemm(c2, b2, h, out, nullptr, TT, HID, DFF, 1);
}

// round 13
// speedup vs baseline: 2.9203x; 1.0135x over previous
#include <cuda_runtime.h>
#include <cuda_fp16.h>
#include <math.h>
#include <stdint.h>

#define BB     2
#define SS     1024
#define TT     (BB*SS)
#define HID    2048
#define NH     32
#define HD     64
#define ROT    16
#define DFF    8192
#define LN_EPS 1e-5f

__device__ float g_q  [(size_t)TT * HID];
__device__ float g_kv [(size_t)TT * (2 * HID)];
__device__ float g_h  [(size_t)TT * HID];

__device__ __half g_a2[(size_t)TT * HID];
__device__ __half g_b2[(size_t)DFF * (2 * HID)];
__device__ __half g_c2[(size_t)TT * DFF];

__device__ __forceinline__ uint32_t smem_u32(const void* p) {
    uint32_t a;
    asm("{ .reg .u64 t; cvta.to.shared.u64 t, %1; cvt.u32.u64 %0, t; }"
        : "=r"(a) : "l"(p));
    return a;
}

#define CP_ASYNC16(sa, ga) \
    asm volatile("cp.async.cg.shared.global [%0], [%1], 16;" :: "r"(sa), "l"(ga))
#define CP_COMMIT() asm volatile("cp.async.commit_group;")
#define CP_WAIT1()  asm volatile("cp.async.wait_group 1;")

#define LDSM4(r, addr) \
    asm volatile("ldmatrix.sync.aligned.m8n8.x4.shared.b16 {%0,%1,%2,%3}, [%4];" \
        : "=r"((r)[0]), "=r"((r)[1]), "=r"((r)[2]), "=r"((r)[3]) : "r"(addr))

#define LDSM4T(r, addr) \
    asm volatile("ldmatrix.sync.aligned.m8n8.x4.trans.shared.b16 {%0,%1,%2,%3}, [%4];" \
        : "=r"((r)[0]), "=r"((r)[1]), "=r"((r)[2]), "=r"((r)[3]) : "r"(addr))

#define MMA16816(d, a, b0, b1) \
    asm volatile("mma.sync.aligned.m16n8k16.row.col.f32.f16.f16.f32 " \
        "{%0,%1,%2,%3}, {%4,%5,%6,%7}, {%8,%9}, {%0,%1,%2,%3};" \
        : "+f"((d)[0]), "+f"((d)[1]), "+f"((d)[2]), "+f"((d)[3]) \
        : "r"((a)[0]), "r"((a)[1]), "r"((a)[2]), "r"((a)[3]), "r"(b0), "r"(b1))

__device__ __forceinline__ uint32_t pack_h2(float a, float b) {
    uint32_t h0 = (uint32_t)__half_as_ushort(__float2half_rn(a));
    uint32_t h1 = (uint32_t)__half_as_ushort(__float2half_rn(b));
    return h0 | (h1 << 16);
}

#define GSTAGES      3
#define GTILE_BYTES  16384
#define GSTAGE_BYTES (2 * GTILE_BYTES)
#define GEMM_DSMEM   (GSTAGES * GSTAGE_BYTES)

__global__ void __launch_bounds__(128, 2) gemm2_kernel(
    const __half* __restrict__ A, const __half* __restrict__ B,
    const float* __restrict__ add, float* __restrict__ C,
    __half* __restrict__ out2,
    int M, int N, int K2, int mode)
{
    extern __shared__ __align__(128) char smem[];
    const uint32_t smem_base = smem_u32(smem);

    const int tid  = threadIdx.x;
    const int lane = tid & 31;
    const int warp = tid >> 5;
    const int wm = warp >> 1;
    const int wn = warp & 1;
    const int bx = blockIdx.x, by = blockIdx.y;
    const int nk = K2 >> 6;

    int lrow[8], lswz[8];
#pragma unroll
    for (int p = 0; p < 8; p++) {
        const int id = p * 128 + tid;
        const int row = id >> 3;
        const int c   = id & 7;
        lrow[p] = row;
        lswz[p] = row * 128 + ((c ^ (row & 7)) << 4);
    }
    const __half* Abase = A + (size_t)(by * 128) * K2;
    const __half* Bbase = B + (size_t)(bx * 128) * K2;

    float acc[4][8][4];
#pragma unroll
    for (int i = 0; i < 4; i++)
#pragma unroll
        for (int j = 0; j < 8; j++)
#pragma unroll
            for (int r = 0; r < 4; r++) acc[i][j][r] = 0.f;

    auto load_part = [&](int ks, int buf, int part) {
        const uint32_t sa = smem_base + buf * GSTAGE_BYTES;
        const uint32_t sb = sa + GTILE_BYTES;
        const int koff = ks * 64;
#pragma unroll
        for (int pp = 0; pp < 2; pp++) {
            const int p = part * 2 + pp;
            const int c = (p * 128 + tid) & 7;
            CP_ASYNC16(sa + lswz[p], Abase + (size_t)lrow[p] * K2 + koff + c * 8);
            CP_ASYNC16(sb + lswz[p], Bbase + (size_t)lrow[p] * K2 + koff + c * 8);
        }
    };

#pragma unroll
    for (int part = 0; part < 4; part++) load_part(0, 0, part);
    CP_COMMIT();
#pragma unroll
    for (int part = 0; part < 4; part++) load_part(1, 1, part);
    CP_COMMIT();

    for (int ks = 0; ks < nk; ks++) {
        CP_WAIT1();
        __syncthreads();

        const int buf = ks % GSTAGES;
        const uint32_t sa = smem_base + buf * GSTAGE_BYTES;
        const uint32_t sb = sa + GTILE_BYTES;
        const bool pf = (ks + 2 < nk);
        const int pbuf = (ks + 2) % GSTAGES;

        uint32_t ra[2][4][4], rb[2][4][4];

        auto ldfrag = [&](int kk, int pb) {
#pragma unroll
            for (int mt = 0; mt < 4; mt++) {
                const int row = wm * 64 + mt * 16 + (lane & 15);
                const int ch  = kk * 2 + (lane >> 4);
                LDSM4(ra[pb][mt], sa + row * 128 + ((ch ^ (row & 7)) << 4));
            }
#pragma unroll
            for (int p = 0; p < 4; p++) {
                const int n  = wn * 64 + p * 16 + (lane & 7) + ((lane >> 4) << 3);
                const int ch = kk * 2 + ((lane >> 3) & 1);
                LDSM4(rb[pb][p], sb + n * 128 + ((ch ^ (n & 7)) << 4));
            }
        };

        ldfrag(0, 0);
#pragma unroll
        for (int kk = 0; kk < 4; kk++) {
            const int cur = kk & 1;
            if (kk < 3) ldfrag(kk + 1, cur ^ 1);
            if (pf) load_part(ks + 2, pbuf, kk);
#pragma unroll
            for (int mt = 0; mt < 4; mt++)
#pragma unroll
                for (int nt = 0; nt < 8; nt++)
                    MMA16816(acc[mt][nt], ra[cur][mt],
                             rb[cur][nt >> 1][(nt & 1) * 2],
                             rb[cur][nt >> 1][(nt & 1) * 2 + 1]);
        }
        CP_COMMIT();
    }

    const int r0 = lane >> 2;
    const int c0 = (lane & 3) * 2;
#pragma unroll
    for (int mt = 0; mt < 4; mt++) {
#pragma unroll
        for (int half_ = 0; half_ < 2; half_++) {
            const int row = by * 128 + wm * 64 + mt * 16 + r0 + half_ * 8;
            const int colb = bx * 128 + wn * 64;
            if (mode == 4) {
                __half* Or = out2 + (size_t)row * (N >> 1);
#pragma unroll
                for (int nt = 0; nt < 8; nt++) {
                    float g = acc[mt][nt][half_ * 2];
                    const float u = acc[mt][nt][half_ * 2 + 1];
                    g = g / (1.f + expf(-g)) * u;
                    Or[(colb + nt * 8 + c0) >> 1] = __float2half_rn(g);
                }
            } else {
                float* Cr = C + (size_t)row * N + colb;
                const float* Ar = (mode == 1) ? add + (size_t)row * N + colb : nullptr;
#pragma unroll
                for (int nt = 0; nt < 8; nt++) {
                    float2 o;
                    o.x = acc[mt][nt][half_ * 2];
                    o.y = acc[mt][nt][half_ * 2 + 1];
                    if (Ar) {
                        const float2 av = *(const float2*)(Ar + nt * 8 + c0);
                        o.x += av.x; o.y += av.y;
                    }
                    *(float2*)(Cr + nt * 8 + c0) = o;
                }
            }
        }
    }
}

#define QS_STRIDE 136
#define VS_STRIDE 72
#define FA_SMEM   (2*(128*QS_STRIDE*2) + 128*VS_STRIDE*2)

__global__ void __launch_bounds__(256, 2) flash_attn_kernel(
    const float* __restrict__ q, const float* __restrict__ kbase,
    const float* __restrict__ vbase, const float* __restrict__ mask,
    __half* __restrict__ ctxh, int kvs)
{
    extern __shared__ __align__(128) char smem[];
    __half* Qs = (__half*)smem;
    __half* Ks = Qs + 128 * QS_STRIDE;
    __half* Vs = Ks + 128 * QS_STRIDE;
    const uint32_t QsB = smem_u32(Qs);
    const uint32_t KsB = smem_u32(Ks);
    const uint32_t VsB = smem_u32(Vs);

    const int tid  = threadIdx.x;
    const int lane = tid & 31;
    const int w    = tid >> 5;
    const int bh = blockIdx.y;
    const int b = bh >> 5, h = bh & 31;
    const int q0 = blockIdx.x * 128;

#pragma unroll
    for (int p = 0; p < 8; p++) {
        const int id = p * 256 + tid;
        const int row = id >> 4;
        const int c4  = (id & 15) * 4;
        const float4 vv = *(const float4*)(q + (size_t)(b * SS + q0 + row) * HID + h * HD + c4);
        uint2 hi, lo;
        hi.x = pack_h2(vv.x, vv.y); hi.y = pack_h2(vv.z, vv.w);
        lo.x = pack_h2(vv.x - __half2float(__float2half_rn(vv.x)),
                       vv.y - __half2float(__float2half_rn(vv.y)));
        lo.y = pack_h2(vv.z - __half2float(__float2half_rn(vv.z)),
                       vv.w - __half2float(__float2half_rn(vv.w)));
        *(uint2*)(Qs + row * QS_STRIDE + c4)      = hi;
        *(uint2*)(Qs + row * QS_STRIDE + 64 + c4) = lo;
    }

    float sc[64];
    float o[8][4];
#pragma unroll
    for (int j = 0; j < 8; j++)
#pragma unroll
        for (int r = 0; r < 4; r++) o[j][r] = 0.f;
    float mrow[2] = {-INFINITY, -INFINITY};
    float lrow[2] = {0.f, 0.f};

    const int rA = lane >> 2;
    const int cA = (lane & 3) * 2;

    for (int kt = 0; kt < SS / 128; kt++) {
        __syncthreads();
#pragma unroll
        for (int p = 0; p < 8; p++) {
            const int id = p * 256 + tid;
            const int row = id >> 4;
            const int c4  = (id & 15) * 4;
            const float4 vv = *(const float4*)(kbase + (size_t)(b * SS + kt * 128 + row) * kvs + h * HD + c4);
            uint2 hi;
            hi.x = pack_h2(vv.x, vv.y); hi.y = pack_h2(vv.z, vv.w);
            *(uint2*)(Ks + row * QS_STRIDE + c4)      = hi;
            *(uint2*)(Ks + row * QS_STRIDE + 64 + c4) = hi;
        }
#pragma unroll
        for (int p = 0; p < 8; p++) {
            const int id = p * 256 + tid;
            const int krow = id >> 4;
            const int c4   = (id & 15) * 4;
            const float4 vv = *(const float4*)(vbase + (size_t)(b * SS + kt * 128 + krow) * kvs + h * HD + c4);
            uint2 hi;
            hi.x = pack_h2(vv.x, vv.y); hi.y = pack_h2(vv.z, vv.w);
            *(uint2*)(Vs + krow * VS_STRIDE + c4) = hi;
        }
        __syncthreads();

#pragma unroll
        for (int i = 0; i < 64; i++) sc[i] = 0.f;
#pragma unroll
        for (int s = 0; s < 8; s++) {
            uint32_t ra[4];
            const int arow2 = 16 * w + (lane & 15);
            LDSM4(ra, QsB + (arow2 * QS_STRIDE + s * 16 + ((lane >> 4) << 3)) * 2);
#pragma unroll
            for (int t2 = 0; t2 < 8; t2++) {
                uint32_t rb[4];
                const int n  = t2 * 16 + (lane & 7) + ((lane >> 4) << 3);
                const int cb = s * 16 + (((lane >> 3) & 1) << 3);
                LDSM4(rb, KsB + (n * QS_STRIDE + cb) * 2);
                MMA16816((sc + (2 * t2) * 4),     ra, rb[0], rb[1]);
                MMA16816((sc + (2 * t2 + 1) * 4), ra, rb[2], rb[3]);
            }
        }

        const int qrA = q0 + 16 * w + rA;
        const int qrB = qrA + 8;
        float tm[2] = {-INFINITY, -INFINITY};
#pragma unroll
        for (int t = 0; t < 16; t++) {
            const int kc = kt * 128 + t * 8 + cA;
            const float2 mA = *(const float2*)(mask + ((size_t)b * SS + qrA) * SS + kc);
            const float2 mB = *(const float2*)(mask + ((size_t)b * SS + qrB) * SS + kc);
            sc[t * 4 + 0] = sc[t * 4 + 0] * 0.125f + mA.x;
            sc[t * 4 + 1] = sc[t * 4 + 1] * 0.125f + mA.y;
            sc[t * 4 + 2] = sc[t * 4 + 2] * 0.125f + mB.x;
            sc[t * 4 + 3] = sc[t * 4 + 3] * 0.125f + mB.y;
            tm[0] = fmaxf(tm[0], fmaxf(sc[t * 4 + 0], sc[t * 4 + 1]));
            tm[1] = fmaxf(tm[1], fmaxf(sc[t * 4 + 2], sc[t * 4 + 3]));
        }
#pragma unroll
        for (int off = 1; off <= 2; off <<= 1) {
            tm[0] = fmaxf(tm[0], __shfl_xor_sync(0xffffffffu, tm[0], off));
            tm[1] = fmaxf(tm[1], __shfl_xor_sync(0xffffffffu, tm[1], off));
        }
        const float mn0 = fmaxf(mrow[0], tm[0]);
        const float mn1 = fmaxf(mrow[1], tm[1]);
        const float e0 = __expf(mrow[0] - mn0);
        const float e1 = __expf(mrow[1] - mn1);
        float ts[2] = {0.f, 0.f};
#pragma unroll
        for (int t = 0; t < 16; t++) {
            sc[t * 4 + 0] = __expf(sc[t * 4 + 0] - mn0);
            sc[t * 4 + 1] = __expf(sc[t * 4 + 1] - mn0);
            sc[t * 4 + 2] = __expf(sc[t * 4 + 2] - mn1);
            sc[t * 4 + 3] = __expf(sc[t * 4 + 3] - mn1);
            ts[0] += sc[t * 4 + 0] + sc[t * 4 + 1];
            ts[1] += sc[t * 4 + 2] + sc[t * 4 + 3];
        }
#pragma unroll
        for (int off = 1; off <= 2; off <<= 1) {
            ts[0] += __shfl_xor_sync(0xffffffffu, ts[0], off);
            ts[1] += __shfl_xor_sync(0xffffffffu, ts[1], off);
        }
        lrow[0] = lrow[0] * e0 + ts[0];
        lrow[1] = lrow[1] * e1 + ts[1];
        mrow[0] = mn0; mrow[1] = mn1;
#pragma unroll
        for (int j = 0; j < 8; j++) {
            o[j][0] *= e0; o[j][1] *= e0;
            o[j][2] *= e1; o[j][3] *= e1;
        }

#pragma unroll
        for (int s2 = 0; s2 < 8; s2++) {
            const float p00 = sc[(2 * s2) * 4 + 0], p01 = sc[(2 * s2) * 4 + 1];
            const float p10 = sc[(2 * s2) * 4 + 2], p11 = sc[(2 * s2) * 4 + 3];
            const float r00 = sc[(2 * s2 + 1) * 4 + 0], r01 = sc[(2 * s2 + 1) * 4 + 1];
            const float r10 = sc[(2 * s2 + 1) * 4 + 2], r11 = sc[(2 * s2 + 1) * 4 + 3];
            uint32_t ph[4], pl[4];
            ph[0] = pack_h2(p00, p01); ph[1] = pack_h2(p10, p11);
            ph[2] = pack_h2(r00, r01); ph[3] = pack_h2(r10, r11);
            pl[0] = pack_h2(p00 - __half2float(__float2half_rn(p00)),
                            p01 - __half2float(__float2half_rn(p01)));
            pl[1] = pack_h2(p10 - __half2float(__float2half_rn(p10)),
                            p11 - __half2float(__float2half_rn(p11)));
            pl[2] = pack_h2(r00 - __half2float(__float2half_rn(r00)),
                            r01 - __half2float(__float2half_rn(r01)));
            pl[3] = pack_h2(r10 - __half2float(__float2half_rn(r10)),
                            r11 - __half2float(__float2half_rn(r11)));
            const int krow = s2 * 16 + (lane & 7) + (((lane >> 3) & 1) << 3);
#pragma unroll
            for (int dt = 0; dt < 4; dt++) {
                uint32_t bh_[4];
                LDSM4T(bh_, VsB + (krow * VS_STRIDE + dt * 16 + ((lane >> 4) << 3)) * 2);
                MMA16816(o[2 * dt],     ph, bh_[0], bh_[1]);
                MMA16816(o[2 * dt + 1], ph, bh_[2], bh_[3]);
                MMA16816(o[2 * dt],     pl, bh_[0], bh_[1]);
                MMA16816(o[2 * dt + 1], pl, bh_[2], bh_[3]);
            }
        }
    }

    const float inv0 = 1.f / lrow[0];
    const float inv1 = 1.f / lrow[1];
    const size_t tokA = (size_t)(b * SS + q0 + 16 * w + rA);
    const size_t tokB = tokA + 8;
#pragma unroll
    for (int j = 0; j < 8; j++) {
        const int cg = h * HD + j * 8 + cA;
        ctxh[tokA * HID + cg]     = __float2half_rn(o[j][0] * inv0);
        ctxh[tokA * HID + cg + 1] = __float2half_rn(o[j][1] * inv0);
        ctxh[tokB * HID + cg]     = __float2half_rn(o[j][2] * inv1);
        ctxh[tokB * HID + cg + 1] = __float2half_rn(o[j][3] * inv1);
    }
}

__global__ void __launch_bounds__(256) conv4_kernel(
    const float* __restrict__ X0, const float* __restrict__ X1,
    const float* __restrict__ X2, const float* __restrict__ X3,
    __half* __restrict__ Y)
{
    const float* X = (blockIdx.y == 0) ? X0 : (blockIdx.y == 1) ? X1 :
                     (blockIdx.y == 2) ? X2 : X3;
    __half* Yb = Y + (size_t)blockIdx.y * ((size_t)HID * HID);
    const size_t i0 = ((size_t)blockIdx.x * 256 + threadIdx.x) * 4;
    const size_t st = (size_t)gridDim.x * 1024;
    float4 v[8];
#pragma unroll
    for (int qq = 0; qq < 8; qq++) v[qq] = *(const float4*)(X + i0 + qq * st);
#pragma unroll
    for (int qq = 0; qq < 8; qq++) {
        uint2 hp;
        hp.x = pack_h2(v[qq].x, v[qq].y);
        hp.y = pack_h2(v[qq].z, v[qq].w);
        *(uint2*)(Yb + i0 + qq * st) = hp;
    }
}

__global__ void __launch_bounds__(256) conv_kernel(
    const float* __restrict__ X, __half* __restrict__ Y)
{
    const size_t i0 = ((size_t)blockIdx.x * 256 + threadIdx.x) * 4;
    const size_t st = (size_t)gridDim.x * 1024;
    float4 v[8];
#pragma unroll
    for (int qq = 0; qq < 8; qq++) v[qq] = *(const float4*)(X + i0 + qq * st);
#pragma unroll
    for (int qq = 0; qq < 8; qq++) {
        uint2 hp;
        hp.x = pack_h2(v[qq].x, v[qq].y);
        hp.y = pack_h2(v[qq].z, v[qq].w);
        *(uint2*)(Y + i0 + qq * st) = hp;
    }
}

__global__ void __launch_bounds__(256) conv_il2_kernel(
    const float* __restrict__ Xg, const float* __restrict__ Xu,
    __half* __restrict__ Y)
{
    const float* X = blockIdx.y ? Xu : Xg;
    const int parity = blockIdx.y;
    const size_t i0 = ((size_t)blockIdx.x * 256 + threadIdx.x) * 4;
    const size_t st = (size_t)gridDim.x * 1024;
    float4 v[8];
#pragma unroll
    for (int qq = 0; qq < 8; qq++) v[qq] = *(const float4*)(X + i0 + qq * st);
#pragma unroll
    for (int qq = 0; qq < 8; qq++) {
        const size_t e = i0 + qq * st;
        const size_t row = e >> 11;
        const size_t col = e & 2047;
        uint2 hp;
        hp.x = pack_h2(v[qq].x, v[qq].y);
        hp.y = pack_h2(v[qq].z, v[qq].w);
        *(uint2*)(Y + ((2 * row + parity) << 11) + col) = hp;
    }
}

__global__ void __launch_bounds__(256) layernorm_h_kernel(
    const float* __restrict__ x, const float* __restrict__ w,
    const float* __restrict__ b, __half* __restrict__ outh)
{
    const int t   = blockIdx.x;
    const int tid = threadIdx.x;
    const float* xr = x + (size_t)t * HID;

    float v[8];
    float s = 0.f, s2 = 0.f;
#pragma unroll
    for (int i = 0; i < 8; i++) {
        v[i] = xr[tid + i * 256];
        s  += v[i];
        s2 += v[i] * v[i];
    }
#pragma unroll
    for (int o = 16; o; o >>= 1) {
        s  += __shfl_xor_sync(0xffffffffu, s,  o);
        s2 += __shfl_xor_sync(0xffffffffu, s2, o);
    }
    __shared__ float ss[8], ss2[8];
    if ((tid & 31) == 0) { ss[tid >> 5] = s; ss2[tid >> 5] = s2; }
    __syncthreads();
    if (tid < 32) {
        s  = (tid < 8) ? ss [tid] : 0.f;
        s2 = (tid < 8) ? ss2[tid] : 0.f;
#pragma unroll
        for (int o = 4; o; o >>= 1) {
            s  += __shfl_xor_sync(0xffffffffu, s,  o);
            s2 += __shfl_xor_sync(0xffffffffu, s2, o);
        }
        if (tid == 0) { ss[0] = s; ss2[0] = s2; }
    }
    __syncthreads();
    const float mean = ss[0] * (1.f / HID);
    const float var  = ss2[0] * (1.f / HID) - mean * mean;
    const float rstd = rsqrtf(var + LN_EPS);
    __half* orow = outh + (size_t)t * HID;
#pragma unroll
    for (int i = 0; i < 8; i++) {
        const int idx = tid + i * 256;
        const float y = (v[i] - mean) * rstd * w[idx] + b[idx];
        orow[idx] = __float2half_rn(y);
    }
}

__global__ void __launch_bounds__(256) rope_kernel(
    float* __restrict__ q, float* __restrict__ k,
    const int* __restrict__ pos_ids, int kvs)
{
    const int idx = blockIdx.x * blockDim.x + threadIdx.x;
    if (idx >= TT * NH * 8) return;
    const int i = idx & 7;
    const int h = (idx >> 3) & 31;
    const int t = idx >> 8;
    const int b = t / SS, s = t % SS;
    const int pos = pos_ids[b * SS + s];

    const float freq = powf(10000.0f, -(2.0f * (float)i) / (float)ROT);
    const float ang  = (float)pos * freq;
    float c, si;
    sincosf(ang, &si, &c);

    {
        const size_t base = (size_t)t * HID + h * HD;
        float q0 = q[base + i], q1 = q[base + i + 8];
        q[base + i]     = q0 * c - q1 * si;
        q[base + i + 8] = q1 * c + q0 * si;
    }
    {
        const size_t base = (size_t)t * kvs + h * HD;
        float k0 = k[base + i], k1 = k[base + i + 8];
        k[base + i]     = k0 * c - k1 * si;
        k[base + i + 8] = k1 * c + k0 * si;
    }
}

extern "C" void kernel_launch(void* const* d_in, const int* in_sizes, int n_in,
                              void* d_out, int out_size)
{
    const float* hidden = (const float*)d_in[0];
    const float* memory = (const float*)d_in[1];
    const float* mask   = (const float*)d_in[2];
    const int*   pos    = (const int*)  d_in[3];
    const float* Wq     = (const float*)d_in[4];
    const float* Wk     = (const float*)d_in[5];
    const float* Wv     = (const float*)d_in[6];
    const float* Wo     = (const float*)d_in[7];
    const float* ln1w   = (const float*)d_in[8];
    const float* ln1b   = (const float*)d_in[9];
    const float* ln2w   = (const float*)d_in[10];
    const float* ln2b   = (const float*)d_in[11];
    const float* gw     = (const float*)d_in[12];
    const float* uw     = (const float*)d_in[13];
    const float* dw     = (const float*)d_in[14];
    float* out = (float*)d_out;

    float *q, *kv, *h;
    __half *a2, *b2, *c2;
    cudaGetSymbolAddress((void**)&q,    g_q);
    cudaGetSymbolAddress((void**)&kv,   g_kv);
    cudaGetSymbolAddress((void**)&h,    g_h);
    cudaGetSymbolAddress((void**)&a2,   g_a2);
    cudaGetSymbolAddress((void**)&b2,   g_b2);
    cudaGetSymbolAddress((void**)&c2,   g_c2);

    cudaFuncSetAttribute(gemm2_kernel,
                         cudaFuncAttributeMaxDynamicSharedMemorySize, GEMM_DSMEM);
    cudaFuncSetAttribute(flash_attn_kernel,
                         cudaFuncAttributeMaxDynamicSharedMemorySize, FA_SMEM);

    const size_t HH = (size_t)HID * HID;

    auto gemm = [&](const __half* A, const __half* B,
                    const float* add, float* C, __half* O2,
                    int M, int N, int K2, int mode) {
        gemm2_kernel<<<dim3(N / 128, M / 128), 128, GEMM_DSMEM>>>(
            A, B, add, C, O2, M, N, K2, mode);
    };

    conv4_kernel<<<dim3((unsigned)(HH / 8192), 4), 256>>>(Wq, Wk, Wv, Wo, b2);
    conv_kernel<<<(unsigned)((size_t)TT * HID / 8192), 256>>>(memory, c2);
    layernorm_h_kernel<<<TT, 256>>>(hidden, ln1w, ln1b, a2);

    gemm(a2, b2, nullptr, q, nullptr, TT, HID, HID, 0);
    gemm(c2, b2 + HH, nullptr, kv, nullptr, TT, 2 * HID, HID, 0);

    rope_kernel<<<(TT * NH * 8) / 256, 256>>>(q, kv, pos, 2 * HID);

    flash_attn_kernel<<<dim3(SS / 128, BB * NH), 256, FA_SMEM>>>(
        q, kv, kv + HID, mask, a2, 2 * HID);

    gemm(a2, b2 + 3 * HH, hidden, h, nullptr, TT, HID, HID, 1);

    layernorm_h_kernel<<<TT, 256>>>(h, ln2w, ln2b, a2);

    conv_il2_kernel<<<dim3((unsigned)((size_t)DFF * HID / 8192), 2), 256>>>(gw, uw, b2);
    gemm(a2, b2, nullptr, nullptr, c2, TT, 2 * DFF, HID, 4);
    conv_kernel<<<(unsigned)((size_t)HID * DFF / 8192), 256>>>(dw, b2);
    gemm(c2, b2, h, out, nullptr, TT, HID, DFF, 1);
}